// round 3
// baseline (speedup 1.0000x reference)
#include <cuda_runtime.h>
#include <math.h>
#include <stdint.h>

// ---------------- problem constants ----------------
#define BB 32
#define LL 1024
#define DD 256
#define HH 4
#define EE 64
#define NBAND 308          // f = 205..512
#define F0 205
#define TOPK 34

// ---------------- scratch layout (floats) ----------------
constexpr size_t SZ   = (size_t)BB * LL * DD;        // 8388608
constexpr size_t SPEC = (size_t)BB * DD * 640;       // 5242880 (8192 x 640)
constexpr size_t SC   = (size_t)BB * HH * LL * LL;   // 134217728

constexpr size_t O_Q    = 0;
constexpr size_t O_K    = O_Q + SZ;
constexpr size_t O_V    = O_K + SZ;
constexpr size_t O_QT   = O_V + SZ;
constexpr size_t O_KT   = O_QT + SZ;
constexpr size_t O_VT   = O_KT + SZ;
constexpr size_t O_SPQ  = O_VT + SZ;
constexpr size_t O_SPK  = O_SPQ + SPEC;
constexpr size_t O_SPV  = O_SPK + SPEC;
constexpr size_t O_QS   = O_SPV + SPEC;
constexpr size_t O_KS   = O_QS + SZ;
constexpr size_t O_VS   = O_KS + SZ;
constexpr size_t O_PR   = O_VS + SZ;       // probs / scores
constexpr size_t O_CSP  = O_PR + SC;       // ctx spatial (B,L,D)
constexpr size_t O_AGG  = O_CSP + SZ;      // time agg (B,D,L)
constexpr size_t O_CTX  = O_AGG + SZ;      // mixed context (B,L,D)
constexpr size_t O_T1   = O_CTX + SZ;
constexpr size_t O_H    = O_T1 + SZ;
constexpr size_t O_G1   = O_H + SZ;
constexpr size_t O_F    = O_G1 + SZ;
constexpr size_t O_BF   = O_F + SZ;              // fwd basis 1024x640
constexpr size_t O_BI   = O_BF + 1024 * 640;     // inv basis 640x1024
constexpr size_t O_S    = O_BI + 640 * 1024;     // per-batch spectrum sum 32x640
constexpr size_t O_MV   = O_S + (size_t)BB * 640;  // mean_value 32x1024
constexpr size_t O_W    = O_MV + (size_t)BB * LL;  // weights 32x64
constexpr size_t TOTAL  = O_W + (size_t)BB * 64;

__device__ float g_scr[TOTAL + 1024];
__device__ int   g_idx[64];

// ---------------- basis fill ----------------
__global__ void fill_fwd_k(float* __restrict__ F) {
    int t = blockIdx.x;           // 0..1023
    int j = threadIdx.x;          // 0..639
    float v = 0.f;
    if (j < NBAND || (j >= 320 && j < 320 + NBAND)) {
        int f = F0 + ((j < 320) ? j : (j - 320));
        int m = (f * t) & 1023;
        float ang = 6.283185307179586f * (float)m / 1024.0f;
        v = (j < 320) ? cosf(ang) : -sinf(ang);   // re: cos, im: -sin
    }
    F[(size_t)t * 640 + j] = v;
}

__global__ void fill_inv_k(float* __restrict__ G) {
    int row = blockIdx.x;         // 0..639
    int t = threadIdx.x;          // 0..1023
    float v = 0.f;
    const float inv_l = 1.0f / 1024.0f;
    if (row < NBAND) {
        int f = F0 + row;
        if (f == 512) v = ((t & 1) ? -1.f : 1.f) * inv_l;
        else {
            int m = (f * t) & 1023;
            v = 2.f * inv_l * cosf(6.283185307179586f * (float)m / 1024.0f);
        }
    } else if (row >= 320 && row < 320 + NBAND) {
        int f = F0 + row - 320;
        if (f != 512) {
            int m = (f * t) & 1023;
            v = -2.f * inv_l * sinf(6.283185307179586f * (float)m / 1024.0f);
        }
    }
    G[(size_t)row * 1024 + t] = v;
}

// ---------------- generic SGEMM: C[M,N] = A[M,K] @ B[K,N] (+epilogue) ------
// EPI: 0 none, 1 +bias, 2 +bias+res, 3 +bias then gelu(erf)
template<int EPI>
__global__ void __launch_bounds__(256) gemm_k(
    const float* __restrict__ A, const float* __restrict__ Bw,
    const float* __restrict__ bias, const float* __restrict__ res,
    float* __restrict__ C, int M, int N, int K)
{
    __shared__ float As[16][128];
    __shared__ float Bs[16][132];
    const int bn = blockIdx.x * 128;
    const int bm = blockIdx.y * 128;
    const int tid = threadIdx.x;
    const int tr = tid >> 4, tc = tid & 15;
    float acc[8][8];
#pragma unroll
    for (int i = 0; i < 8; i++)
#pragma unroll
        for (int j = 0; j < 8; j++) acc[i][j] = 0.f;

    for (int k0 = 0; k0 < K; k0 += 16) {
#pragma unroll
        for (int u = 0; u < 2; u++) {
            int id = tid + u * 256;
            int row = id >> 2, c4 = id & 3;
            float4 av = *(const float4*)&A[(size_t)(bm + row) * K + k0 + c4 * 4];
            As[c4 * 4 + 0][row] = av.x;
            As[c4 * 4 + 1][row] = av.y;
            As[c4 * 4 + 2][row] = av.z;
            As[c4 * 4 + 3][row] = av.w;
            int r = id >> 5, cc = id & 31;
            *(float4*)&Bs[r][cc * 4] =
                *(const float4*)&Bw[(size_t)(k0 + r) * N + bn + cc * 4];
        }
        __syncthreads();
#pragma unroll
        for (int kk = 0; kk < 16; kk++) {
            float a[8], b[8];
            *(float4*)(a)     = *(float4*)&As[kk][tr * 8];
            *(float4*)(a + 4) = *(float4*)&As[kk][tr * 8 + 4];
            *(float4*)(b)     = *(float4*)&Bs[kk][tc * 8];
            *(float4*)(b + 4) = *(float4*)&Bs[kk][tc * 8 + 4];
#pragma unroll
            for (int i = 0; i < 8; i++)
#pragma unroll
                for (int j = 0; j < 8; j++) acc[i][j] = fmaf(a[i], b[j], acc[i][j]);
        }
        __syncthreads();
    }
#pragma unroll
    for (int i = 0; i < 8; i++) {
        int row = bm + tr * 8 + i;
#pragma unroll
        for (int jj = 0; jj < 2; jj++) {
            int col = bn + tc * 8 + jj * 4;
            float o[4];
#pragma unroll
            for (int q = 0; q < 4; q++) o[q] = acc[i][jj * 4 + q];
            if (EPI >= 1) {
                float4 bb = *(const float4*)&bias[col];
                o[0] += bb.x; o[1] += bb.y; o[2] += bb.z; o[3] += bb.w;
            }
            if (EPI == 2) {
                float4 rr = *(const float4*)&res[(size_t)row * N + col];
                o[0] += rr.x; o[1] += rr.y; o[2] += rr.z; o[3] += rr.w;
            }
            if (EPI == 3) {
#pragma unroll
                for (int q = 0; q < 4; q++)
                    o[q] = o[q] * 0.5f * (1.0f + erff(o[q] * 0.70710678118654752f));
            }
            float4 ov; ov.x = o[0]; ov.y = o[1]; ov.z = o[2]; ov.w = o[3];
            *(float4*)&C[(size_t)row * N + col] = ov;
        }
    }
}

// ---------------- transpose (B,L,D) -> (B,D,L) ----------------
__global__ void transpose_k(const float* __restrict__ in, float* __restrict__ out)
{
    __shared__ float tile[32][33];
    int b = blockIdx.z;
    int l0 = blockIdx.x * 32, d0 = blockIdx.y * 32;
    int x = threadIdx.x, y = threadIdx.y;
#pragma unroll
    for (int i = 0; i < 32; i += 8)
        tile[y + i][x] = in[((size_t)b * LL + l0 + y + i) * DD + d0 + x];
    __syncthreads();
#pragma unroll
    for (int i = 0; i < 32; i += 8)
        out[((size_t)b * DD + d0 + y + i) * LL + l0 + x] = tile[x][y + i];
}

// ---------------- per-batch spectrum sum S[b,f] = sum_rows Q conj(K) --------
__global__ void corr_spec_k(const float* __restrict__ Qs, const float* __restrict__ Ks,
                            float* __restrict__ S)
{
    int j = blockIdx.x;   // 0..307
    int b = blockIdx.y;   // 0..31
    int t = threadIdx.x;  // 0..255
    size_t row = (size_t)(b * 256 + t) * 640;
    float qr = Qs[row + j], qi = Qs[row + 320 + j];
    float kr = Ks[row + j], ki = Ks[row + 320 + j];
    float re = qr * kr + qi * ki;
    float im = qi * kr - qr * ki;
    __shared__ float sr[256], si[256];
    sr[t] = re; si[t] = im; __syncthreads();
    for (int s = 128; s > 0; s >>= 1) {
        if (t < s) { sr[t] += sr[t + s]; si[t] += si[t + s]; }
        __syncthreads();
    }
    if (t == 0) { S[(size_t)b * 640 + j] = sr[0]; S[(size_t)b * 640 + 320 + j] = si[0]; }
}

// ---------------- mean_value[b,t] = (1/256) irfft(S*mask)[t] ----------------
__global__ void meanv_k(const float* __restrict__ S, float* __restrict__ mv)
{
    int b = blockIdx.x, t = threadIdx.x;  // 256 threads
    __shared__ float sre[NBAND], sim[NBAND], tbl[1024];
    for (int j = t; j < NBAND; j += 256) {
        sre[j] = S[(size_t)b * 640 + j];
        sim[j] = S[(size_t)b * 640 + 320 + j];
    }
    for (int m = t; m < 1024; m += 256)
        tbl[m] = cosf(6.283185307179586f * (float)m / 1024.0f);
    __syncthreads();
    for (int tt = t; tt < 1024; tt += 256) {
        float acc = sre[NBAND - 1] * ((tt & 1) ? -1.f : 1.f);   // f=512 Nyquist
        for (int j = 0; j < NBAND - 1; j++) {
            int f = F0 + j;
            int m = (f * tt) & 1023;
            float c = tbl[m];
            float s = tbl[(m + 768) & 1023];   // sin(theta) = cos(theta + 3pi/2)
            acc += 2.f * (sre[j] * c - sim[j] * s);
        }
        mv[(size_t)b * 1024 + tt] = acc * (1.0f / (256.0f * 1024.0f));
    }
}

// ---------------- top-k over batch-mean ----------------
__global__ void topk_k(const float* __restrict__ mv, int* __restrict__ idxout)
{
    int t = threadIdx.x;  // 1024
    __shared__ float vals[1024];
    __shared__ float rv[1024];
    __shared__ int   ri[1024];
    float g = 0.f;
    for (int b = 0; b < BB; b++) g += mv[(size_t)b * 1024 + t];
    vals[t] = g;
    __syncthreads();
    for (int k = 0; k < TOPK; k++) {
        rv[t] = vals[t]; ri[t] = t; __syncthreads();
        for (int s = 512; s > 0; s >>= 1) {
            if (t < s) {
                if (rv[t + s] > rv[t] || (rv[t + s] == rv[t] && ri[t + s] < ri[t])) {
                    rv[t] = rv[t + s]; ri[t] = ri[t + s];
                }
            }
            __syncthreads();
        }
        if (t == 0) { idxout[k] = ri[0]; vals[ri[0]] = -3.4e38f; }
        __syncthreads();
    }
}

// ---------------- per-batch softmax weights ----------------
__global__ void weights_k(const float* __restrict__ mv, const int* __restrict__ idx,
                          float* __restrict__ w)
{
    int b = blockIdx.x, t = threadIdx.x;  // 64 threads
    __shared__ float sv[64];
    float v = (t < TOPK) ? mv[(size_t)b * 1024 + idx[t]] : -3.4e38f;
    sv[t] = v; __syncthreads();
    float mx = -3.4e38f;
    for (int i = 0; i < TOPK; i++) mx = fmaxf(mx, sv[i]);
    __syncthreads();
    float e = (t < TOPK) ? expf(v - mx) : 0.f;
    sv[t] = e; __syncthreads();
    float sm = 0.f;
    for (int i = 0; i < TOPK; i++) sm += sv[i];
    if (t < TOPK) w[(size_t)b * 64 + t] = e / sm;
}

// ---------------- scores[b,h,l,s] = (1/8) sum_e qs[e,l]*ks[e,s] -------------
__global__ void __launch_bounds__(256) scores_k(
    const float* __restrict__ qs, const float* __restrict__ ks, float* __restrict__ sc)
{
    int bh = blockIdx.z;
    int b = bh >> 2, h = bh & 3;
    const float* Q = qs + ((size_t)b * DD + h * EE) * LL;
    const float* Kp = ks + ((size_t)b * DD + h * EE) * LL;
    float* out = sc + (size_t)bh * LL * LL;
    int l0 = blockIdx.x * 128, s0 = blockIdx.y * 128;
    __shared__ float Qsm[16][128];
    __shared__ float Ksm[16][136];
    int tid = threadIdx.x, tr = tid >> 4, tc = tid & 15;
    float acc[8][8];
#pragma unroll
    for (int i = 0; i < 8; i++)
#pragma unroll
        for (int j = 0; j < 8; j++) acc[i][j] = 0.f;

    for (int e0 = 0; e0 < EE; e0 += 16) {
#pragma unroll
        for (int u = 0; u < 2; u++) {
            int id = tid + u * 256;
            int r = id >> 5, c = id & 31;
            *(float4*)&Qsm[r][c * 4] = *(const float4*)&Q[(size_t)(e0 + r) * LL + l0 + c * 4];
            *(float4*)&Ksm[r][c * 4] = *(const float4*)&Kp[(size_t)(e0 + r) * LL + s0 + c * 4];
        }
        __syncthreads();
#pragma unroll
        for (int e = 0; e < 16; e++) {
            float a[8], bb[8];
            *(float4*)(a)      = *(float4*)&Qsm[e][tr * 8];
            *(float4*)(a + 4)  = *(float4*)&Qsm[e][tr * 8 + 4];
            *(float4*)(bb)     = *(float4*)&Ksm[e][tc * 8];
            *(float4*)(bb + 4) = *(float4*)&Ksm[e][tc * 8 + 4];
#pragma unroll
            for (int i = 0; i < 8; i++)
#pragma unroll
                for (int j = 0; j < 8; j++) acc[i][j] = fmaf(a[i], bb[j], acc[i][j]);
        }
        __syncthreads();
    }
#pragma unroll
    for (int i = 0; i < 8; i++) {
        int row = l0 + tr * 8 + i;
#pragma unroll
        for (int jj = 0; jj < 2; jj++) {
            int col = s0 + tc * 8 + jj * 4;
            float4 ov;
            ov.x = acc[i][jj * 4 + 0] * 0.125f;
            ov.y = acc[i][jj * 4 + 1] * 0.125f;
            ov.z = acc[i][jj * 4 + 2] * 0.125f;
            ov.w = acc[i][jj * 4 + 3] * 0.125f;
            *(float4*)&out[(size_t)row * LL + col] = ov;
        }
    }
}

// ---------------- row softmax over 1024 ----------------
__global__ void softmax_k(float* __restrict__ sc)
{
    size_t row = blockIdx.x;
    float* p = sc + row * 1024;
    int t = threadIdx.x;  // 256
    float4 v = *(float4*)&p[t * 4];
    __shared__ float red[256];
    float mx = fmaxf(fmaxf(v.x, v.y), fmaxf(v.z, v.w));
    red[t] = mx; __syncthreads();
    for (int s = 128; s > 0; s >>= 1) { if (t < s) red[t] = fmaxf(red[t], red[t + s]); __syncthreads(); }
    mx = red[0]; __syncthreads();
    v.x = expf(v.x - mx); v.y = expf(v.y - mx); v.z = expf(v.z - mx); v.w = expf(v.w - mx);
    red[t] = v.x + v.y + v.z + v.w; __syncthreads();
    for (int s = 128; s > 0; s >>= 1) { if (t < s) red[t] += red[t + s]; __syncthreads(); }
    float inv = 1.0f / red[0];
    v.x *= inv; v.y *= inv; v.z *= inv; v.w *= inv;
    *(float4*)&p[t * 4] = v;
}

// ---------------- ctx_sp[b,l,h*64+e] = sum_s probs[l,s]*vs[e,s] -------------
__global__ void __launch_bounds__(256) ctxv_k(
    const float* __restrict__ pr, const float* __restrict__ vs, float* __restrict__ out)
{
    int bh = blockIdx.y;
    int b = bh >> 2, h = bh & 3;
    const float* P = pr + (size_t)bh * LL * LL;
    const float* V = vs + ((size_t)b * DD + h * EE) * LL;
    int l0 = blockIdx.x * 128;
    __shared__ float Ps[128][36];
    __shared__ float Vsm[64][36];
    int tid = threadIdx.x, tr = tid >> 4, tc = tid & 15;
    float acc[8][4];
#pragma unroll
    for (int i = 0; i < 8; i++)
#pragma unroll
        for (int j = 0; j < 4; j++) acc[i][j] = 0.f;

    for (int s0 = 0; s0 < 1024; s0 += 32) {
        int r = tid >> 1, cc = (tid & 1) * 16;
#pragma unroll
        for (int u = 0; u < 4; u++)
            *(float4*)&Ps[r][cc + u * 4] =
                *(const float4*)&P[(size_t)(l0 + r) * LL + s0 + cc + u * 4];
        int r2 = tid >> 2, c2 = (tid & 3) * 8;
#pragma unroll
        for (int u = 0; u < 2; u++)
            *(float4*)&Vsm[r2][c2 + u * 4] =
                *(const float4*)&V[(size_t)r2 * LL + s0 + c2 + u * 4];
        __syncthreads();
#pragma unroll
        for (int s = 0; s < 32; s++) {
            float a[8], bb[4];
#pragma unroll
            for (int i = 0; i < 8; i++) a[i] = Ps[tr * 8 + i][s];
#pragma unroll
            for (int j = 0; j < 4; j++) bb[j] = Vsm[tc * 4 + j][s];
#pragma unroll
            for (int i = 0; i < 8; i++)
#pragma unroll
                for (int j = 0; j < 4; j++) acc[i][j] = fmaf(a[i], bb[j], acc[i][j]);
        }
        __syncthreads();
    }
#pragma unroll
    for (int i = 0; i < 8; i++) {
        size_t o = ((size_t)b * LL + l0 + tr * 8 + i) * DD + h * EE + tc * 4;
        float4 ov; ov.x = acc[i][0]; ov.y = acc[i][1]; ov.z = acc[i][2]; ov.w = acc[i][3];
        *(float4*)&out[o] = ov;
    }
}

// ---------------- time delay aggregation (B,D,L) ----------------
__global__ void timeagg_k(const float* __restrict__ Vt, const float* __restrict__ w,
                          const int* __restrict__ idx, float* __restrict__ agg)
{
    int bd = blockIdx.x;        // b*256+d
    int b = bd >> 8;
    __shared__ float row[1024];
    __shared__ float ws[TOPK];
    __shared__ int   is[TOPK];
    int t = threadIdx.x;        // 256
    for (int l = t; l < 1024; l += 256) row[l] = Vt[(size_t)bd * 1024 + l];
    if (t < TOPK) { ws[t] = w[(size_t)b * 64 + t]; is[t] = idx[t]; }
    __syncthreads();
    for (int l = t; l < 1024; l += 256) {
        float a = 0.f;
#pragma unroll
        for (int k = 0; k < TOPK; k++) a = fmaf(ws[k], row[(l + is[k]) & 1023], a);
        agg[(size_t)bd * 1024 + l] = a;
    }
}

// ---------------- context = 0.9*agg^T + 0.1*ctx_sp ----------------
// agg is (B,D,L); ctx/csp are (B,L,D). Standard tiled transpose:
//   write phase keeps x as the fast index over d (contiguous in ctx).
__global__ void mix_k(const float* __restrict__ agg, const float* __restrict__ csp,
                      float* __restrict__ ctx)
{
    __shared__ float tile[32][33];
    int b = blockIdx.z;
    int l0 = blockIdx.x * 32, d0 = blockIdx.y * 32;
    int x = threadIdx.x, y = threadIdx.y;
#pragma unroll
    for (int i = 0; i < 32; i += 8)
        tile[y + i][x] = agg[((size_t)b * DD + d0 + y + i) * LL + l0 + x];  // tile[d][l]
    __syncthreads();
#pragma unroll
    for (int i = 0; i < 32; i += 8) {
        // ctx[b, l0+y+i, d0+x] = agg[b, d0+x, l0+y+i] = tile[x][y+i]
        size_t o = ((size_t)b * LL + l0 + y + i) * DD + d0 + x;
        ctx[o] = 0.9f * tile[x][y + i] + 0.1f * csp[o];
    }
}

// ---------------- LayerNorm over D=256 ----------------
__global__ void ln_k(const float* __restrict__ in, const float* __restrict__ g,
                     const float* __restrict__ b, float* __restrict__ out)
{
    size_t row = blockIdx.x;
    int t = threadIdx.x;   // 256
    float v = in[row * DD + t];
    __shared__ float red[256];
    red[t] = v; __syncthreads();
    for (int s = 128; s > 0; s >>= 1) { if (t < s) red[t] += red[t + s]; __syncthreads(); }
    float m = red[0] * (1.0f / 256.0f);
    __syncthreads();
    float d = v - m;
    red[t] = d * d; __syncthreads();
    for (int s = 128; s > 0; s >>= 1) { if (t < s) red[t] += red[t + s]; __syncthreads(); }
    float var = red[0] * (1.0f / 256.0f);
    out[row * DD + t] = d * rsqrtf(var + 1e-8f) * g[t] + b[t];
}

// ---------------- launch ----------------
extern "C" void kernel_launch(void* const* d_in, const int* in_sizes, int n_in,
                              void* d_out, int out_size)
{
    const float* x   = (const float*)d_in[0];
    const float* Wq  = (const float*)d_in[1];
    const float* bq  = (const float*)d_in[2];
    const float* Wk  = (const float*)d_in[3];
    const float* bk  = (const float*)d_in[4];
    const float* Wv  = (const float*)d_in[5];
    const float* bv  = (const float*)d_in[6];
    const float* Wd  = (const float*)d_in[7];
    const float* bd  = (const float*)d_in[8];
    const float* ln1g = (const float*)d_in[9];
    const float* ln1b = (const float*)d_in[10];
    const float* W1  = (const float*)d_in[11];
    const float* b1  = (const float*)d_in[12];
    const float* W2  = (const float*)d_in[13];
    const float* b2  = (const float*)d_in[14];
    const float* ln2g = (const float*)d_in[15];
    const float* ln2b = (const float*)d_in[16];
    float* out = (float*)d_out;

    float* scr = nullptr;
    int* idxp = nullptr;
    cudaGetSymbolAddress((void**)&scr, g_scr);
    cudaGetSymbolAddress((void**)&idxp, g_idx);

    float* bQ   = scr + O_Q;   float* bK  = scr + O_K;   float* bV  = scr + O_V;
    float* Qt   = scr + O_QT;  float* Kt  = scr + O_KT;  float* Vt  = scr + O_VT;
    float* spQ  = scr + O_SPQ; float* spK = scr + O_SPK; float* spV = scr + O_SPV;
    float* qsb  = scr + O_QS;  float* ksb = scr + O_KS;  float* vsb = scr + O_VS;
    float* probs = scr + O_PR;
    float* csp  = scr + O_CSP; float* agg = scr + O_AGG; float* ctx = scr + O_CTX;
    float* t1   = scr + O_T1;  float* hb  = scr + O_H;
    float* g1b  = scr + O_G1;  float* fb  = scr + O_F;
    float* basF = scr + O_BF;  float* basI = scr + O_BI;
    float* Sb   = scr + O_S;   float* mv  = scr + O_MV;  float* wts = scr + O_W;

    // 1. DFT bases
    fill_fwd_k<<<1024, 640>>>(basF);
    fill_inv_k<<<640, 1024>>>(basI);

    // 2. QKV projections (M=32768, N=256, K=256)
    {
        dim3 g(2, 256);
        gemm_k<1><<<g, 256>>>(x, Wq, bq, nullptr, bQ, BB * LL, DD, DD);
        gemm_k<1><<<g, 256>>>(x, Wk, bk, nullptr, bK, BB * LL, DD, DD);
        gemm_k<1><<<g, 256>>>(x, Wv, bv, nullptr, bV, BB * LL, DD, DD);
    }

    // 3. transpose to (B,D,L)
    {
        dim3 g(32, 8, 32), blk(32, 8);
        transpose_k<<<g, blk>>>(bQ, Qt);
        transpose_k<<<g, blk>>>(bK, Kt);
        transpose_k<<<g, blk>>>(bV, Vt);
    }

    // 4. forward band DFT (M=8192, N=640, K=1024)
    {
        dim3 g(5, 64);
        gemm_k<0><<<g, 256>>>(Qt, basF, nullptr, nullptr, spQ, BB * DD, 640, LL);
        gemm_k<0><<<g, 256>>>(Kt, basF, nullptr, nullptr, spK, BB * DD, 640, LL);
        gemm_k<0><<<g, 256>>>(Vt, basF, nullptr, nullptr, spV, BB * DD, 640, LL);
    }

    // 5. corr mean path
    corr_spec_k<<<dim3(NBAND, BB), 256>>>(spQ, spK, Sb);
    meanv_k<<<BB, 256>>>(Sb, mv);
    topk_k<<<1, 1024>>>(mv, idxp);
    weights_k<<<BB, 64>>>(mv, idxp, wts);

    // 6. inverse band DFT -> qs, ks, vs (M=8192, N=1024, K=640)
    {
        dim3 g(8, 64);
        gemm_k<0><<<g, 256>>>(spQ, basI, nullptr, nullptr, qsb, BB * DD, LL, 640);
        gemm_k<0><<<g, 256>>>(spK, basI, nullptr, nullptr, ksb, BB * DD, LL, 640);
        gemm_k<0><<<g, 256>>>(spV, basI, nullptr, nullptr, vsb, BB * DD, LL, 640);
    }

    // 7. spatial attention
    scores_k<<<dim3(8, 8, BB * HH), 256>>>(qsb, ksb, probs);
    softmax_k<<<BB * HH * LL, 256>>>(probs);
    ctxv_k<<<dim3(8, BB * HH), 256>>>(probs, vsb, csp);

    // 8. time aggregation + mix
    timeagg_k<<<BB * DD, 256>>>(Vt, wts, idxp, agg);
    mix_k<<<dim3(32, 8, 32), dim3(32, 8)>>>(agg, csp, ctx);

    // 9. output projection + residual + LN1
    gemm_k<2><<<dim3(2, 256), 256>>>(ctx, Wd, bd, x, t1, BB * LL, DD, DD);
    ln_k<<<BB * LL, 256>>>(t1, ln1g, ln1b, hb);

    // 10. FFN + LN2
    gemm_k<3><<<dim3(2, 256), 256>>>(hb, W1, b1, nullptr, g1b, BB * LL, DD, DD);
    gemm_k<2><<<dim3(2, 256), 256>>>(g1b, W2, b2, hb, fb, BB * LL, DD, DD);
    ln_k<<<BB * LL, 256>>>(fb, ln2g, ln2b, out);
}

// round 4
// speedup vs baseline: 1.0354x; 1.0354x over previous
#include <cuda_runtime.h>
#include <math.h>
#include <stdint.h>

// ---------------- problem constants ----------------
#define BB 32
#define LL 1024
#define DD 256
#define HH 4
#define EE 64
#define NBAND 308          // f = 205..512
#define F0 205
#define TOPK 34

// ---------------- scratch layout (floats) ----------------
constexpr size_t SZ   = (size_t)BB * LL * DD;        // 8388608
constexpr size_t SPEC = (size_t)BB * DD * 640;       // 5242880 (8192 x 640)

constexpr size_t O_Q    = 0;
constexpr size_t O_K    = O_Q + SZ;
constexpr size_t O_V    = O_K + SZ;
constexpr size_t O_QT   = O_V + SZ;
constexpr size_t O_KT   = O_QT + SZ;
constexpr size_t O_VT   = O_KT + SZ;
constexpr size_t O_SPQ  = O_VT + SZ;
constexpr size_t O_SPK  = O_SPQ + SPEC;
constexpr size_t O_SPV  = O_SPK + SPEC;
constexpr size_t O_QS   = O_SPV + SPEC;
constexpr size_t O_KS   = O_QS + SZ;
constexpr size_t O_VS   = O_KS + SZ;
constexpr size_t O_CSP  = O_VS + SZ;       // ctx spatial (B,L,D)
constexpr size_t O_AGG  = O_CSP + SZ;      // time agg (B,D,L)
constexpr size_t O_CTX  = O_AGG + SZ;      // mixed context (B,L,D)
constexpr size_t O_T1   = O_CTX + SZ;
constexpr size_t O_H    = O_T1 + SZ;
constexpr size_t O_G1   = O_H + SZ;
constexpr size_t O_F    = O_G1 + SZ;
constexpr size_t O_BF   = O_F + SZ;              // fwd basis 1024x640
constexpr size_t O_BI   = O_BF + 1024 * 640;     // inv basis 640x1024
constexpr size_t O_S    = O_BI + 640 * 1024;     // per-batch spectrum sum 32x640
constexpr size_t O_MV   = O_S + (size_t)BB * 640;  // mean_value 32x1024
constexpr size_t O_W    = O_MV + (size_t)BB * LL;  // weights 32x64
constexpr size_t TOTAL  = O_W + (size_t)BB * 64;

__device__ float g_scr[TOTAL + 1024];
__device__ int   g_idx[64];

// ---------------- basis fill ----------------
__global__ void fill_fwd_k(float* __restrict__ F) {
    int t = blockIdx.x;           // 0..1023
    int j = threadIdx.x;          // 0..639
    float v = 0.f;
    if (j < NBAND || (j >= 320 && j < 320 + NBAND)) {
        int f = F0 + ((j < 320) ? j : (j - 320));
        int m = (f * t) & 1023;
        float ang = 6.283185307179586f * (float)m / 1024.0f;
        v = (j < 320) ? cosf(ang) : -sinf(ang);   // re: cos, im: -sin
    }
    F[(size_t)t * 640 + j] = v;
}

__global__ void fill_inv_k(float* __restrict__ G) {
    int row = blockIdx.x;         // 0..639
    int t = threadIdx.x;          // 0..1023
    float v = 0.f;
    const float inv_l = 1.0f / 1024.0f;
    if (row < NBAND) {
        int f = F0 + row;
        if (f == 512) v = ((t & 1) ? -1.f : 1.f) * inv_l;
        else {
            int m = (f * t) & 1023;
            v = 2.f * inv_l * cosf(6.283185307179586f * (float)m / 1024.0f);
        }
    } else if (row >= 320 && row < 320 + NBAND) {
        int f = F0 + row - 320;
        if (f != 512) {
            int m = (f * t) & 1023;
            v = -2.f * inv_l * sinf(6.283185307179586f * (float)m / 1024.0f);
        }
    }
    G[(size_t)row * 1024 + t] = v;
}

// ---------------- double-buffered SGEMM: C = A@B (+epilogue) ----------------
// EPI: 0 none, 1 +bias, 2 +bias+res, 3 +bias then gelu(erf)
template<int EPI>
__global__ void __launch_bounds__(256, 2) gemm_k(
    const float* __restrict__ A, const float* __restrict__ Bw,
    const float* __restrict__ bias, const float* __restrict__ res,
    float* __restrict__ C, int M, int N, int K)
{
    __shared__ float As[2][16][128];
    __shared__ float Bs[2][16][132];
    const int bn = blockIdx.x * 128;
    const int bm = blockIdx.y * 128;
    const int tid = threadIdx.x;
    const int tr = tid >> 4, tc = tid & 15;

    int a_row[2], a_c4[2], b_r[2], b_c[2];
#pragma unroll
    for (int u = 0; u < 2; u++) {
        int id = tid + u * 256;
        a_row[u] = id >> 2; a_c4[u] = (id & 3) * 4;
        b_r[u]   = id >> 5; b_c[u]  = (id & 31) * 4;
    }

    // stage 0 load
#pragma unroll
    for (int u = 0; u < 2; u++) {
        float4 av = *(const float4*)&A[(size_t)(bm + a_row[u]) * K + a_c4[u]];
        As[0][a_c4[u] + 0][a_row[u]] = av.x;
        As[0][a_c4[u] + 1][a_row[u]] = av.y;
        As[0][a_c4[u] + 2][a_row[u]] = av.z;
        As[0][a_c4[u] + 3][a_row[u]] = av.w;
        *(float4*)&Bs[0][b_r[u]][b_c[u]] =
            *(const float4*)&Bw[(size_t)b_r[u] * N + bn + b_c[u]];
    }
    __syncthreads();

    float acc[8][8];
#pragma unroll
    for (int i = 0; i < 8; i++)
#pragma unroll
        for (int j = 0; j < 8; j++) acc[i][j] = 0.f;

    int cur = 0;
    for (int k0 = 0; k0 < K; k0 += 16) {
        float4 pa[2], pb[2];
        const bool hn = (k0 + 16) < K;
        if (hn) {
#pragma unroll
            for (int u = 0; u < 2; u++) {
                pa[u] = *(const float4*)&A[(size_t)(bm + a_row[u]) * K + k0 + 16 + a_c4[u]];
                pb[u] = *(const float4*)&Bw[(size_t)(k0 + 16 + b_r[u]) * N + bn + b_c[u]];
            }
        }
#pragma unroll
        for (int kk = 0; kk < 16; kk++) {
            float a[8], b[8];
            *(float4*)(a)     = *(float4*)&As[cur][kk][tr * 8];
            *(float4*)(a + 4) = *(float4*)&As[cur][kk][tr * 8 + 4];
            *(float4*)(b)     = *(float4*)&Bs[cur][kk][tc * 8];
            *(float4*)(b + 4) = *(float4*)&Bs[cur][kk][tc * 8 + 4];
#pragma unroll
            for (int i = 0; i < 8; i++)
#pragma unroll
                for (int j = 0; j < 8; j++) acc[i][j] = fmaf(a[i], b[j], acc[i][j]);
        }
        if (hn) {
            int nxt = cur ^ 1;
#pragma unroll
            for (int u = 0; u < 2; u++) {
                As[nxt][a_c4[u] + 0][a_row[u]] = pa[u].x;
                As[nxt][a_c4[u] + 1][a_row[u]] = pa[u].y;
                As[nxt][a_c4[u] + 2][a_row[u]] = pa[u].z;
                As[nxt][a_c4[u] + 3][a_row[u]] = pa[u].w;
                *(float4*)&Bs[nxt][b_r[u]][b_c[u]] = pb[u];
            }
        }
        __syncthreads();
        cur ^= 1;
    }
#pragma unroll
    for (int i = 0; i < 8; i++) {
        int row = bm + tr * 8 + i;
#pragma unroll
        for (int jj = 0; jj < 2; jj++) {
            int col = bn + tc * 8 + jj * 4;
            float o[4];
#pragma unroll
            for (int q = 0; q < 4; q++) o[q] = acc[i][jj * 4 + q];
            if (EPI >= 1) {
                float4 bbv = *(const float4*)&bias[col];
                o[0] += bbv.x; o[1] += bbv.y; o[2] += bbv.z; o[3] += bbv.w;
            }
            if (EPI == 2) {
                float4 rr = *(const float4*)&res[(size_t)row * N + col];
                o[0] += rr.x; o[1] += rr.y; o[2] += rr.z; o[3] += rr.w;
            }
            if (EPI == 3) {
#pragma unroll
                for (int q = 0; q < 4; q++)
                    o[q] = o[q] * 0.5f * (1.0f + erff(o[q] * 0.70710678118654752f));
            }
            float4 ov; ov.x = o[0]; ov.y = o[1]; ov.z = o[2]; ov.w = o[3];
            *(float4*)&C[(size_t)row * N + col] = ov;
        }
    }
}

// ---------------- transpose (B,L,D) -> (B,D,L) ----------------
__global__ void transpose_k(const float* __restrict__ in, float* __restrict__ out)
{
    __shared__ float tile[32][33];
    int b = blockIdx.z;
    int l0 = blockIdx.x * 32, d0 = blockIdx.y * 32;
    int x = threadIdx.x, y = threadIdx.y;
#pragma unroll
    for (int i = 0; i < 32; i += 8)
        tile[y + i][x] = in[((size_t)b * LL + l0 + y + i) * DD + d0 + x];
    __syncthreads();
#pragma unroll
    for (int i = 0; i < 32; i += 8)
        out[((size_t)b * DD + d0 + y + i) * LL + l0 + x] = tile[x][y + i];
}

// ---------------- per-batch spectrum sum S[b,f] = sum_rows Q conj(K) --------
__global__ void corr_spec_k(const float* __restrict__ Qs, const float* __restrict__ Ks,
                            float* __restrict__ S)
{
    int j = blockIdx.x;   // 0..307
    int b = blockIdx.y;   // 0..31
    int t = threadIdx.x;  // 0..255
    size_t row = (size_t)(b * 256 + t) * 640;
    float qr = Qs[row + j], qi = Qs[row + 320 + j];
    float kr = Ks[row + j], ki = Ks[row + 320 + j];
    float re = qr * kr + qi * ki;
    float im = qi * kr - qr * ki;
    __shared__ float sr[256], si[256];
    sr[t] = re; si[t] = im; __syncthreads();
    for (int s = 128; s > 0; s >>= 1) {
        if (t < s) { sr[t] += sr[t + s]; si[t] += si[t + s]; }
        __syncthreads();
    }
    if (t == 0) { S[(size_t)b * 640 + j] = sr[0]; S[(size_t)b * 640 + 320 + j] = si[0]; }
}

// ---------------- mean_value[b,t] = (1/256) irfft(S*mask)[t] ----------------
__global__ void meanv_k(const float* __restrict__ S, float* __restrict__ mv)
{
    int b = blockIdx.x, t = threadIdx.x;  // 256 threads
    __shared__ float sre[NBAND], sim[NBAND], tbl[1024];
    for (int j = t; j < NBAND; j += 256) {
        sre[j] = S[(size_t)b * 640 + j];
        sim[j] = S[(size_t)b * 640 + 320 + j];
    }
    for (int m = t; m < 1024; m += 256)
        tbl[m] = cosf(6.283185307179586f * (float)m / 1024.0f);
    __syncthreads();
    for (int tt = t; tt < 1024; tt += 256) {
        float acc = sre[NBAND - 1] * ((tt & 1) ? -1.f : 1.f);   // f=512 Nyquist
        for (int j = 0; j < NBAND - 1; j++) {
            int f = F0 + j;
            int m = (f * tt) & 1023;
            float c = tbl[m];
            float s = tbl[(m + 768) & 1023];   // sin(theta) = cos(theta + 3pi/2)
            acc += 2.f * (sre[j] * c - sim[j] * s);
        }
        mv[(size_t)b * 1024 + tt] = acc * (1.0f / (256.0f * 1024.0f));
    }
}

// ---------------- top-k over batch-mean ----------------
__global__ void topk_k(const float* __restrict__ mv, int* __restrict__ idxout)
{
    int t = threadIdx.x;  // 1024
    __shared__ float vals[1024];
    __shared__ float rv[1024];
    __shared__ int   ri[1024];
    float g = 0.f;
    for (int b = 0; b < BB; b++) g += mv[(size_t)b * 1024 + t];
    vals[t] = g;
    __syncthreads();
    for (int k = 0; k < TOPK; k++) {
        rv[t] = vals[t]; ri[t] = t; __syncthreads();
        for (int s = 512; s > 0; s >>= 1) {
            if (t < s) {
                if (rv[t + s] > rv[t] || (rv[t + s] == rv[t] && ri[t + s] < ri[t])) {
                    rv[t] = rv[t + s]; ri[t] = ri[t + s];
                }
            }
            __syncthreads();
        }
        if (t == 0) { idxout[k] = ri[0]; vals[ri[0]] = -3.4e38f; }
        __syncthreads();
    }
}

// ---------------- per-batch softmax weights ----------------
__global__ void weights_k(const float* __restrict__ mv, const int* __restrict__ idx,
                          float* __restrict__ w)
{
    int b = blockIdx.x, t = threadIdx.x;  // 64 threads
    __shared__ float sv[64];
    float v = (t < TOPK) ? mv[(size_t)b * 1024 + idx[t]] : -3.4e38f;
    sv[t] = v; __syncthreads();
    float mx = -3.4e38f;
    for (int i = 0; i < TOPK; i++) mx = fmaxf(mx, sv[i]);
    __syncthreads();
    float e = (t < TOPK) ? expf(v - mx) : 0.f;
    sv[t] = e; __syncthreads();
    float sm = 0.f;
    for (int i = 0; i < TOPK; i++) sm += sv[i];
    if (t < TOPK) w[(size_t)b * 64 + t] = e / sm;
}

// ---------------- flash attention (fp32 SIMT) ----------------
// qs/ks/vs in (B,D,L) layout: row = b*256 + h*64 + e, col = l/s.
// out = csp in (B,L,D). scores scaled by 1/8, softmax over s (full 1024).
__global__ void __launch_bounds__(256) flash_k(
    const float* __restrict__ qs, const float* __restrict__ ks,
    const float* __restrict__ vs, float* __restrict__ out)
{
    extern __shared__ float sm[];
    float* Qs = sm;                 // [64][68]  (e-major: Qs[e][l])
    float* Ks = sm + 64 * 68;       // [64][68]  (e-major: Ks[e][s])
    float* Vs = sm + 2 * 64 * 68;   // [64][68]  (s-major: Vs[s][e])
    float* Ps = sm + 3 * 64 * 68;   // [64][68]  (l-major: Ps[l][s])
    const int bh = blockIdx.y, b = bh >> 2, h = bh & 3;
    const int l0 = blockIdx.x * 64;
    const float* Q  = qs + ((size_t)b * DD + h * EE) * LL;
    const float* Kp = ks + ((size_t)b * DD + h * EE) * LL;
    const float* V  = vs + ((size_t)b * DD + h * EE) * LL;
    const int tid = threadIdx.x;
    const int tr = tid >> 4, tc = tid & 15;
    const int le = tid >> 2;        // 0..63
    const int lq = tid & 3;         // 0..3

    // load Q tile (once)
#pragma unroll
    for (int w = 0; w < 4; w++) {
        int col = w * 16 + lq * 4;
        *(float4*)&Qs[le * 68 + col] = *(const float4*)&Q[(size_t)le * LL + l0 + col];
    }

    float m_i[4], l_i[4], o[4][4];
#pragma unroll
    for (int i = 0; i < 4; i++) {
        m_i[i] = -1e30f; l_i[i] = 0.f;
#pragma unroll
        for (int j = 0; j < 4; j++) o[i][j] = 0.f;
    }

    for (int s0 = 0; s0 < LL; s0 += 64) {
        __syncthreads();   // previous iteration done with Ks/Vs/Ps
#pragma unroll
        for (int w = 0; w < 4; w++) {
            int col = w * 16 + lq * 4;
            *(float4*)&Ks[le * 68 + col] = *(const float4*)&Kp[(size_t)le * LL + s0 + col];
            float4 vv = *(const float4*)&V[(size_t)le * LL + s0 + col];
            Vs[(col + 0) * 68 + le] = vv.x;
            Vs[(col + 1) * 68 + le] = vv.y;
            Vs[(col + 2) * 68 + le] = vv.z;
            Vs[(col + 3) * 68 + le] = vv.w;
        }
        __syncthreads();

        // S[l][s] = sum_e Q[e][l] K[e][s]
        float s_[4][4];
#pragma unroll
        for (int i = 0; i < 4; i++)
#pragma unroll
            for (int j = 0; j < 4; j++) s_[i][j] = 0.f;
        for (int e4 = 0; e4 < 16; e4++) {
            float qa[4][4], kb[4][4];
#pragma unroll
            for (int c = 0; c < 4; c++) {
                float4 t1 = *(float4*)&Qs[(e4 * 4 + c) * 68 + tr * 4];
                qa[c][0] = t1.x; qa[c][1] = t1.y; qa[c][2] = t1.z; qa[c][3] = t1.w;
                float4 t2 = *(float4*)&Ks[(e4 * 4 + c) * 68 + tc * 4];
                kb[c][0] = t2.x; kb[c][1] = t2.y; kb[c][2] = t2.z; kb[c][3] = t2.w;
            }
#pragma unroll
            for (int c = 0; c < 4; c++)
#pragma unroll
                for (int i = 0; i < 4; i++)
#pragma unroll
                    for (int j = 0; j < 4; j++)
                        s_[i][j] = fmaf(qa[c][i], kb[c][j], s_[i][j]);
        }

        // online softmax per row (l = tr*4+i), reduce across 16 tc lanes
#pragma unroll
        for (int i = 0; i < 4; i++) {
            float mx = -1e30f;
#pragma unroll
            for (int j = 0; j < 4; j++) {
                s_[i][j] *= 0.125f;
                mx = fmaxf(mx, s_[i][j]);
            }
#pragma unroll
            for (int off = 8; off > 0; off >>= 1)
                mx = fmaxf(mx, __shfl_xor_sync(0xffffffffu, mx, off));
            float mn = fmaxf(m_i[i], mx);
            float alpha = expf(m_i[i] - mn);
            float p0 = expf(s_[i][0] - mn);
            float p1 = expf(s_[i][1] - mn);
            float p2 = expf(s_[i][2] - mn);
            float p3 = expf(s_[i][3] - mn);
            float ps = p0 + p1 + p2 + p3;
#pragma unroll
            for (int off = 8; off > 0; off >>= 1)
                ps += __shfl_xor_sync(0xffffffffu, ps, off);
            l_i[i] = l_i[i] * alpha + ps;
            m_i[i] = mn;
#pragma unroll
            for (int j = 0; j < 4; j++) o[i][j] *= alpha;
            float4 pv; pv.x = p0; pv.y = p1; pv.z = p2; pv.w = p3;
            *(float4*)&Ps[(tr * 4 + i) * 68 + tc * 4] = pv;
        }
        __syncthreads();

        // O[l][e] += sum_s P[l][s] V[s][e]
        for (int s4 = 0; s4 < 16; s4++) {
            float av[4][4], bv[4][4];
#pragma unroll
            for (int i = 0; i < 4; i++) {
                float4 t1 = *(float4*)&Ps[(tr * 4 + i) * 68 + s4 * 4];
                av[i][0] = t1.x; av[i][1] = t1.y; av[i][2] = t1.z; av[i][3] = t1.w;
            }
#pragma unroll
            for (int c = 0; c < 4; c++) {
                float4 t2 = *(float4*)&Vs[(s4 * 4 + c) * 68 + tc * 4];
                bv[c][0] = t2.x; bv[c][1] = t2.y; bv[c][2] = t2.z; bv[c][3] = t2.w;
            }
#pragma unroll
            for (int c = 0; c < 4; c++)
#pragma unroll
                for (int i = 0; i < 4; i++)
#pragma unroll
                    for (int j = 0; j < 4; j++)
                        o[i][j] = fmaf(av[i][c], bv[c][j], o[i][j]);
        }
    }

    // epilogue: normalize and store to (B,L,D)
#pragma unroll
    for (int i = 0; i < 4; i++) {
        float inv = 1.0f / l_i[i];
        float4 ov;
        ov.x = o[i][0] * inv; ov.y = o[i][1] * inv;
        ov.z = o[i][2] * inv; ov.w = o[i][3] * inv;
        size_t off = ((size_t)b * LL + l0 + tr * 4 + i) * DD + h * EE + tc * 4;
        *(float4*)&out[off] = ov;
    }
}

// ---------------- time delay aggregation (B,D,L) ----------------
__global__ void timeagg_k(const float* __restrict__ Vt, const float* __restrict__ w,
                          const int* __restrict__ idx, float* __restrict__ agg)
{
    int bd = blockIdx.x;        // b*256+d
    int b = bd >> 8;
    __shared__ float row[1024];
    __shared__ float ws[TOPK];
    __shared__ int   is[TOPK];
    int t = threadIdx.x;        // 256
    for (int l = t; l < 1024; l += 256) row[l] = Vt[(size_t)bd * 1024 + l];
    if (t < TOPK) { ws[t] = w[(size_t)b * 64 + t]; is[t] = idx[t]; }
    __syncthreads();
    for (int l = t; l < 1024; l += 256) {
        float a = 0.f;
#pragma unroll
        for (int k = 0; k < TOPK; k++) a = fmaf(ws[k], row[(l + is[k]) & 1023], a);
        agg[(size_t)bd * 1024 + l] = a;
    }
}

// ---------------- context = 0.9*agg^T + 0.1*ctx_sp ----------------
__global__ void mix_k(const float* __restrict__ agg, const float* __restrict__ csp,
                      float* __restrict__ ctx)
{
    __shared__ float tile[32][33];
    int b = blockIdx.z;
    int l0 = blockIdx.x * 32, d0 = blockIdx.y * 32;
    int x = threadIdx.x, y = threadIdx.y;
#pragma unroll
    for (int i = 0; i < 32; i += 8)
        tile[y + i][x] = agg[((size_t)b * DD + d0 + y + i) * LL + l0 + x];  // tile[d][l]
    __syncthreads();
#pragma unroll
    for (int i = 0; i < 32; i += 8) {
        size_t o = ((size_t)b * LL + l0 + y + i) * DD + d0 + x;
        ctx[o] = 0.9f * tile[x][y + i] + 0.1f * csp[o];
    }
}

// ---------------- LayerNorm over D=256 ----------------
__global__ void ln_k(const float* __restrict__ in, const float* __restrict__ g,
                     const float* __restrict__ b, float* __restrict__ out)
{
    size_t row = blockIdx.x;
    int t = threadIdx.x;   // 256
    float v = in[row * DD + t];
    __shared__ float red[256];
    red[t] = v; __syncthreads();
    for (int s = 128; s > 0; s >>= 1) { if (t < s) red[t] += red[t + s]; __syncthreads(); }
    float m = red[0] * (1.0f / 256.0f);
    __syncthreads();
    float d = v - m;
    red[t] = d * d; __syncthreads();
    for (int s = 128; s > 0; s >>= 1) { if (t < s) red[t] += red[t + s]; __syncthreads(); }
    float var = red[0] * (1.0f / 256.0f);
    out[row * DD + t] = d * rsqrtf(var + 1e-8f) * g[t] + b[t];
}

// ---------------- launch ----------------
extern "C" void kernel_launch(void* const* d_in, const int* in_sizes, int n_in,
                              void* d_out, int out_size)
{
    const float* x   = (const float*)d_in[0];
    const float* Wq  = (const float*)d_in[1];
    const float* bq  = (const float*)d_in[2];
    const float* Wk  = (const float*)d_in[3];
    const float* bk  = (const float*)d_in[4];
    const float* Wv  = (const float*)d_in[5];
    const float* bv  = (const float*)d_in[6];
    const float* Wd  = (const float*)d_in[7];
    const float* bd  = (const float*)d_in[8];
    const float* ln1g = (const float*)d_in[9];
    const float* ln1b = (const float*)d_in[10];
    const float* W1  = (const float*)d_in[11];
    const float* b1  = (const float*)d_in[12];
    const float* W2  = (const float*)d_in[13];
    const float* b2  = (const float*)d_in[14];
    const float* ln2g = (const float*)d_in[15];
    const float* ln2b = (const float*)d_in[16];
    float* out = (float*)d_out;

    float* scr = nullptr;
    int* idxp = nullptr;
    cudaGetSymbolAddress((void**)&scr, g_scr);
    cudaGetSymbolAddress((void**)&idxp, g_idx);

    float* bQ   = scr + O_Q;   float* bK  = scr + O_K;   float* bV  = scr + O_V;
    float* Qt   = scr + O_QT;  float* Kt  = scr + O_KT;  float* Vt  = scr + O_VT;
    float* spQ  = scr + O_SPQ; float* spK = scr + O_SPK; float* spV = scr + O_SPV;
    float* qsb  = scr + O_QS;  float* ksb = scr + O_KS;  float* vsb = scr + O_VS;
    float* csp  = scr + O_CSP; float* agg = scr + O_AGG; float* ctx = scr + O_CTX;
    float* t1   = scr + O_T1;  float* hb  = scr + O_H;
    float* g1b  = scr + O_G1;  float* fb  = scr + O_F;
    float* basF = scr + O_BF;  float* basI = scr + O_BI;
    float* Sb   = scr + O_S;   float* mv  = scr + O_MV;  float* wts = scr + O_W;

    const int flash_smem = 4 * 64 * 68 * sizeof(float);   // 69632 B
    cudaFuncSetAttribute(flash_k, cudaFuncAttributeMaxDynamicSharedMemorySize, flash_smem);

    // 1. DFT bases
    fill_fwd_k<<<1024, 640>>>(basF);
    fill_inv_k<<<640, 1024>>>(basI);

    // 2. QKV projections (M=32768, N=256, K=256)
    {
        dim3 g(2, 256);
        gemm_k<1><<<g, 256>>>(x, Wq, bq, nullptr, bQ, BB * LL, DD, DD);
        gemm_k<1><<<g, 256>>>(x, Wk, bk, nullptr, bK, BB * LL, DD, DD);
        gemm_k<1><<<g, 256>>>(x, Wv, bv, nullptr, bV, BB * LL, DD, DD);
    }

    // 3. transpose to (B,D,L)
    {
        dim3 g(32, 8, 32), blk(32, 8);
        transpose_k<<<g, blk>>>(bQ, Qt);
        transpose_k<<<g, blk>>>(bK, Kt);
        transpose_k<<<g, blk>>>(bV, Vt);
    }

    // 4. forward band DFT (M=8192, N=640, K=1024)
    {
        dim3 g(5, 64);
        gemm_k<0><<<g, 256>>>(Qt, basF, nullptr, nullptr, spQ, BB * DD, 640, LL);
        gemm_k<0><<<g, 256>>>(Kt, basF, nullptr, nullptr, spK, BB * DD, 640, LL);
        gemm_k<0><<<g, 256>>>(Vt, basF, nullptr, nullptr, spV, BB * DD, 640, LL);
    }

    // 5. corr mean path
    corr_spec_k<<<dim3(NBAND, BB), 256>>>(spQ, spK, Sb);
    meanv_k<<<BB, 256>>>(Sb, mv);
    topk_k<<<1, 1024>>>(mv, idxp);
    weights_k<<<BB, 64>>>(mv, idxp, wts);

    // 6. inverse band DFT -> qs, ks, vs (M=8192, N=1024, K=640)
    {
        dim3 g(8, 64);
        gemm_k<0><<<g, 256>>>(spQ, basI, nullptr, nullptr, qsb, BB * DD, LL, 640);
        gemm_k<0><<<g, 256>>>(spK, basI, nullptr, nullptr, ksb, BB * DD, LL, 640);
        gemm_k<0><<<g, 256>>>(spV, basI, nullptr, nullptr, vsb, BB * DD, LL, 640);
    }

    // 7. spatial attention (flash-fused)
    flash_k<<<dim3(16, BB * HH), 256, flash_smem>>>(qsb, ksb, vsb, csp);

    // 8. time aggregation + mix
    timeagg_k<<<BB * DD, 256>>>(Vt, wts, idxp, agg);
    mix_k<<<dim3(32, 8, 32), dim3(32, 8)>>>(agg, csp, ctx);

    // 9. output projection + residual + LN1
    gemm_k<2><<<dim3(2, 256), 256>>>(ctx, Wd, bd, x, t1, BB * LL, DD, DD);
    ln_k<<<BB * LL, 256>>>(t1, ln1g, ln1b, hb);

    // 10. FFN + LN2
    gemm_k<3><<<dim3(2, 256), 256>>>(hb, W1, b1, nullptr, g1b, BB * LL, DD, DD);
    gemm_k<2><<<dim3(2, 256), 256>>>(g1b, W2, b2, hb, fb, BB * LL, DD, DD);
    ln_k<<<BB * LL, 256>>>(fb, ln2g, ln2b, out);
}

// round 5
// speedup vs baseline: 1.1842x; 1.1437x over previous
#include <cuda_runtime.h>
#include <math.h>
#include <stdint.h>

// ---------------- problem constants ----------------
#define BB 32
#define LL 1024
#define DD 256
#define HH 4
#define EE 64
#define NBAND 308          // f = 205..512
#define F0 205
#define TOPK 34

// ---------------- scratch layout (floats) ----------------
constexpr size_t SZ   = (size_t)BB * LL * DD;        // 8388608
constexpr size_t SPEC = (size_t)BB * DD * 640;       // 5242880 (8192 x 640)

constexpr size_t O_Q    = 0;
constexpr size_t O_K    = O_Q + SZ;
constexpr size_t O_V    = O_K + SZ;
constexpr size_t O_QT   = O_V + SZ;
constexpr size_t O_KT   = O_QT + SZ;
constexpr size_t O_VT   = O_KT + SZ;
constexpr size_t O_SPQ  = O_VT + SZ;
constexpr size_t O_SPK  = O_SPQ + SPEC;
constexpr size_t O_SPV  = O_SPK + SPEC;
constexpr size_t O_QS   = O_SPV + SPEC;
constexpr size_t O_VS   = O_QS + SZ;
constexpr size_t O_CSP  = O_VS + SZ;       // ctx spatial (B,L,D)
constexpr size_t O_AGG  = O_CSP + SZ;      // time agg (B,D,L)
constexpr size_t O_CTX  = O_AGG + SZ;      // mixed context (B,L,D)
constexpr size_t O_T1   = O_CTX + SZ;
constexpr size_t O_H    = O_T1 + SZ;
constexpr size_t O_G1   = O_H + SZ;
constexpr size_t O_F    = O_G1 + SZ;
constexpr size_t O_BF   = O_F + SZ;              // fwd basis 1024x640
constexpr size_t O_BI   = O_BF + 1024 * 640;     // inv basis 640x1024
constexpr size_t O_S    = O_BI + 640 * 1024;     // per-batch spectrum sum 32x640
constexpr size_t O_MV   = O_S + (size_t)BB * 640;  // mean_value 32x1024
constexpr size_t O_W    = O_MV + (size_t)BB * LL;  // weights 32x64
constexpr size_t TOTAL  = O_W + (size_t)BB * 64;

__device__ float g_scr[TOTAL + 1024];
__device__ int   g_idx[64];

// ---------------- fast exp on the FMA pipe (no MUFU) ----------------
// exp(x) for x <= 0 (softmax-style inputs). Clamp keeps 2^e finite.
__device__ __forceinline__ float fexp(float x) {
    x = fmaxf(x, -87.0f);
    float z = x * 1.4426950408889634f;
    float r = rintf(z);
    float f = z - r;                    // f in [-0.5, 0.5]
    float p = 1.5403530e-4f;            // (ln2)^6/720
    p = fmaf(p, f, 1.3333558e-3f);      // (ln2)^5/120
    p = fmaf(p, f, 9.6181291e-3f);      // (ln2)^4/24
    p = fmaf(p, f, 5.5504109e-2f);      // (ln2)^3/6
    p = fmaf(p, f, 2.4022651e-1f);      // (ln2)^2/2
    p = fmaf(p, f, 6.9314718e-1f);      // ln2
    p = fmaf(p, f, 1.0f);
    int e = (int)r;
    return __int_as_float((e + 127) << 23) * p;
}

// ---------------- basis fill ----------------
__global__ void fill_fwd_k(float* __restrict__ F) {
    int t = blockIdx.x;           // 0..1023
    int j = threadIdx.x;          // 0..639
    float v = 0.f;
    if (j < NBAND || (j >= 320 && j < 320 + NBAND)) {
        int f = F0 + ((j < 320) ? j : (j - 320));
        int m = (f * t) & 1023;
        float ang = 6.283185307179586f * (float)m / 1024.0f;
        v = (j < 320) ? cosf(ang) : -sinf(ang);   // re: cos, im: -sin
    }
    F[(size_t)t * 640 + j] = v;
}

__global__ void fill_inv_k(float* __restrict__ G) {
    int row = blockIdx.x;         // 0..639
    int t = threadIdx.x;          // 0..1023
    float v = 0.f;
    const float inv_l = 1.0f / 1024.0f;
    if (row < NBAND) {
        int f = F0 + row;
        if (f == 512) v = ((t & 1) ? -1.f : 1.f) * inv_l;
        else {
            int m = (f * t) & 1023;
            v = 2.f * inv_l * cosf(6.283185307179586f * (float)m / 1024.0f);
        }
    } else if (row >= 320 && row < 320 + NBAND) {
        int f = F0 + row - 320;
        if (f != 512) {
            int m = (f * t) & 1023;
            v = -2.f * inv_l * sinf(6.283185307179586f * (float)m / 1024.0f);
        }
    }
    G[(size_t)row * 1024 + t] = v;
}

// ---------------- SGEMM (R3 proven version): C = A@B (+epilogue) -----------
// EPI: 0 none, 1 +bias, 2 +bias+res, 3 +bias then gelu(erf)
template<int EPI>
__global__ void __launch_bounds__(256) gemm_k(
    const float* __restrict__ A, const float* __restrict__ Bw,
    const float* __restrict__ bias, const float* __restrict__ res,
    float* __restrict__ C, int M, int N, int K)
{
    __shared__ float As[16][128];
    __shared__ float Bs[16][132];
    const int bn = blockIdx.x * 128;
    const int bm = blockIdx.y * 128;
    const int tid = threadIdx.x;
    const int tr = tid >> 4, tc = tid & 15;
    float acc[8][8];
#pragma unroll
    for (int i = 0; i < 8; i++)
#pragma unroll
        for (int j = 0; j < 8; j++) acc[i][j] = 0.f;

    for (int k0 = 0; k0 < K; k0 += 16) {
#pragma unroll
        for (int u = 0; u < 2; u++) {
            int id = tid + u * 256;
            int row = id >> 2, c4 = id & 3;
            float4 av = *(const float4*)&A[(size_t)(bm + row) * K + k0 + c4 * 4];
            As[c4 * 4 + 0][row] = av.x;
            As[c4 * 4 + 1][row] = av.y;
            As[c4 * 4 + 2][row] = av.z;
            As[c4 * 4 + 3][row] = av.w;
            int r = id >> 5, cc = id & 31;
            *(float4*)&Bs[r][cc * 4] =
                *(const float4*)&Bw[(size_t)(k0 + r) * N + bn + cc * 4];
        }
        __syncthreads();
#pragma unroll
        for (int kk = 0; kk < 16; kk++) {
            float a[8], b[8];
            *(float4*)(a)     = *(float4*)&As[kk][tr * 8];
            *(float4*)(a + 4) = *(float4*)&As[kk][tr * 8 + 4];
            *(float4*)(b)     = *(float4*)&Bs[kk][tc * 8];
            *(float4*)(b + 4) = *(float4*)&Bs[kk][tc * 8 + 4];
#pragma unroll
            for (int i = 0; i < 8; i++)
#pragma unroll
                for (int j = 0; j < 8; j++) acc[i][j] = fmaf(a[i], b[j], acc[i][j]);
        }
        __syncthreads();
    }
#pragma unroll
    for (int i = 0; i < 8; i++) {
        int row = bm + tr * 8 + i;
#pragma unroll
        for (int jj = 0; jj < 2; jj++) {
            int col = bn + tc * 8 + jj * 4;
            float o[4];
#pragma unroll
            for (int q = 0; q < 4; q++) o[q] = acc[i][jj * 4 + q];
            if (EPI >= 1) {
                float4 bbv = *(const float4*)&bias[col];
                o[0] += bbv.x; o[1] += bbv.y; o[2] += bbv.z; o[3] += bbv.w;
            }
            if (EPI == 2) {
                float4 rr = *(const float4*)&res[(size_t)row * N + col];
                o[0] += rr.x; o[1] += rr.y; o[2] += rr.z; o[3] += rr.w;
            }
            if (EPI == 3) {
#pragma unroll
                for (int q = 0; q < 4; q++)
                    o[q] = o[q] * 0.5f * (1.0f + erff(o[q] * 0.70710678118654752f));
            }
            float4 ov; ov.x = o[0]; ov.y = o[1]; ov.z = o[2]; ov.w = o[3];
            *(float4*)&C[(size_t)row * N + col] = ov;
        }
    }
}

// ---------------- transpose (B,L,D) -> (B,D,L) ----------------
__global__ void transpose_k(const float* __restrict__ in, float* __restrict__ out)
{
    __shared__ float tile[32][33];
    int b = blockIdx.z;
    int l0 = blockIdx.x * 32, d0 = blockIdx.y * 32;
    int x = threadIdx.x, y = threadIdx.y;
#pragma unroll
    for (int i = 0; i < 32; i += 8)
        tile[y + i][x] = in[((size_t)b * LL + l0 + y + i) * DD + d0 + x];
    __syncthreads();
#pragma unroll
    for (int i = 0; i < 32; i += 8)
        out[((size_t)b * DD + d0 + y + i) * LL + l0 + x] = tile[x][y + i];
}

// ---------------- per-batch spectrum sum S[b,f] = sum_rows Q conj(K) --------
__global__ void corr_spec_k(const float* __restrict__ Qs, const float* __restrict__ Ks,
                            float* __restrict__ S)
{
    int j = blockIdx.x;   // 0..307
    int b = blockIdx.y;   // 0..31
    int t = threadIdx.x;  // 0..255
    size_t row = (size_t)(b * 256 + t) * 640;
    float qr = Qs[row + j], qi = Qs[row + 320 + j];
    float kr = Ks[row + j], ki = Ks[row + 320 + j];
    float re = qr * kr + qi * ki;
    float im = qi * kr - qr * ki;
    __shared__ float sr[256], si[256];
    sr[t] = re; si[t] = im; __syncthreads();
    for (int s = 128; s > 0; s >>= 1) {
        if (t < s) { sr[t] += sr[t + s]; si[t] += si[t + s]; }
        __syncthreads();
    }
    if (t == 0) { S[(size_t)b * 640 + j] = sr[0]; S[(size_t)b * 640 + 320 + j] = si[0]; }
}

// ---------------- mean_value[b,t] = (1/256) irfft(S*mask)[t] ----------------
__global__ void meanv_k(const float* __restrict__ S, float* __restrict__ mv)
{
    int b = blockIdx.x, t = threadIdx.x;  // 256 threads
    __shared__ float sre[NBAND], sim[NBAND], tbl[1024];
    for (int j = t; j < NBAND; j += 256) {
        sre[j] = S[(size_t)b * 640 + j];
        sim[j] = S[(size_t)b * 640 + 320 + j];
    }
    for (int m = t; m < 1024; m += 256)
        tbl[m] = cosf(6.283185307179586f * (float)m / 1024.0f);
    __syncthreads();
    for (int tt = t; tt < 1024; tt += 256) {
        float acc = sre[NBAND - 1] * ((tt & 1) ? -1.f : 1.f);   // f=512 Nyquist
        for (int j = 0; j < NBAND - 1; j++) {
            int f = F0 + j;
            int m = (f * tt) & 1023;
            float c = tbl[m];
            float s = tbl[(m + 768) & 1023];   // sin(theta) = cos(theta + 3pi/2)
            acc += 2.f * (sre[j] * c - sim[j] * s);
        }
        mv[(size_t)b * 1024 + tt] = acc * (1.0f / (256.0f * 1024.0f));
    }
}

// ---------------- top-k over batch-mean ----------------
__global__ void topk_k(const float* __restrict__ mv, int* __restrict__ idxout)
{
    int t = threadIdx.x;  // 1024
    __shared__ float vals[1024];
    __shared__ float rv[1024];
    __shared__ int   ri[1024];
    float g = 0.f;
    for (int b = 0; b < BB; b++) g += mv[(size_t)b * 1024 + t];
    vals[t] = g;
    __syncthreads();
    for (int k = 0; k < TOPK; k++) {
        rv[t] = vals[t]; ri[t] = t; __syncthreads();
        for (int s = 512; s > 0; s >>= 1) {
            if (t < s) {
                if (rv[t + s] > rv[t] || (rv[t + s] == rv[t] && ri[t + s] < ri[t])) {
                    rv[t] = rv[t + s]; ri[t] = ri[t + s];
                }
            }
            __syncthreads();
        }
        if (t == 0) { idxout[k] = ri[0]; vals[ri[0]] = -3.4e38f; }
        __syncthreads();
    }
}

// ---------------- per-batch softmax weights ----------------
__global__ void weights_k(const float* __restrict__ mv, const int* __restrict__ idx,
                          float* __restrict__ w)
{
    int b = blockIdx.x, t = threadIdx.x;  // 64 threads
    __shared__ float sv[64];
    float v = (t < TOPK) ? mv[(size_t)b * 1024 + idx[t]] : -3.4e38f;
    sv[t] = v; __syncthreads();
    float mx = -3.4e38f;
    for (int i = 0; i < TOPK; i++) mx = fmaxf(mx, sv[i]);
    __syncthreads();
    float e = (t < TOPK) ? expf(v - mx) : 0.f;
    sv[t] = e; __syncthreads();
    float sm = 0.f;
    for (int i = 0; i < TOPK; i++) sm += sv[i];
    if (t < TOPK) w[(size_t)b * 64 + t] = e / sm;
}

// ---------------- flash attention (fp32 SIMT, poly exp) ----------------
// qs/ks/vs in (B,D,L) layout: row = b*256 + h*64 + e, col = l/s.
// out = csp in (B,L,D). scores scaled by 1/8, softmax over s (full 1024).
// NOTE: K operand is the RAW filtered-free Kt — valid because the band filter
// C is a symmetric projection: (qC)(kC)^T = qC k^T.
__global__ void __launch_bounds__(256) flash_k(
    const float* __restrict__ qs, const float* __restrict__ ks,
    const float* __restrict__ vs, float* __restrict__ out)
{
    extern __shared__ float sm[];
    float* Qs = sm;                 // [64][68]  (e-major: Qs[e][l])
    float* Ks = sm + 64 * 68;       // [64][68]  (e-major: Ks[e][s])
    float* Vs = sm + 2 * 64 * 68;   // [64][68]  (s-major: Vs[s][e])
    float* Ps = sm + 3 * 64 * 68;   // [64][68]  (l-major: Ps[l][s])
    const int bh = blockIdx.y, b = bh >> 2, h = bh & 3;
    const int l0 = blockIdx.x * 64;
    const float* Q  = qs + ((size_t)b * DD + h * EE) * LL;
    const float* Kp = ks + ((size_t)b * DD + h * EE) * LL;
    const float* V  = vs + ((size_t)b * DD + h * EE) * LL;
    const int tid = threadIdx.x;
    const int tr = tid >> 4, tc = tid & 15;
    const int le = tid >> 2;        // 0..63
    const int lq = tid & 3;         // 0..3

    // load Q tile (once)
#pragma unroll
    for (int w = 0; w < 4; w++) {
        int col = w * 16 + lq * 4;
        *(float4*)&Qs[le * 68 + col] = *(const float4*)&Q[(size_t)le * LL + l0 + col];
    }

    float m_i[4], l_i[4], o[4][4];
#pragma unroll
    for (int i = 0; i < 4; i++) {
        m_i[i] = -1e30f; l_i[i] = 0.f;
#pragma unroll
        for (int j = 0; j < 4; j++) o[i][j] = 0.f;
    }

    for (int s0 = 0; s0 < LL; s0 += 64) {
        __syncthreads();   // previous iteration done with Ks/Vs/Ps
#pragma unroll
        for (int w = 0; w < 4; w++) {
            int col = w * 16 + lq * 4;
            *(float4*)&Ks[le * 68 + col] = *(const float4*)&Kp[(size_t)le * LL + s0 + col];
            float4 vv = *(const float4*)&V[(size_t)le * LL + s0 + col];
            Vs[(col + 0) * 68 + le] = vv.x;
            Vs[(col + 1) * 68 + le] = vv.y;
            Vs[(col + 2) * 68 + le] = vv.z;
            Vs[(col + 3) * 68 + le] = vv.w;
        }
        __syncthreads();

        // S[l][s] = sum_e Q[e][l] K[e][s]
        float s_[4][4];
#pragma unroll
        for (int i = 0; i < 4; i++)
#pragma unroll
            for (int j = 0; j < 4; j++) s_[i][j] = 0.f;
        for (int e4 = 0; e4 < 16; e4++) {
            float qa[4][4], kb[4][4];
#pragma unroll
            for (int c = 0; c < 4; c++) {
                float4 t1 = *(float4*)&Qs[(e4 * 4 + c) * 68 + tr * 4];
                qa[c][0] = t1.x; qa[c][1] = t1.y; qa[c][2] = t1.z; qa[c][3] = t1.w;
                float4 t2 = *(float4*)&Ks[(e4 * 4 + c) * 68 + tc * 4];
                kb[c][0] = t2.x; kb[c][1] = t2.y; kb[c][2] = t2.z; kb[c][3] = t2.w;
            }
#pragma unroll
            for (int c = 0; c < 4; c++)
#pragma unroll
                for (int i = 0; i < 4; i++)
#pragma unroll
                    for (int j = 0; j < 4; j++)
                        s_[i][j] = fmaf(qa[c][i], kb[c][j], s_[i][j]);
        }

        // online softmax per row (l = tr*4+i), reduce across 16 tc lanes
#pragma unroll
        for (int i = 0; i < 4; i++) {
            float mx = -1e30f;
#pragma unroll
            for (int j = 0; j < 4; j++) {
                s_[i][j] *= 0.125f;
                mx = fmaxf(mx, s_[i][j]);
            }
#pragma unroll
            for (int off = 8; off > 0; off >>= 1)
                mx = fmaxf(mx, __shfl_xor_sync(0xffffffffu, mx, off));
            float mn = fmaxf(m_i[i], mx);
            float alpha = fexp(m_i[i] - mn);
            float p0 = fexp(s_[i][0] - mn);
            float p1 = fexp(s_[i][1] - mn);
            float p2 = fexp(s_[i][2] - mn);
            float p3 = fexp(s_[i][3] - mn);
            float ps = p0 + p1 + p2 + p3;
#pragma unroll
            for (int off = 8; off > 0; off >>= 1)
                ps += __shfl_xor_sync(0xffffffffu, ps, off);
            l_i[i] = l_i[i] * alpha + ps;
            m_i[i] = mn;
#pragma unroll
            for (int j = 0; j < 4; j++) o[i][j] *= alpha;
            float4 pv; pv.x = p0; pv.y = p1; pv.z = p2; pv.w = p3;
            *(float4*)&Ps[(tr * 4 + i) * 68 + tc * 4] = pv;
        }
        __syncthreads();

        // O[l][e] += sum_s P[l][s] V[s][e]
        for (int s4 = 0; s4 < 16; s4++) {
            float av[4][4], bv[4][4];
#pragma unroll
            for (int i = 0; i < 4; i++) {
                float4 t1 = *(float4*)&Ps[(tr * 4 + i) * 68 + s4 * 4];
                av[i][0] = t1.x; av[i][1] = t1.y; av[i][2] = t1.z; av[i][3] = t1.w;
            }
#pragma unroll
            for (int c = 0; c < 4; c++) {
                float4 t2 = *(float4*)&Vs[(s4 * 4 + c) * 68 + tc * 4];
                bv[c][0] = t2.x; bv[c][1] = t2.y; bv[c][2] = t2.z; bv[c][3] = t2.w;
            }
#pragma unroll
            for (int c = 0; c < 4; c++)
#pragma unroll
                for (int i = 0; i < 4; i++)
#pragma unroll
                    for (int j = 0; j < 4; j++)
                        o[i][j] = fmaf(av[i][c], bv[c][j], o[i][j]);
        }
    }

    // epilogue: normalize and store to (B,L,D)
#pragma unroll
    for (int i = 0; i < 4; i++) {
        float inv = 1.0f / l_i[i];
        float4 ov;
        ov.x = o[i][0] * inv; ov.y = o[i][1] * inv;
        ov.z = o[i][2] * inv; ov.w = o[i][3] * inv;
        size_t off = ((size_t)b * LL + l0 + tr * 4 + i) * DD + h * EE + tc * 4;
        *(float4*)&out[off] = ov;
    }
}

// ---------------- time delay aggregation (B,D,L) ----------------
__global__ void timeagg_k(const float* __restrict__ Vt, const float* __restrict__ w,
                          const int* __restrict__ idx, float* __restrict__ agg)
{
    int bd = blockIdx.x;        // b*256+d
    int b = bd >> 8;
    __shared__ float row[1024];
    __shared__ float ws[TOPK];
    __shared__ int   is[TOPK];
    int t = threadIdx.x;        // 256
    for (int l = t; l < 1024; l += 256) row[l] = Vt[(size_t)bd * 1024 + l];
    if (t < TOPK) { ws[t] = w[(size_t)b * 64 + t]; is[t] = idx[t]; }
    __syncthreads();
    for (int l = t; l < 1024; l += 256) {
        float a = 0.f;
#pragma unroll
        for (int k = 0; k < TOPK; k++) a = fmaf(ws[k], row[(l + is[k]) & 1023], a);
        agg[(size_t)bd * 1024 + l] = a;
    }
}

// ---------------- context = 0.9*agg^T + 0.1*ctx_sp ----------------
__global__ void mix_k(const float* __restrict__ agg, const float* __restrict__ csp,
                      float* __restrict__ ctx)
{
    __shared__ float tile[32][33];
    int b = blockIdx.z;
    int l0 = blockIdx.x * 32, d0 = blockIdx.y * 32;
    int x = threadIdx.x, y = threadIdx.y;
#pragma unroll
    for (int i = 0; i < 32; i += 8)
        tile[y + i][x] = agg[((size_t)b * DD + d0 + y + i) * LL + l0 + x];  // tile[d][l]
    __syncthreads();
#pragma unroll
    for (int i = 0; i < 32; i += 8) {
        size_t o = ((size_t)b * LL + l0 + y + i) * DD + d0 + x;
        ctx[o] = 0.9f * tile[x][y + i] + 0.1f * csp[o];
    }
}

// ---------------- LayerNorm over D=256 ----------------
__global__ void ln_k(const float* __restrict__ in, const float* __restrict__ g,
                     const float* __restrict__ b, float* __restrict__ out)
{
    size_t row = blockIdx.x;
    int t = threadIdx.x;   // 256
    float v = in[row * DD + t];
    __shared__ float red[256];
    red[t] = v; __syncthreads();
    for (int s = 128; s > 0; s >>= 1) { if (t < s) red[t] += red[t + s]; __syncthreads(); }
    float m = red[0] * (1.0f / 256.0f);
    __syncthreads();
    float d = v - m;
    red[t] = d * d; __syncthreads();
    for (int s = 128; s > 0; s >>= 1) { if (t < s) red[t] += red[t + s]; __syncthreads(); }
    float var = red[0] * (1.0f / 256.0f);
    out[row * DD + t] = d * rsqrtf(var + 1e-8f) * g[t] + b[t];
}

// ---------------- launch ----------------
extern "C" void kernel_launch(void* const* d_in, const int* in_sizes, int n_in,
                              void* d_out, int out_size)
{
    const float* x   = (const float*)d_in[0];
    const float* Wq  = (const float*)d_in[1];
    const float* bq  = (const float*)d_in[2];
    const float* Wk  = (const float*)d_in[3];
    const float* bk  = (const float*)d_in[4];
    const float* Wv  = (const float*)d_in[5];
    const float* bv  = (const float*)d_in[6];
    const float* Wd  = (const float*)d_in[7];
    const float* bd  = (const float*)d_in[8];
    const float* ln1g = (const float*)d_in[9];
    const float* ln1b = (const float*)d_in[10];
    const float* W1  = (const float*)d_in[11];
    const float* b1  = (const float*)d_in[12];
    const float* W2  = (const float*)d_in[13];
    const float* b2  = (const float*)d_in[14];
    const float* ln2g = (const float*)d_in[15];
    const float* ln2b = (const float*)d_in[16];
    float* out = (float*)d_out;

    float* scr = nullptr;
    int* idxp = nullptr;
    cudaGetSymbolAddress((void**)&scr, g_scr);
    cudaGetSymbolAddress((void**)&idxp, g_idx);

    float* bQ   = scr + O_Q;   float* bK  = scr + O_K;   float* bV  = scr + O_V;
    float* Qt   = scr + O_QT;  float* Kt  = scr + O_KT;  float* Vt  = scr + O_VT;
    float* spQ  = scr + O_SPQ; float* spK = scr + O_SPK; float* spV = scr + O_SPV;
    float* qsb  = scr + O_QS;  float* vsb = scr + O_VS;
    float* csp  = scr + O_CSP; float* agg = scr + O_AGG; float* ctx = scr + O_CTX;
    float* t1   = scr + O_T1;  float* hb  = scr + O_H;
    float* g1b  = scr + O_G1;  float* fb  = scr + O_F;
    float* basF = scr + O_BF;  float* basI = scr + O_BI;
    float* Sb   = scr + O_S;   float* mv  = scr + O_MV;  float* wts = scr + O_W;

    const int flash_smem = 4 * 64 * 68 * sizeof(float);   // 69632 B
    cudaFuncSetAttribute(flash_k, cudaFuncAttributeMaxDynamicSharedMemorySize, flash_smem);

    // 1. DFT bases
    fill_fwd_k<<<1024, 640>>>(basF);
    fill_inv_k<<<640, 1024>>>(basI);

    // 2. QKV projections (M=32768, N=256, K=256)
    {
        dim3 g(2, 256);
        gemm_k<1><<<g, 256>>>(x, Wq, bq, nullptr, bQ, BB * LL, DD, DD);
        gemm_k<1><<<g, 256>>>(x, Wk, bk, nullptr, bK, BB * LL, DD, DD);
        gemm_k<1><<<g, 256>>>(x, Wv, bv, nullptr, bV, BB * LL, DD, DD);
    }

    // 3. transpose to (B,D,L)
    {
        dim3 g(32, 8, 32), blk(32, 8);
        transpose_k<<<g, blk>>>(bQ, Qt);
        transpose_k<<<g, blk>>>(bK, Kt);
        transpose_k<<<g, blk>>>(bV, Vt);
    }

    // 4. forward band DFT (M=8192, N=640, K=1024)
    {
        dim3 g(5, 64);
        gemm_k<0><<<g, 256>>>(Qt, basF, nullptr, nullptr, spQ, BB * DD, 640, LL);
        gemm_k<0><<<g, 256>>>(Kt, basF, nullptr, nullptr, spK, BB * DD, 640, LL);
        gemm_k<0><<<g, 256>>>(Vt, basF, nullptr, nullptr, spV, BB * DD, 640, LL);
    }

    // 5. corr mean path
    corr_spec_k<<<dim3(NBAND, BB), 256>>>(spQ, spK, Sb);
    meanv_k<<<BB, 256>>>(Sb, mv);
    topk_k<<<1, 1024>>>(mv, idxp);
    weights_k<<<BB, 64>>>(mv, idxp, wts);

    // 6. inverse band DFT -> qs, vs (M=8192, N=1024, K=640).
    //    ks is NOT needed: scores = (qC)(kC)^T = (qC)k^T since C is a
    //    symmetric idempotent band projection.
    {
        dim3 g(8, 64);
        gemm_k<0><<<g, 256>>>(spQ, basI, nullptr, nullptr, qsb, BB * DD, LL, 640);
        gemm_k<0><<<g, 256>>>(spV, basI, nullptr, nullptr, vsb, BB * DD, LL, 640);
    }

    // 7. spatial attention (flash-fused; K = raw Kt)
    flash_k<<<dim3(16, BB * HH), 256, flash_smem>>>(qsb, Kt, vsb, csp);

    // 8. time aggregation + mix
    timeagg_k<<<BB * DD, 256>>>(Vt, wts, idxp, agg);
    mix_k<<<dim3(32, 8, 32), dim3(32, 8)>>>(agg, csp, ctx);

    // 9. output projection + residual + LN1
    gemm_k<2><<<dim3(2, 256), 256>>>(ctx, Wd, bd, x, t1, BB * LL, DD, DD);
    ln_k<<<BB * LL, 256>>>(t1, ln1g, ln1b, hb);

    // 10. FFN + LN2
    gemm_k<3><<<dim3(2, 256), 256>>>(hb, W1, b1, nullptr, g1b, BB * LL, DD, DD);
    gemm_k<2><<<dim3(2, 256), 256>>>(g1b, W2, b2, hb, fb, BB * LL, DD, DD);
    ln_k<<<BB * LL, 256>>>(fb, ln2g, ln2b, out);
}

// round 6
// speedup vs baseline: 1.2618x; 1.0655x over previous
#include <cuda_runtime.h>
#include <math.h>
#include <stdint.h>

// ---------------- problem constants ----------------
#define BB 32
#define LL 1024
#define DD 256
#define HH 4
#define EE 64
#define NBAND 308          // f = 205..512
#define F0 205
#define TOPK 34

// ---------------- scratch layout (floats) ----------------
constexpr size_t SZ   = (size_t)BB * LL * DD;        // 8388608
constexpr size_t SPEC = (size_t)BB * DD * 640;       // 5242880 (8192 x 640)

constexpr size_t O_Q    = 0;
constexpr size_t O_K    = O_Q + SZ;
constexpr size_t O_V    = O_K + SZ;
constexpr size_t O_KT   = O_V + SZ;
constexpr size_t O_VT   = O_KT + SZ;
constexpr size_t O_TR   = O_VT + SZ;       // shared transpose buffer (xT/ctxT/hbT/g1bT)
constexpr size_t O_SPQ  = O_TR + SZ;
constexpr size_t O_SPK  = O_SPQ + SPEC;
constexpr size_t O_SPV  = O_SPK + SPEC;
constexpr size_t O_SPT  = O_SPV + SPEC;    // shared transpose buffer (spQt/spVt)
constexpr size_t O_QS   = O_SPT + SPEC;
constexpr size_t O_VS   = O_QS + SZ;
constexpr size_t O_CSP  = O_VS + SZ;       // ctx spatial (B,L,D)
constexpr size_t O_AGG  = O_CSP + SZ;      // time agg (B,D,L)
constexpr size_t O_CTX  = O_AGG + SZ;      // mixed context (B,L,D)
constexpr size_t O_T1   = O_CTX + SZ;
constexpr size_t O_H    = O_T1 + SZ;
constexpr size_t O_G1   = O_H + SZ;
constexpr size_t O_F    = O_G1 + SZ;
constexpr size_t O_BF   = O_F + SZ;              // fwd basis 1024x640
constexpr size_t O_BI   = O_BF + 1024 * 640;     // inv basis 640x1024
constexpr size_t O_S    = O_BI + 640 * 1024;     // per-batch spectrum sum 32x640
constexpr size_t O_MV   = O_S + (size_t)BB * 640;  // mean_value 32x1024
constexpr size_t O_W    = O_MV + (size_t)BB * LL;  // weights 32x64
constexpr size_t TOTAL  = O_W + (size_t)BB * 64;

__device__ float g_scr[TOTAL + 1024];
__device__ int   g_idx[64];

// ---------------- cp.async helpers ----------------
__device__ __forceinline__ void cpa16(uint32_t saddr, const void* gptr) {
    asm volatile("cp.async.cg.shared.global [%0], [%1], 16;" :: "r"(saddr), "l"(gptr));
}
__device__ __forceinline__ void cpa_commit() {
    asm volatile("cp.async.commit_group;");
}
template<int N>
__device__ __forceinline__ void cpa_wait() {
    asm volatile("cp.async.wait_group %0;" :: "n"(N));
}

// ---------------- fast exp on the FMA pipe (no MUFU) ----------------
__device__ __forceinline__ float fexp(float x) {
    x = fmaxf(x, -87.0f);
    float z = x * 1.4426950408889634f;
    float r = rintf(z);
    float f = z - r;                    // f in [-0.5, 0.5]
    float p = 1.5403530e-4f;
    p = fmaf(p, f, 1.3333558e-3f);
    p = fmaf(p, f, 9.6181291e-3f);
    p = fmaf(p, f, 5.5504109e-2f);
    p = fmaf(p, f, 2.4022651e-1f);
    p = fmaf(p, f, 6.9314718e-1f);
    p = fmaf(p, f, 1.0f);
    int e = (int)r;
    return __int_as_float((e + 127) << 23) * p;
}

// ---------------- basis fill ----------------
__global__ void fill_fwd_k(float* __restrict__ F) {
    int t = blockIdx.x;           // 0..1023
    int j = threadIdx.x;          // 0..639
    float v = 0.f;
    if (j < NBAND || (j >= 320 && j < 320 + NBAND)) {
        int f = F0 + ((j < 320) ? j : (j - 320));
        int m = (f * t) & 1023;
        float ang = 6.283185307179586f * (float)m / 1024.0f;
        v = (j < 320) ? cosf(ang) : -sinf(ang);   // re: cos, im: -sin
    }
    F[(size_t)t * 640 + j] = v;
}

__global__ void fill_inv_k(float* __restrict__ G) {
    int row = blockIdx.x;         // 0..639
    int t = threadIdx.x;          // 0..1023
    float v = 0.f;
    const float inv_l = 1.0f / 1024.0f;
    if (row < NBAND) {
        int f = F0 + row;
        if (f == 512) v = ((t & 1) ? -1.f : 1.f) * inv_l;
        else {
            int m = (f * t) & 1023;
            v = 2.f * inv_l * cosf(6.283185307179586f * (float)m / 1024.0f);
        }
    } else if (row >= 320 && row < 320 + NBAND) {
        int f = F0 + row - 320;
        if (f != 512) {
            int m = (f * t) & 1023;
            v = -2.f * inv_l * sinf(6.283185307179586f * (float)m / 1024.0f);
        }
    }
    G[(size_t)row * 1024 + t] = v;
}

// ---------------- cp.async double-buffered GEMM on AT operand --------------
// C_b[M,N] = (AT_b)^T @ Bw  where AT_b is [K][M] (k-major). Batched over z.
// EPI: 0 none, 1 +bias, 2 +bias+res, 3 +bias then gelu(erf)
template<int EPI>
__global__ void __launch_bounds__(256) gemm_t(
    const float* __restrict__ AT, const float* __restrict__ Bw,
    const float* __restrict__ bias, const float* __restrict__ res,
    float* __restrict__ C, int M, int N, int K,
    size_t sAT, size_t sC)
{
    __shared__ float As[2][16][128];
    __shared__ float Bs[2][16][132];
    const int bz = blockIdx.z;
    const float* A = AT + (size_t)bz * sAT;
    float* Cb = C + (size_t)bz * sC;
    const int bn = blockIdx.x * 128;
    const int bm = blockIdx.y * 128;
    const int tid = threadIdx.x;
    const int tr = tid >> 4, tc = tid & 15;

    const int r0 = tid >> 5;          // 0..7
    const int r1 = r0 + 8;            // 8..15
    const int c0 = (tid & 31) * 4;    // 0..124

    const uint32_t asb = (uint32_t)__cvta_generic_to_shared(&As[0][0][0]);
    const uint32_t bsb = (uint32_t)__cvta_generic_to_shared(&Bs[0][0][0]);
    const uint32_t aO0 = (uint32_t)(r0 * 128 + c0) * 4;
    const uint32_t aO1 = (uint32_t)(r1 * 128 + c0) * 4;
    const uint32_t bO0 = (uint32_t)(r0 * 132 + c0) * 4;
    const uint32_t bO1 = (uint32_t)(r1 * 132 + c0) * 4;

    const int T = K >> 4;

    // prologue: stage 0
    {
        const float* ab = A + bm + c0;
        cpa16(asb + aO0, ab + (size_t)r0 * M);
        cpa16(asb + aO1, ab + (size_t)r1 * M);
        const float* bb = Bw + bn + c0;
        cpa16(bsb + bO0, bb + (size_t)r0 * N);
        cpa16(bsb + bO1, bb + (size_t)r1 * N);
        cpa_commit();
    }

    float acc[8][8];
#pragma unroll
    for (int i = 0; i < 8; i++)
#pragma unroll
        for (int j = 0; j < 8; j++) acc[i][j] = 0.f;

    for (int kt = 0; kt < T; kt++) {
        if (kt + 1 < T) {
            int st = (kt + 1) & 1;
            int k1 = (kt + 1) << 4;
            const float* ab = A + (size_t)k1 * M + bm + c0;
            cpa16(asb + st * 8192 + aO0, ab + (size_t)r0 * M);
            cpa16(asb + st * 8192 + aO1, ab + (size_t)r1 * M);
            const float* bb = Bw + (size_t)k1 * N + bn + c0;
            cpa16(bsb + st * 8448 + bO0, bb + (size_t)r0 * N);
            cpa16(bsb + st * 8448 + bO1, bb + (size_t)r1 * N);
            cpa_commit();
            cpa_wait<1>();
        } else {
            cpa_wait<0>();
        }
        __syncthreads();

        const int st = kt & 1;
#pragma unroll
        for (int kk = 0; kk < 16; kk++) {
            float a[8], b[8];
            *(float4*)(a)     = *(float4*)&As[st][kk][tr * 8];
            *(float4*)(a + 4) = *(float4*)&As[st][kk][tr * 8 + 4];
            *(float4*)(b)     = *(float4*)&Bs[st][kk][tc * 8];
            *(float4*)(b + 4) = *(float4*)&Bs[st][kk][tc * 8 + 4];
#pragma unroll
            for (int i = 0; i < 8; i++)
#pragma unroll
                for (int j = 0; j < 8; j++) acc[i][j] = fmaf(a[i], b[j], acc[i][j]);
        }
        __syncthreads();
    }

#pragma unroll
    for (int i = 0; i < 8; i++) {
        int row = bm + tr * 8 + i;
#pragma unroll
        for (int jj = 0; jj < 2; jj++) {
            int col = bn + tc * 8 + jj * 4;
            float o[4];
#pragma unroll
            for (int q = 0; q < 4; q++) o[q] = acc[i][jj * 4 + q];
            if (EPI >= 1) {
                float4 bbv = *(const float4*)&bias[col];
                o[0] += bbv.x; o[1] += bbv.y; o[2] += bbv.z; o[3] += bbv.w;
            }
            if (EPI == 2) {
                float4 rr = *(const float4*)&res[(size_t)row * N + col];
                o[0] += rr.x; o[1] += rr.y; o[2] += rr.z; o[3] += rr.w;
            }
            if (EPI == 3) {
#pragma unroll
                for (int q = 0; q < 4; q++)
                    o[q] = o[q] * 0.5f * (1.0f + erff(o[q] * 0.70710678118654752f));
            }
            float4 ov; ov.x = o[0]; ov.y = o[1]; ov.z = o[2]; ov.w = o[3];
            *(float4*)&Cb[(size_t)row * N + col] = ov;
        }
    }
}

// ---------------- generic batched transpose: in[R][Cc] -> out[Cc][R] --------
__global__ void tr_k(const float* __restrict__ in, float* __restrict__ out,
                     int R, int Cc, size_t sIn, size_t sOut)
{
    __shared__ float tile[32][33];
    int b = blockIdx.z;
    const float* I = in + (size_t)b * sIn;
    float* O = out + (size_t)b * sOut;
    int c0 = blockIdx.x * 32, r0 = blockIdx.y * 32;
    int x = threadIdx.x, y = threadIdx.y;
#pragma unroll
    for (int i = 0; i < 32; i += 8)
        tile[y + i][x] = I[(size_t)(r0 + y + i) * Cc + c0 + x];
    __syncthreads();
#pragma unroll
    for (int i = 0; i < 32; i += 8)
        O[(size_t)(c0 + y + i) * R + r0 + x] = tile[x][y + i];
}

// ---------------- per-batch spectrum sum S[b,f] = sum_rows Q conj(K) --------
__global__ void corr_spec_k(const float* __restrict__ Qs, const float* __restrict__ Ks,
                            float* __restrict__ S)
{
    int j = blockIdx.x;   // 0..307
    int b = blockIdx.y;   // 0..31
    int t = threadIdx.x;  // 0..255
    size_t row = (size_t)(b * 256 + t) * 640;
    float qr = Qs[row + j], qi = Qs[row + 320 + j];
    float kr = Ks[row + j], ki = Ks[row + 320 + j];
    float re = qr * kr + qi * ki;
    float im = qi * kr - qr * ki;
    __shared__ float sr[256], si[256];
    sr[t] = re; si[t] = im; __syncthreads();
    for (int s = 128; s > 0; s >>= 1) {
        if (t < s) { sr[t] += sr[t + s]; si[t] += si[t + s]; }
        __syncthreads();
    }
    if (t == 0) { S[(size_t)b * 640 + j] = sr[0]; S[(size_t)b * 640 + 320 + j] = si[0]; }
}

// ---------------- mean_value[b,t] = (1/256) irfft(S*mask)[t] ----------------
__global__ void meanv_k(const float* __restrict__ S, float* __restrict__ mv)
{
    int b = blockIdx.x, t = threadIdx.x;  // 256 threads
    __shared__ float sre[NBAND], sim[NBAND], tbl[1024];
    for (int j = t; j < NBAND; j += 256) {
        sre[j] = S[(size_t)b * 640 + j];
        sim[j] = S[(size_t)b * 640 + 320 + j];
    }
    for (int m = t; m < 1024; m += 256)
        tbl[m] = cosf(6.283185307179586f * (float)m / 1024.0f);
    __syncthreads();
    for (int tt = t; tt < 1024; tt += 256) {
        float acc = sre[NBAND - 1] * ((tt & 1) ? -1.f : 1.f);   // f=512 Nyquist
        for (int j = 0; j < NBAND - 1; j++) {
            int f = F0 + j;
            int m = (f * tt) & 1023;
            float c = tbl[m];
            float s = tbl[(m + 768) & 1023];
            acc += 2.f * (sre[j] * c - sim[j] * s);
        }
        mv[(size_t)b * 1024 + tt] = acc * (1.0f / (256.0f * 1024.0f));
    }
}

// ---------------- top-k over batch-mean ----------------
__global__ void topk_k(const float* __restrict__ mv, int* __restrict__ idxout)
{
    int t = threadIdx.x;  // 1024
    __shared__ float vals[1024];
    __shared__ float rv[1024];
    __shared__ int   ri[1024];
    float g = 0.f;
    for (int b = 0; b < BB; b++) g += mv[(size_t)b * 1024 + t];
    vals[t] = g;
    __syncthreads();
    for (int k = 0; k < TOPK; k++) {
        rv[t] = vals[t]; ri[t] = t; __syncthreads();
        for (int s = 512; s > 0; s >>= 1) {
            if (t < s) {
                if (rv[t + s] > rv[t] || (rv[t + s] == rv[t] && ri[t + s] < ri[t])) {
                    rv[t] = rv[t + s]; ri[t] = ri[t + s];
                }
            }
            __syncthreads();
        }
        if (t == 0) { idxout[k] = ri[0]; vals[ri[0]] = -3.4e38f; }
        __syncthreads();
    }
}

// ---------------- per-batch softmax weights ----------------
__global__ void weights_k(const float* __restrict__ mv, const int* __restrict__ idx,
                          float* __restrict__ w)
{
    int b = blockIdx.x, t = threadIdx.x;  // 64 threads
    __shared__ float sv[64];
    float v = (t < TOPK) ? mv[(size_t)b * 1024 + idx[t]] : -3.4e38f;
    sv[t] = v; __syncthreads();
    float mx = -3.4e38f;
    for (int i = 0; i < TOPK; i++) mx = fmaxf(mx, sv[i]);
    __syncthreads();
    float e = (t < TOPK) ? expf(v - mx) : 0.f;
    sv[t] = e; __syncthreads();
    float sm = 0.f;
    for (int i = 0; i < TOPK; i++) sm += sv[i];
    if (t < TOPK) w[(size_t)b * 64 + t] = e / sm;
}

// ---------------- flash attention (fp32 SIMT, poly exp) ----------------
// qs/ks/vs in (B,D,L): row = b*256 + h*64 + e, col = l/s.  out in (B,L,D).
// K = raw Kt: valid since the band filter C is a symmetric projection.
__global__ void __launch_bounds__(256) flash_k(
    const float* __restrict__ qs, const float* __restrict__ ks,
    const float* __restrict__ vs, float* __restrict__ out)
{
    extern __shared__ float sm[];
    float* Qs = sm;
    float* Ks = sm + 64 * 68;
    float* Vs = sm + 2 * 64 * 68;
    float* Ps = sm + 3 * 64 * 68;
    const int bh = blockIdx.y, b = bh >> 2, h = bh & 3;
    const int l0 = blockIdx.x * 64;
    const float* Q  = qs + ((size_t)b * DD + h * EE) * LL;
    const float* Kp = ks + ((size_t)b * DD + h * EE) * LL;
    const float* V  = vs + ((size_t)b * DD + h * EE) * LL;
    const int tid = threadIdx.x;
    const int tr = tid >> 4, tc = tid & 15;
    const int le = tid >> 2;
    const int lq = tid & 3;

#pragma unroll
    for (int w = 0; w < 4; w++) {
        int col = w * 16 + lq * 4;
        *(float4*)&Qs[le * 68 + col] = *(const float4*)&Q[(size_t)le * LL + l0 + col];
    }

    float m_i[4], l_i[4], o[4][4];
#pragma unroll
    for (int i = 0; i < 4; i++) {
        m_i[i] = -1e30f; l_i[i] = 0.f;
#pragma unroll
        for (int j = 0; j < 4; j++) o[i][j] = 0.f;
    }

    for (int s0 = 0; s0 < LL; s0 += 64) {
        __syncthreads();
#pragma unroll
        for (int w = 0; w < 4; w++) {
            int col = w * 16 + lq * 4;
            *(float4*)&Ks[le * 68 + col] = *(const float4*)&Kp[(size_t)le * LL + s0 + col];
            float4 vv = *(const float4*)&V[(size_t)le * LL + s0 + col];
            Vs[(col + 0) * 68 + le] = vv.x;
            Vs[(col + 1) * 68 + le] = vv.y;
            Vs[(col + 2) * 68 + le] = vv.z;
            Vs[(col + 3) * 68 + le] = vv.w;
        }
        __syncthreads();

        float s_[4][4];
#pragma unroll
        for (int i = 0; i < 4; i++)
#pragma unroll
            for (int j = 0; j < 4; j++) s_[i][j] = 0.f;
        for (int e4 = 0; e4 < 16; e4++) {
            float qa[4][4], kb[4][4];
#pragma unroll
            for (int c = 0; c < 4; c++) {
                float4 t1 = *(float4*)&Qs[(e4 * 4 + c) * 68 + tr * 4];
                qa[c][0] = t1.x; qa[c][1] = t1.y; qa[c][2] = t1.z; qa[c][3] = t1.w;
                float4 t2 = *(float4*)&Ks[(e4 * 4 + c) * 68 + tc * 4];
                kb[c][0] = t2.x; kb[c][1] = t2.y; kb[c][2] = t2.z; kb[c][3] = t2.w;
            }
#pragma unroll
            for (int c = 0; c < 4; c++)
#pragma unroll
                for (int i = 0; i < 4; i++)
#pragma unroll
                    for (int j = 0; j < 4; j++)
                        s_[i][j] = fmaf(qa[c][i], kb[c][j], s_[i][j]);
        }

#pragma unroll
        for (int i = 0; i < 4; i++) {
            float mx = -1e30f;
#pragma unroll
            for (int j = 0; j < 4; j++) {
                s_[i][j] *= 0.125f;
                mx = fmaxf(mx, s_[i][j]);
            }
#pragma unroll
            for (int off = 8; off > 0; off >>= 1)
                mx = fmaxf(mx, __shfl_xor_sync(0xffffffffu, mx, off));
            float mn = fmaxf(m_i[i], mx);
            float alpha = fexp(m_i[i] - mn);
            float p0 = fexp(s_[i][0] - mn);
            float p1 = fexp(s_[i][1] - mn);
            float p2 = fexp(s_[i][2] - mn);
            float p3 = fexp(s_[i][3] - mn);
            float ps = p0 + p1 + p2 + p3;
#pragma unroll
            for (int off = 8; off > 0; off >>= 1)
                ps += __shfl_xor_sync(0xffffffffu, ps, off);
            l_i[i] = l_i[i] * alpha + ps;
            m_i[i] = mn;
#pragma unroll
            for (int j = 0; j < 4; j++) o[i][j] *= alpha;
            float4 pv; pv.x = p0; pv.y = p1; pv.z = p2; pv.w = p3;
            *(float4*)&Ps[(tr * 4 + i) * 68 + tc * 4] = pv;
        }
        __syncthreads();

        for (int s4 = 0; s4 < 16; s4++) {
            float av[4][4], bv[4][4];
#pragma unroll
            for (int i = 0; i < 4; i++) {
                float4 t1 = *(float4*)&Ps[(tr * 4 + i) * 68 + s4 * 4];
                av[i][0] = t1.x; av[i][1] = t1.y; av[i][2] = t1.z; av[i][3] = t1.w;
            }
#pragma unroll
            for (int c = 0; c < 4; c++) {
                float4 t2 = *(float4*)&Vs[(s4 * 4 + c) * 68 + tc * 4];
                bv[c][0] = t2.x; bv[c][1] = t2.y; bv[c][2] = t2.z; bv[c][3] = t2.w;
            }
#pragma unroll
            for (int c = 0; c < 4; c++)
#pragma unroll
                for (int i = 0; i < 4; i++)
#pragma unroll
                    for (int j = 0; j < 4; j++)
                        o[i][j] = fmaf(av[i][c], bv[c][j], o[i][j]);
        }
    }

#pragma unroll
    for (int i = 0; i < 4; i++) {
        float inv = 1.0f / l_i[i];
        float4 ov;
        ov.x = o[i][0] * inv; ov.y = o[i][1] * inv;
        ov.z = o[i][2] * inv; ov.w = o[i][3] * inv;
        size_t off = ((size_t)b * LL + l0 + tr * 4 + i) * DD + h * EE + tc * 4;
        *(float4*)&out[off] = ov;
    }
}

// ---------------- time delay aggregation (B,D,L) ----------------
__global__ void timeagg_k(const float* __restrict__ Vt, const float* __restrict__ w,
                          const int* __restrict__ idx, float* __restrict__ agg)
{
    int bd = blockIdx.x;        // b*256+d
    int b = bd >> 8;
    __shared__ float row[1024];
    __shared__ float ws[TOPK];
    __shared__ int   is[TOPK];
    int t = threadIdx.x;        // 256
    for (int l = t; l < 1024; l += 256) row[l] = Vt[(size_t)bd * 1024 + l];
    if (t < TOPK) { ws[t] = w[(size_t)b * 64 + t]; is[t] = idx[t]; }
    __syncthreads();
    for (int l = t; l < 1024; l += 256) {
        float a = 0.f;
#pragma unroll
        for (int k = 0; k < TOPK; k++) a = fmaf(ws[k], row[(l + is[k]) & 1023], a);
        agg[(size_t)bd * 1024 + l] = a;
    }
}

// ---------------- context = 0.9*agg^T + 0.1*ctx_sp ----------------
__global__ void mix_k(const float* __restrict__ agg, const float* __restrict__ csp,
                      float* __restrict__ ctx)
{
    __shared__ float tile[32][33];
    int b = blockIdx.z;
    int l0 = blockIdx.x * 32, d0 = blockIdx.y * 32;
    int x = threadIdx.x, y = threadIdx.y;
#pragma unroll
    for (int i = 0; i < 32; i += 8)
        tile[y + i][x] = agg[((size_t)b * DD + d0 + y + i) * LL + l0 + x];
    __syncthreads();
#pragma unroll
    for (int i = 0; i < 32; i += 8) {
        size_t o = ((size_t)b * LL + l0 + y + i) * DD + d0 + x;
        ctx[o] = 0.9f * tile[x][y + i] + 0.1f * csp[o];
    }
}

// ---------------- LayerNorm over D=256 ----------------
__global__ void ln_k(const float* __restrict__ in, const float* __restrict__ g,
                     const float* __restrict__ b, float* __restrict__ out)
{
    size_t row = blockIdx.x;
    int t = threadIdx.x;   // 256
    float v = in[row * DD + t];
    __shared__ float red[256];
    red[t] = v; __syncthreads();
    for (int s = 128; s > 0; s >>= 1) { if (t < s) red[t] += red[t + s]; __syncthreads(); }
    float m = red[0] * (1.0f / 256.0f);
    __syncthreads();
    float d = v - m;
    red[t] = d * d; __syncthreads();
    for (int s = 128; s > 0; s >>= 1) { if (t < s) red[t] += red[t + s]; __syncthreads(); }
    float var = red[0] * (1.0f / 256.0f);
    out[row * DD + t] = d * rsqrtf(var + 1e-8f) * g[t] + b[t];
}

// ---------------- launch ----------------
extern "C" void kernel_launch(void* const* d_in, const int* in_sizes, int n_in,
                              void* d_out, int out_size)
{
    const float* x   = (const float*)d_in[0];
    const float* Wq  = (const float*)d_in[1];
    const float* bq  = (const float*)d_in[2];
    const float* Wk  = (const float*)d_in[3];
    const float* bk  = (const float*)d_in[4];
    const float* Wv  = (const float*)d_in[5];
    const float* bv  = (const float*)d_in[6];
    const float* Wd  = (const float*)d_in[7];
    const float* bd  = (const float*)d_in[8];
    const float* ln1g = (const float*)d_in[9];
    const float* ln1b = (const float*)d_in[10];
    const float* W1  = (const float*)d_in[11];
    const float* b1  = (const float*)d_in[12];
    const float* W2  = (const float*)d_in[13];
    const float* b2  = (const float*)d_in[14];
    const float* ln2g = (const float*)d_in[15];
    const float* ln2b = (const float*)d_in[16];
    float* out = (float*)d_out;

    float* scr = nullptr;
    int* idxp = nullptr;
    cudaGetSymbolAddress((void**)&scr, g_scr);
    cudaGetSymbolAddress((void**)&idxp, g_idx);

    float* bQ   = scr + O_Q;   float* bK  = scr + O_K;   float* bV  = scr + O_V;
    float* Kt   = scr + O_KT;  float* Vt  = scr + O_VT;  float* trb = scr + O_TR;
    float* spQ  = scr + O_SPQ; float* spK = scr + O_SPK; float* spV = scr + O_SPV;
    float* spT  = scr + O_SPT;
    float* qsb  = scr + O_QS;  float* vsb = scr + O_VS;
    float* csp  = scr + O_CSP; float* agg = scr + O_AGG; float* ctx = scr + O_CTX;
    float* t1   = scr + O_T1;  float* hb  = scr + O_H;
    float* g1b  = scr + O_G1;  float* fb  = scr + O_F;
    float* basF = scr + O_BF;  float* basI = scr + O_BI;
    float* Sb   = scr + O_S;   float* mv  = scr + O_MV;  float* wts = scr + O_W;

    const int flash_smem = 4 * 64 * 68 * sizeof(float);   // 69632 B
    cudaFuncSetAttribute(flash_k, cudaFuncAttributeMaxDynamicSharedMemorySize, flash_smem);

    const dim3 tb(32, 8);

    // 1. DFT bases
    fill_fwd_k<<<1024, 640>>>(basF);
    fill_inv_k<<<640, 1024>>>(basI);

    // 2. xT (full-matrix transpose 32768x256 -> 256x32768), then QKV
    tr_k<<<dim3(8, 1024, 1), tb>>>(x, trb, BB * LL, DD, 0, 0);
    gemm_t<1><<<dim3(2, 256, 1), 256>>>(trb, Wq, bq, nullptr, bQ, BB * LL, DD, DD, 0, 0);
    gemm_t<1><<<dim3(2, 256, 1), 256>>>(trb, Wk, bk, nullptr, bK, BB * LL, DD, DD, 0, 0);
    gemm_t<1><<<dim3(2, 256, 1), 256>>>(trb, Wv, bv, nullptr, bV, BB * LL, DD, DD, 0, 0);

    // 3. Kt/Vt (per-batch 1024x256 -> 256x1024); needed for flash / timeagg
    tr_k<<<dim3(8, 32, BB), tb>>>(bK, Kt, LL, DD, LL * DD, LL * DD);
    tr_k<<<dim3(8, 32, BB), tb>>>(bV, Vt, LL, DD, LL * DD, LL * DD);

    // 4. forward band DFT, batched: per batch M=256 (d), K=1024 (l), N=640.
    //    AT_b = bQ[b] ([l][d] = k-major) directly.
    gemm_t<0><<<dim3(5, 2, BB), 256>>>(bQ, basF, nullptr, nullptr, spQ,
                                        DD, 640, LL, (size_t)LL * DD, (size_t)DD * 640);
    gemm_t<0><<<dim3(5, 2, BB), 256>>>(bK, basF, nullptr, nullptr, spK,
                                        DD, 640, LL, (size_t)LL * DD, (size_t)DD * 640);
    gemm_t<0><<<dim3(5, 2, BB), 256>>>(bV, basF, nullptr, nullptr, spV,
                                        DD, 640, LL, (size_t)LL * DD, (size_t)DD * 640);

    // 5. corr mean path
    corr_spec_k<<<dim3(NBAND, BB), 256>>>(spQ, spK, Sb);
    meanv_k<<<BB, 256>>>(Sb, mv);
    topk_k<<<1, 1024>>>(mv, idxp);
    weights_k<<<BB, 64>>>(mv, idxp, wts);

    // 6. inverse band DFT (batched, M=256, K=640, N=1024), AT = per-batch
    //    transpose of spQ/spV. ks not needed (C is a symmetric projection).
    tr_k<<<dim3(20, 8, BB), tb>>>(spQ, spT, DD, 640, (size_t)DD * 640, (size_t)DD * 640);
    gemm_t<0><<<dim3(8, 2, BB), 256>>>(spT, basI, nullptr, nullptr, qsb,
                                        DD, LL, 640, (size_t)DD * 640, (size_t)DD * LL);
    tr_k<<<dim3(20, 8, BB), tb>>>(spV, spT, DD, 640, (size_t)DD * 640, (size_t)DD * 640);
    gemm_t<0><<<dim3(8, 2, BB), 256>>>(spT, basI, nullptr, nullptr, vsb,
                                        DD, LL, 640, (size_t)DD * 640, (size_t)DD * LL);

    // 7. spatial attention (flash-fused; K = raw Kt)
    flash_k<<<dim3(16, BB * HH), 256, flash_smem>>>(qsb, Kt, vsb, csp);

    // 8. time aggregation + mix
    timeagg_k<<<BB * DD, 256>>>(Vt, wts, idxp, agg);
    mix_k<<<dim3(32, 8, BB), tb>>>(agg, csp, ctx);

    // 9. output projection + residual + LN1
    tr_k<<<dim3(8, 1024, 1), tb>>>(ctx, trb, BB * LL, DD, 0, 0);
    gemm_t<2><<<dim3(2, 256, 1), 256>>>(trb, Wd, bd, x, t1, BB * LL, DD, DD, 0, 0);
    ln_k<<<BB * LL, 256>>>(t1, ln1g, ln1b, hb);

    // 10. FFN + LN2
    tr_k<<<dim3(8, 1024, 1), tb>>>(hb, trb, BB * LL, DD, 0, 0);
    gemm_t<3><<<dim3(2, 256, 1), 256>>>(trb, W1, b1, nullptr, g1b, BB * LL, DD, DD, 0, 0);
    tr_k<<<dim3(8, 1024, 1), tb>>>(g1b, trb, BB * LL, DD, 0, 0);
    gemm_t<2><<<dim3(2, 256, 1), 256>>>(trb, W2, b2, hb, fb, BB * LL, DD, DD, 0, 0);
    ln_k<<<BB * LL, 256>>>(fb, ln2g, ln2b, out);
}

// round 7
// speedup vs baseline: 1.6768x; 1.3289x over previous
#include <cuda_runtime.h>
#include <math.h>
#include <stdint.h>

// ---------------- problem constants ----------------
#define BB 32
#define LL 1024
#define DD 256
#define HH 4
#define EE 64
#define NBAND 308          // f = 205..512
#define F0 205
#define TOPK 34

// ---------------- scratch layout (floats) ----------------
constexpr size_t SZ   = (size_t)BB * LL * DD;        // 8388608
constexpr size_t SPEC = (size_t)BB * DD * 640;       // 5242880 (8192 x 640)

constexpr size_t O_Q    = 0;
constexpr size_t O_K    = O_Q + SZ;
constexpr size_t O_V    = O_K + SZ;
constexpr size_t O_KT   = O_V + SZ;
constexpr size_t O_VT   = O_KT + SZ;
constexpr size_t O_TR   = O_VT + SZ;       // shared transpose buffer (xT/Qt/ctxT/hbT/g1bT)
constexpr size_t O_SPQ  = O_TR + SZ;
constexpr size_t O_SPK  = O_SPQ + SPEC;
constexpr size_t O_SPV  = O_SPK + SPEC;
constexpr size_t O_QS   = O_SPV + SPEC;
constexpr size_t O_VS   = O_QS + SZ;
constexpr size_t O_CSP  = O_VS + SZ;       // ctx spatial (B,L,D)
constexpr size_t O_AGG  = O_CSP + SZ;      // time agg (B,D,L)
constexpr size_t O_CTX  = O_AGG + SZ;      // mixed context (B,L,D)
constexpr size_t O_T1   = O_CTX + SZ;
constexpr size_t O_H    = O_T1 + SZ;
constexpr size_t O_G1   = O_H + SZ;
constexpr size_t O_F    = O_G1 + SZ;
constexpr size_t O_S    = O_F + SZ;                 // per-batch spectrum sum 32x640
constexpr size_t O_MV   = O_S + (size_t)BB * 640;   // mean_value 32x1024
constexpr size_t O_W    = O_MV + (size_t)BB * LL;   // weights 32x64
constexpr size_t TOTAL  = O_W + (size_t)BB * 64;

__device__ float g_scr[TOTAL + 1024];
__device__ int   g_idx[64];

// ---------------- cp.async helpers ----------------
__device__ __forceinline__ void cpa16(uint32_t saddr, const void* gptr) {
    asm volatile("cp.async.cg.shared.global [%0], [%1], 16;" :: "r"(saddr), "l"(gptr));
}
__device__ __forceinline__ void cpa_commit() {
    asm volatile("cp.async.commit_group;");
}
template<int N>
__device__ __forceinline__ void cpa_wait() {
    asm volatile("cp.async.wait_group %0;" :: "n"(N));
}

// ---------------- fast exp on the FMA pipe (no MUFU) ----------------
__device__ __forceinline__ float fexp(float x) {
    x = fmaxf(x, -87.0f);
    float z = x * 1.4426950408889634f;
    float r = rintf(z);
    float f = z - r;                    // f in [-0.5, 0.5]
    float p = 1.5403530e-4f;
    p = fmaf(p, f, 1.3333558e-3f);
    p = fmaf(p, f, 9.6181291e-3f);
    p = fmaf(p, f, 5.5504109e-2f);
    p = fmaf(p, f, 2.4022651e-1f);
    p = fmaf(p, f, 6.9314718e-1f);
    p = fmaf(p, f, 1.0f);
    int e = (int)r;
    return __int_as_float((e + 127) << 23) * p;
}

// ---------------- 1024-pt radix-2 FFT machinery ----------------
// Forward: rows of `in` (contiguous length-1024 real), write band bins
// 205..512 packed as spec[row*640 + j] = Re, spec[row*640 + 320 + j] = Im.
__global__ void __launch_bounds__(256) fftfwd_k(
    const float* __restrict__ in, float* __restrict__ spec)
{
    __shared__ float2 s[1024];
    __shared__ float2 tw[512];
    const int row = blockIdx.x;
    const float* xr = in + (size_t)row * LL;
    const int t = threadIdx.x;  // 256

    for (int k = t; k < 512; k += 256) {
        float ang = -6.283185307179586f * (float)k / 1024.0f;
        tw[k] = make_float2(cosf(ang), sinf(ang));
    }
    for (int l = t; l < 1024; l += 256) {
        int r = __brev((unsigned)l) >> 22;
        s[r] = make_float2(xr[l], 0.f);
    }
    __syncthreads();
#pragma unroll
    for (int st = 0; st < 10; st++) {
        const int half = 1 << st;
#pragma unroll
        for (int u = 0; u < 2; u++) {
            int j = t + (u << 8);
            int pos = j & (half - 1);
            int base = ((j >> st) << (st + 1)) | pos;
            float2 w = tw[pos << (9 - st)];
            float2 a = s[base], b = s[base + half];
            float2 bw = make_float2(b.x * w.x - b.y * w.y, b.x * w.y + b.y * w.x);
            s[base]        = make_float2(a.x + bw.x, a.y + bw.y);
            s[base + half] = make_float2(a.x - bw.x, a.y - bw.y);
        }
        __syncthreads();
    }
    for (int j = t; j < NBAND; j += 256) {
        float2 v = s[F0 + j];
        spec[(size_t)row * 640 + j]       = v.x;
        spec[(size_t)row * 640 + 320 + j] = v.y;
    }
}

// Inverse: packed band spectrum -> real signal (length 1024, contiguous).
// Full spectrum: X[f] = S[f] for f in [205,512], X[1024-f] = conj(S[f]) for
// f in [205,511], else 0. x[t] = Re( (1/1024) sum X[f] e^{+2 pi i f t/1024} ).
__global__ void __launch_bounds__(256) fftinv_k(
    const float* __restrict__ spec, float* __restrict__ outr)
{
    __shared__ float2 s[1024];
    __shared__ float2 tw[512];
    const int row = blockIdx.x;
    const float* sp = spec + (size_t)row * 640;
    const int t = threadIdx.x;

    for (int k = t; k < 512; k += 256) {
        float ang = 6.283185307179586f * (float)k / 1024.0f;   // +i
        tw[k] = make_float2(cosf(ang), sinf(ang));
    }
    for (int l = t; l < 1024; l += 256) {
        float2 v = make_float2(0.f, 0.f);
        if (l >= F0 && l <= 512) {
            v.x = sp[l - F0];
            v.y = sp[320 + l - F0];
        } else if (l >= 513 && l <= 1024 - F0) {
            int f = 1024 - l;
            v.x = sp[f - F0];
            v.y = -sp[320 + f - F0];
        }
        s[__brev((unsigned)l) >> 22] = v;
    }
    __syncthreads();
#pragma unroll
    for (int st = 0; st < 10; st++) {
        const int half = 1 << st;
#pragma unroll
        for (int u = 0; u < 2; u++) {
            int j = t + (u << 8);
            int pos = j & (half - 1);
            int base = ((j >> st) << (st + 1)) | pos;
            float2 w = tw[pos << (9 - st)];
            float2 a = s[base], b = s[base + half];
            float2 bw = make_float2(b.x * w.x - b.y * w.y, b.x * w.y + b.y * w.x);
            s[base]        = make_float2(a.x + bw.x, a.y + bw.y);
            s[base + half] = make_float2(a.x - bw.x, a.y - bw.y);
        }
        __syncthreads();
    }
    const float sc = 1.0f / 1024.0f;
    for (int l = t; l < 1024; l += 256)
        outr[(size_t)row * LL + l] = s[l].x * sc;
}

// ---------------- cp.async double-buffered GEMM on AT operand --------------
// C_b[M,N] = (AT_b)^T @ Bw  where AT_b is [K][M] (k-major). Batched over z.
// EPI: 0 none, 1 +bias, 2 +bias+res, 3 +bias then gelu(erf)
template<int EPI>
__global__ void __launch_bounds__(256) gemm_t(
    const float* __restrict__ AT, const float* __restrict__ Bw,
    const float* __restrict__ bias, const float* __restrict__ res,
    float* __restrict__ C, int M, int N, int K,
    size_t sAT, size_t sC)
{
    __shared__ float As[2][16][128];
    __shared__ float Bs[2][16][132];
    const int bz = blockIdx.z;
    const float* A = AT + (size_t)bz * sAT;
    float* Cb = C + (size_t)bz * sC;
    const int bn = blockIdx.x * 128;
    const int bm = blockIdx.y * 128;
    const int tid = threadIdx.x;
    const int tr = tid >> 4, tc = tid & 15;

    const int r0 = tid >> 5;          // 0..7
    const int r1 = r0 + 8;            // 8..15
    const int c0 = (tid & 31) * 4;    // 0..124

    const uint32_t asb = (uint32_t)__cvta_generic_to_shared(&As[0][0][0]);
    const uint32_t bsb = (uint32_t)__cvta_generic_to_shared(&Bs[0][0][0]);
    const uint32_t aO0 = (uint32_t)(r0 * 128 + c0) * 4;
    const uint32_t aO1 = (uint32_t)(r1 * 128 + c0) * 4;
    const uint32_t bO0 = (uint32_t)(r0 * 132 + c0) * 4;
    const uint32_t bO1 = (uint32_t)(r1 * 132 + c0) * 4;

    const int T = K >> 4;

    {
        const float* ab = A + bm + c0;
        cpa16(asb + aO0, ab + (size_t)r0 * M);
        cpa16(asb + aO1, ab + (size_t)r1 * M);
        const float* bb = Bw + bn + c0;
        cpa16(bsb + bO0, bb + (size_t)r0 * N);
        cpa16(bsb + bO1, bb + (size_t)r1 * N);
        cpa_commit();
    }

    float acc[8][8];
#pragma unroll
    for (int i = 0; i < 8; i++)
#pragma unroll
        for (int j = 0; j < 8; j++) acc[i][j] = 0.f;

    for (int kt = 0; kt < T; kt++) {
        if (kt + 1 < T) {
            int st = (kt + 1) & 1;
            int k1 = (kt + 1) << 4;
            const float* ab = A + (size_t)k1 * M + bm + c0;
            cpa16(asb + st * 8192 + aO0, ab + (size_t)r0 * M);
            cpa16(asb + st * 8192 + aO1, ab + (size_t)r1 * M);
            const float* bb = Bw + (size_t)k1 * N + bn + c0;
            cpa16(bsb + st * 8448 + bO0, bb + (size_t)r0 * N);
            cpa16(bsb + st * 8448 + bO1, bb + (size_t)r1 * N);
            cpa_commit();
            cpa_wait<1>();
        } else {
            cpa_wait<0>();
        }
        __syncthreads();

        const int st = kt & 1;
#pragma unroll
        for (int kk = 0; kk < 16; kk++) {
            float a[8], b[8];
            *(float4*)(a)     = *(float4*)&As[st][kk][tr * 8];
            *(float4*)(a + 4) = *(float4*)&As[st][kk][tr * 8 + 4];
            *(float4*)(b)     = *(float4*)&Bs[st][kk][tc * 8];
            *(float4*)(b + 4) = *(float4*)&Bs[st][kk][tc * 8 + 4];
#pragma unroll
            for (int i = 0; i < 8; i++)
#pragma unroll
                for (int j = 0; j < 8; j++) acc[i][j] = fmaf(a[i], b[j], acc[i][j]);
        }
        __syncthreads();
    }

#pragma unroll
    for (int i = 0; i < 8; i++) {
        int row = bm + tr * 8 + i;
#pragma unroll
        for (int jj = 0; jj < 2; jj++) {
            int col = bn + tc * 8 + jj * 4;
            float o[4];
#pragma unroll
            for (int q = 0; q < 4; q++) o[q] = acc[i][jj * 4 + q];
            if (EPI >= 1) {
                float4 bbv = *(const float4*)&bias[col];
                o[0] += bbv.x; o[1] += bbv.y; o[2] += bbv.z; o[3] += bbv.w;
            }
            if (EPI == 2) {
                float4 rr = *(const float4*)&res[(size_t)row * N + col];
                o[0] += rr.x; o[1] += rr.y; o[2] += rr.z; o[3] += rr.w;
            }
            if (EPI == 3) {
#pragma unroll
                for (int q = 0; q < 4; q++)
                    o[q] = o[q] * 0.5f * (1.0f + erff(o[q] * 0.70710678118654752f));
            }
            float4 ov; ov.x = o[0]; ov.y = o[1]; ov.z = o[2]; ov.w = o[3];
            *(float4*)&Cb[(size_t)row * N + col] = ov;
        }
    }
}

// ---------------- generic batched transpose: in[R][Cc] -> out[Cc][R] --------
__global__ void tr_k(const float* __restrict__ in, float* __restrict__ out,
                     int R, int Cc, size_t sIn, size_t sOut)
{
    __shared__ float tile[32][33];
    int b = blockIdx.z;
    const float* I = in + (size_t)b * sIn;
    float* O = out + (size_t)b * sOut;
    int c0 = blockIdx.x * 32, r0 = blockIdx.y * 32;
    int x = threadIdx.x, y = threadIdx.y;
#pragma unroll
    for (int i = 0; i < 32; i += 8)
        tile[y + i][x] = I[(size_t)(r0 + y + i) * Cc + c0 + x];
    __syncthreads();
#pragma unroll
    for (int i = 0; i < 32; i += 8)
        O[(size_t)(c0 + y + i) * R + r0 + x] = tile[x][y + i];
}

// ---------------- per-batch spectrum sum S[b,f] = sum_rows Q conj(K) --------
__global__ void corr_spec_k(const float* __restrict__ Qs, const float* __restrict__ Ks,
                            float* __restrict__ S)
{
    int j = blockIdx.x;   // 0..307
    int b = blockIdx.y;   // 0..31
    int t = threadIdx.x;  // 0..255
    size_t row = (size_t)(b * 256 + t) * 640;
    float qr = Qs[row + j], qi = Qs[row + 320 + j];
    float kr = Ks[row + j], ki = Ks[row + 320 + j];
    float re = qr * kr + qi * ki;
    float im = qi * kr - qr * ki;
    __shared__ float sr[256], si[256];
    sr[t] = re; si[t] = im; __syncthreads();
    for (int s = 128; s > 0; s >>= 1) {
        if (t < s) { sr[t] += sr[t + s]; si[t] += si[t + s]; }
        __syncthreads();
    }
    if (t == 0) { S[(size_t)b * 640 + j] = sr[0]; S[(size_t)b * 640 + 320 + j] = si[0]; }
}

// ---------------- mean_value[b,t] = (1/256) irfft(S*mask)[t] ----------------
__global__ void meanv_k(const float* __restrict__ S, float* __restrict__ mv)
{
    int b = blockIdx.x, t = threadIdx.x;  // 256 threads
    __shared__ float sre[NBAND], sim[NBAND], tbl[1024];
    for (int j = t; j < NBAND; j += 256) {
        sre[j] = S[(size_t)b * 640 + j];
        sim[j] = S[(size_t)b * 640 + 320 + j];
    }
    for (int m = t; m < 1024; m += 256)
        tbl[m] = cosf(6.283185307179586f * (float)m / 1024.0f);
    __syncthreads();
    for (int tt = t; tt < 1024; tt += 256) {
        float acc = sre[NBAND - 1] * ((tt & 1) ? -1.f : 1.f);   // f=512 Nyquist
        for (int j = 0; j < NBAND - 1; j++) {
            int f = F0 + j;
            int m = (f * tt) & 1023;
            float c = tbl[m];
            float s = tbl[(m + 768) & 1023];
            acc += 2.f * (sre[j] * c - sim[j] * s);
        }
        mv[(size_t)b * 1024 + tt] = acc * (1.0f / (256.0f * 1024.0f));
    }
}

// ---------------- top-k over batch-mean ----------------
__global__ void topk_k(const float* __restrict__ mv, int* __restrict__ idxout)
{
    int t = threadIdx.x;  // 1024
    __shared__ float vals[1024];
    __shared__ float rv[1024];
    __shared__ int   ri[1024];
    float g = 0.f;
    for (int b = 0; b < BB; b++) g += mv[(size_t)b * 1024 + t];
    vals[t] = g;
    __syncthreads();
    for (int k = 0; k < TOPK; k++) {
        rv[t] = vals[t]; ri[t] = t; __syncthreads();
        for (int s = 512; s > 0; s >>= 1) {
            if (t < s) {
                if (rv[t + s] > rv[t] || (rv[t + s] == rv[t] && ri[t + s] < ri[t])) {
                    rv[t] = rv[t + s]; ri[t] = ri[t + s];
                }
            }
            __syncthreads();
        }
        if (t == 0) { idxout[k] = ri[0]; vals[ri[0]] = -3.4e38f; }
        __syncthreads();
    }
}

// ---------------- per-batch softmax weights ----------------
__global__ void weights_k(const float* __restrict__ mv, const int* __restrict__ idx,
                          float* __restrict__ w)
{
    int b = blockIdx.x, t = threadIdx.x;  // 64 threads
    __shared__ float sv[64];
    float v = (t < TOPK) ? mv[(size_t)b * 1024 + idx[t]] : -3.4e38f;
    sv[t] = v; __syncthreads();
    float mx = -3.4e38f;
    for (int i = 0; i < TOPK; i++) mx = fmaxf(mx, sv[i]);
    __syncthreads();
    float e = (t < TOPK) ? expf(v - mx) : 0.f;
    sv[t] = e; __syncthreads();
    float sm = 0.f;
    for (int i = 0; i < TOPK; i++) sm += sv[i];
    if (t < TOPK) w[(size_t)b * 64 + t] = e / sm;
}

// ---------------- flash attention (fp32 SIMT, poly exp) ----------------
// qs/ks/vs in (B,D,L): row = b*256 + h*64 + e, col = l/s.  out in (B,L,D).
// K = raw Kt: valid since the band filter C is a symmetric projection.
__global__ void __launch_bounds__(256) flash_k(
    const float* __restrict__ qs, const float* __restrict__ ks,
    const float* __restrict__ vs, float* __restrict__ out)
{
    extern __shared__ float sm[];
    float* Qs = sm;
    float* Ks = sm + 64 * 68;
    float* Vs = sm + 2 * 64 * 68;
    float* Ps = sm + 3 * 64 * 68;
    const int bh = blockIdx.y, b = bh >> 2, h = bh & 3;
    const int l0 = blockIdx.x * 64;
    const float* Q  = qs + ((size_t)b * DD + h * EE) * LL;
    const float* Kp = ks + ((size_t)b * DD + h * EE) * LL;
    const float* V  = vs + ((size_t)b * DD + h * EE) * LL;
    const int tid = threadIdx.x;
    const int tr = tid >> 4, tc = tid & 15;
    const int le = tid >> 2;
    const int lq = tid & 3;

#pragma unroll
    for (int w = 0; w < 4; w++) {
        int col = w * 16 + lq * 4;
        *(float4*)&Qs[le * 68 + col] = *(const float4*)&Q[(size_t)le * LL + l0 + col];
    }

    float m_i[4], l_i[4], o[4][4];
#pragma unroll
    for (int i = 0; i < 4; i++) {
        m_i[i] = -1e30f; l_i[i] = 0.f;
#pragma unroll
        for (int j = 0; j < 4; j++) o[i][j] = 0.f;
    }

    for (int s0 = 0; s0 < LL; s0 += 64) {
        __syncthreads();
#pragma unroll
        for (int w = 0; w < 4; w++) {
            int col = w * 16 + lq * 4;
            *(float4*)&Ks[le * 68 + col] = *(const float4*)&Kp[(size_t)le * LL + s0 + col];
            float4 vv = *(const float4*)&V[(size_t)le * LL + s0 + col];
            Vs[(col + 0) * 68 + le] = vv.x;
            Vs[(col + 1) * 68 + le] = vv.y;
            Vs[(col + 2) * 68 + le] = vv.z;
            Vs[(col + 3) * 68 + le] = vv.w;
        }
        __syncthreads();

        float s_[4][4];
#pragma unroll
        for (int i = 0; i < 4; i++)
#pragma unroll
            for (int j = 0; j < 4; j++) s_[i][j] = 0.f;
        for (int e4 = 0; e4 < 16; e4++) {
            float qa[4][4], kb[4][4];
#pragma unroll
            for (int c = 0; c < 4; c++) {
                float4 t1 = *(float4*)&Qs[(e4 * 4 + c) * 68 + tr * 4];
                qa[c][0] = t1.x; qa[c][1] = t1.y; qa[c][2] = t1.z; qa[c][3] = t1.w;
                float4 t2 = *(float4*)&Ks[(e4 * 4 + c) * 68 + tc * 4];
                kb[c][0] = t2.x; kb[c][1] = t2.y; kb[c][2] = t2.z; kb[c][3] = t2.w;
            }
#pragma unroll
            for (int c = 0; c < 4; c++)
#pragma unroll
                for (int i = 0; i < 4; i++)
#pragma unroll
                    for (int j = 0; j < 4; j++)
                        s_[i][j] = fmaf(qa[c][i], kb[c][j], s_[i][j]);
        }

#pragma unroll
        for (int i = 0; i < 4; i++) {
            float mx = -1e30f;
#pragma unroll
            for (int j = 0; j < 4; j++) {
                s_[i][j] *= 0.125f;
                mx = fmaxf(mx, s_[i][j]);
            }
#pragma unroll
            for (int off = 8; off > 0; off >>= 1)
                mx = fmaxf(mx, __shfl_xor_sync(0xffffffffu, mx, off));
            float mn = fmaxf(m_i[i], mx);
            float alpha = fexp(m_i[i] - mn);
            float p0 = fexp(s_[i][0] - mn);
            float p1 = fexp(s_[i][1] - mn);
            float p2 = fexp(s_[i][2] - mn);
            float p3 = fexp(s_[i][3] - mn);
            float ps = p0 + p1 + p2 + p3;
#pragma unroll
            for (int off = 8; off > 0; off >>= 1)
                ps += __shfl_xor_sync(0xffffffffu, ps, off);
            l_i[i] = l_i[i] * alpha + ps;
            m_i[i] = mn;
#pragma unroll
            for (int j = 0; j < 4; j++) o[i][j] *= alpha;
            float4 pv; pv.x = p0; pv.y = p1; pv.z = p2; pv.w = p3;
            *(float4*)&Ps[(tr * 4 + i) * 68 + tc * 4] = pv;
        }
        __syncthreads();

        for (int s4 = 0; s4 < 16; s4++) {
            float av[4][4], bv[4][4];
#pragma unroll
            for (int i = 0; i < 4; i++) {
                float4 t1 = *(float4*)&Ps[(tr * 4 + i) * 68 + s4 * 4];
                av[i][0] = t1.x; av[i][1] = t1.y; av[i][2] = t1.z; av[i][3] = t1.w;
            }
#pragma unroll
            for (int c = 0; c < 4; c++) {
                float4 t2 = *(float4*)&Vs[(s4 * 4 + c) * 68 + tc * 4];
                bv[c][0] = t2.x; bv[c][1] = t2.y; bv[c][2] = t2.z; bv[c][3] = t2.w;
            }
#pragma unroll
            for (int c = 0; c < 4; c++)
#pragma unroll
                for (int i = 0; i < 4; i++)
#pragma unroll
                    for (int j = 0; j < 4; j++)
                        o[i][j] = fmaf(av[i][c], bv[c][j], o[i][j]);
        }
    }

#pragma unroll
    for (int i = 0; i < 4; i++) {
        float inv = 1.0f / l_i[i];
        float4 ov;
        ov.x = o[i][0] * inv; ov.y = o[i][1] * inv;
        ov.z = o[i][2] * inv; ov.w = o[i][3] * inv;
        size_t off = ((size_t)b * LL + l0 + tr * 4 + i) * DD + h * EE + tc * 4;
        *(float4*)&out[off] = ov;
    }
}

// ---------------- time delay aggregation (B,D,L) ----------------
__global__ void timeagg_k(const float* __restrict__ Vt, const float* __restrict__ w,
                          const int* __restrict__ idx, float* __restrict__ agg)
{
    int bd = blockIdx.x;        // b*256+d
    int b = bd >> 8;
    __shared__ float row[1024];
    __shared__ float ws[TOPK];
    __shared__ int   is[TOPK];
    int t = threadIdx.x;        // 256
    for (int l = t; l < 1024; l += 256) row[l] = Vt[(size_t)bd * 1024 + l];
    if (t < TOPK) { ws[t] = w[(size_t)b * 64 + t]; is[t] = idx[t]; }
    __syncthreads();
    for (int l = t; l < 1024; l += 256) {
        float a = 0.f;
#pragma unroll
        for (int k = 0; k < TOPK; k++) a = fmaf(ws[k], row[(l + is[k]) & 1023], a);
        agg[(size_t)bd * 1024 + l] = a;
    }
}

// ---------------- context = 0.9*agg^T + 0.1*ctx_sp ----------------
__global__ void mix_k(const float* __restrict__ agg, const float* __restrict__ csp,
                      float* __restrict__ ctx)
{
    __shared__ float tile[32][33];
    int b = blockIdx.z;
    int l0 = blockIdx.x * 32, d0 = blockIdx.y * 32;
    int x = threadIdx.x, y = threadIdx.y;
#pragma unroll
    for (int i = 0; i < 32; i += 8)
        tile[y + i][x] = agg[((size_t)b * DD + d0 + y + i) * LL + l0 + x];
    __syncthreads();
#pragma unroll
    for (int i = 0; i < 32; i += 8) {
        size_t o = ((size_t)b * LL + l0 + y + i) * DD + d0 + x;
        ctx[o] = 0.9f * tile[x][y + i] + 0.1f * csp[o];
    }
}

// ---------------- LayerNorm over D=256 ----------------
__global__ void ln_k(const float* __restrict__ in, const float* __restrict__ g,
                     const float* __restrict__ b, float* __restrict__ out)
{
    size_t row = blockIdx.x;
    int t = threadIdx.x;   // 256
    float v = in[row * DD + t];
    __shared__ float red[256];
    red[t] = v; __syncthreads();
    for (int s = 128; s > 0; s >>= 1) { if (t < s) red[t] += red[t + s]; __syncthreads(); }
    float m = red[0] * (1.0f / 256.0f);
    __syncthreads();
    float d = v - m;
    red[t] = d * d; __syncthreads();
    for (int s = 128; s > 0; s >>= 1) { if (t < s) red[t] += red[t + s]; __syncthreads(); }
    float var = red[0] * (1.0f / 256.0f);
    out[row * DD + t] = d * rsqrtf(var + 1e-8f) * g[t] + b[t];
}

// ---------------- launch ----------------
extern "C" void kernel_launch(void* const* d_in, const int* in_sizes, int n_in,
                              void* d_out, int out_size)
{
    const float* x   = (const float*)d_in[0];
    const float* Wq  = (const float*)d_in[1];
    const float* bq  = (const float*)d_in[2];
    const float* Wk  = (const float*)d_in[3];
    const float* bk  = (const float*)d_in[4];
    const float* Wv  = (const float*)d_in[5];
    const float* bv  = (const float*)d_in[6];
    const float* Wd  = (const float*)d_in[7];
    const float* bd  = (const float*)d_in[8];
    const float* ln1g = (const float*)d_in[9];
    const float* ln1b = (const float*)d_in[10];
    const float* W1  = (const float*)d_in[11];
    const float* b1  = (const float*)d_in[12];
    const float* W2  = (const float*)d_in[13];
    const float* b2  = (const float*)d_in[14];
    const float* ln2g = (const float*)d_in[15];
    const float* ln2b = (const float*)d_in[16];
    float* out = (float*)d_out;

    float* scr = nullptr;
    int* idxp = nullptr;
    cudaGetSymbolAddress((void**)&scr, g_scr);
    cudaGetSymbolAddress((void**)&idxp, g_idx);

    float* bQ   = scr + O_Q;   float* bK  = scr + O_K;   float* bV  = scr + O_V;
    float* Kt   = scr + O_KT;  float* Vt  = scr + O_VT;  float* trb = scr + O_TR;
    float* spQ  = scr + O_SPQ; float* spK = scr + O_SPK; float* spV = scr + O_SPV;
    float* qsb  = scr + O_QS;  float* vsb = scr + O_VS;
    float* csp  = scr + O_CSP; float* agg = scr + O_AGG; float* ctx = scr + O_CTX;
    float* t1   = scr + O_T1;  float* hb  = scr + O_H;
    float* g1b  = scr + O_G1;  float* fb  = scr + O_F;
    float* Sb   = scr + O_S;   float* mv  = scr + O_MV;  float* wts = scr + O_W;

    const int flash_smem = 4 * 64 * 68 * sizeof(float);   // 69632 B
    cudaFuncSetAttribute(flash_k, cudaFuncAttributeMaxDynamicSharedMemorySize, flash_smem);

    const dim3 tb(32, 8);

    // 1. xT, then QKV projections
    tr_k<<<dim3(8, 1024, 1), tb>>>(x, trb, BB * LL, DD, 0, 0);
    gemm_t<1><<<dim3(2, 256, 1), 256>>>(trb, Wq, bq, nullptr, bQ, BB * LL, DD, DD, 0, 0);
    gemm_t<1><<<dim3(2, 256, 1), 256>>>(trb, Wk, bk, nullptr, bK, BB * LL, DD, DD, 0, 0);
    gemm_t<1><<<dim3(2, 256, 1), 256>>>(trb, Wv, bv, nullptr, bV, BB * LL, DD, DD, 0, 0);

    // 2. transposes to (B,D,L): Kt/Vt persist; Qt reuses trb (xT now dead)
    tr_k<<<dim3(8, 32, BB), tb>>>(bK, Kt, LL, DD, LL * DD, LL * DD);
    tr_k<<<dim3(8, 32, BB), tb>>>(bV, Vt, LL, DD, LL * DD, LL * DD);
    tr_k<<<dim3(8, 32, BB), tb>>>(bQ, trb, LL, DD, LL * DD, LL * DD);

    // 3. forward band FFT (replaces DFT GEMMs)
    fftfwd_k<<<BB * DD, 256>>>(trb, spQ);
    fftfwd_k<<<BB * DD, 256>>>(Kt, spK);
    fftfwd_k<<<BB * DD, 256>>>(Vt, spV);

    // 4. corr mean path
    corr_spec_k<<<dim3(NBAND, BB), 256>>>(spQ, spK, Sb);
    meanv_k<<<BB, 256>>>(Sb, mv);
    topk_k<<<1, 1024>>>(mv, idxp);
    weights_k<<<BB, 64>>>(mv, idxp, wts);

    // 5. inverse band FFT -> qs, vs (ks not needed: C is a symmetric projection)
    fftinv_k<<<BB * DD, 256>>>(spQ, qsb);
    fftinv_k<<<BB * DD, 256>>>(spV, vsb);

    // 6. spatial attention (flash-fused; K = raw Kt)
    flash_k<<<dim3(16, BB * HH), 256, flash_smem>>>(qsb, Kt, vsb, csp);

    // 7. time aggregation + mix
    timeagg_k<<<BB * DD, 256>>>(Vt, wts, idxp, agg);
    mix_k<<<dim3(32, 8, BB), tb>>>(agg, csp, ctx);

    // 8. output projection + residual + LN1
    tr_k<<<dim3(8, 1024, 1), tb>>>(ctx, trb, BB * LL, DD, 0, 0);
    gemm_t<2><<<dim3(2, 256, 1), 256>>>(trb, Wd, bd, x, t1, BB * LL, DD, DD, 0, 0);
    ln_k<<<BB * LL, 256>>>(t1, ln1g, ln1b, hb);

    // 9. FFN + LN2
    tr_k<<<dim3(8, 1024, 1), tb>>>(hb, trb, BB * LL, DD, 0, 0);
    gemm_t<3><<<dim3(2, 256, 1), 256>>>(trb, W1, b1, nullptr, g1b, BB * LL, DD, DD, 0, 0);
    tr_k<<<dim3(8, 1024, 1), tb>>>(g1b, trb, BB * LL, DD, 0, 0);
    gemm_t<2><<<dim3(2, 256, 1), 256>>>(trb, W2, b2, hb, fb, BB * LL, DD, DD, 0, 0);
    ln_k<<<BB * LL, 256>>>(fb, ln2g, ln2b, out);
}

// round 8
// speedup vs baseline: 2.0219x; 1.2058x over previous
#include <cuda_runtime.h>
#include <math.h>
#include <stdint.h>

// ---------------- problem constants ----------------
#define BB 32
#define LL 1024
#define DD 256
#define HH 4
#define EE 64
#define NBAND 308          // f = 205..512
#define F0 205
#define TOPK 34

// ---------------- scratch layout (floats) ----------------
constexpr size_t SZ   = (size_t)BB * LL * DD;        // 8388608
constexpr size_t SPEC = (size_t)BB * DD * 640;       // 5242880 (8192 x 640)

constexpr size_t O_Q    = 0;
constexpr size_t O_K    = O_Q + SZ;
constexpr size_t O_V    = O_K + SZ;
constexpr size_t O_KT   = O_V + SZ;
constexpr size_t O_VT   = O_KT + SZ;
constexpr size_t O_TR   = O_VT + SZ;       // shared transpose buffer (xT / Qt)
constexpr size_t O_SPQ  = O_TR + SZ;
constexpr size_t O_SPK  = O_SPQ + SPEC;
constexpr size_t O_SPV  = O_SPK + SPEC;
constexpr size_t O_QS   = O_SPV + SPEC;
constexpr size_t O_VS   = O_QS + SZ;
constexpr size_t O_CSP  = O_VS + SZ;       // ctx spatial (B,L,D)
constexpr size_t O_AGG  = O_CSP + SZ;      // time agg (B,D,L)
constexpr size_t O_CTX  = O_AGG + SZ;      // mixed context (B,L,D)
constexpr size_t O_T1   = O_CTX + SZ;
constexpr size_t O_H    = O_T1 + SZ;
constexpr size_t O_G1   = O_H + SZ;
constexpr size_t O_F    = O_G1 + SZ;
constexpr size_t O_S    = O_F + SZ;                 // per-batch spectrum sum 32x640
constexpr size_t O_MV   = O_S + (size_t)BB * 640;   // mean_value 32x1024
constexpr size_t O_W    = O_MV + (size_t)BB * LL;   // weights 32x64
constexpr size_t TOTAL  = O_W + (size_t)BB * 64;

__device__ float g_scr[TOTAL + 1024];
__device__ int   g_idx[64];

// ---------------- cp.async helpers ----------------
__device__ __forceinline__ void cpa16(uint32_t saddr, const void* gptr) {
    asm volatile("cp.async.cg.shared.global [%0], [%1], 16;" :: "r"(saddr), "l"(gptr));
}
__device__ __forceinline__ void cpa_commit() {
    asm volatile("cp.async.commit_group;");
}
template<int N>
__device__ __forceinline__ void cpa_wait() {
    asm volatile("cp.async.wait_group %0;" :: "n"(N));
}

// ---------------- tf32 mma helpers ----------------
__device__ __forceinline__ uint32_t f2tf(float f) {
    uint32_t u;
    asm("cvt.rna.tf32.f32 %0, %1;" : "=r"(u) : "f"(f));
    return u;
}
__device__ __forceinline__ void mma_tf32(float* d, const uint32_t* a, const uint32_t* b) {
    asm volatile(
        "mma.sync.aligned.m16n8k8.row.col.f32.tf32.tf32.f32 "
        "{%0,%1,%2,%3}, {%4,%5,%6,%7}, {%8,%9}, {%0,%1,%2,%3};"
        : "+f"(d[0]), "+f"(d[1]), "+f"(d[2]), "+f"(d[3])
        : "r"(a[0]), "r"(a[1]), "r"(a[2]), "r"(a[3]), "r"(b[0]), "r"(b[1]));
}

// ---------------- fast exp on the FMA pipe (no MUFU) ----------------
__device__ __forceinline__ float fexp(float x) {
    x = fmaxf(x, -87.0f);
    float z = x * 1.4426950408889634f;
    float r = rintf(z);
    float f = z - r;
    float p = 1.5403530e-4f;
    p = fmaf(p, f, 1.3333558e-3f);
    p = fmaf(p, f, 9.6181291e-3f);
    p = fmaf(p, f, 5.5504109e-2f);
    p = fmaf(p, f, 2.4022651e-1f);
    p = fmaf(p, f, 6.9314718e-1f);
    p = fmaf(p, f, 1.0f);
    int e = (int)r;
    return __int_as_float((e + 127) << 23) * p;
}

// ---------------- 1024-pt radix-2 FFT machinery ----------------
__global__ void __launch_bounds__(256) fftfwd_k(
    const float* __restrict__ in, float* __restrict__ spec)
{
    __shared__ float2 s[1024];
    __shared__ float2 tw[512];
    const int row = blockIdx.x;
    const float* xr = in + (size_t)row * LL;
    const int t = threadIdx.x;

    for (int k = t; k < 512; k += 256) {
        float ang = -6.283185307179586f * (float)k / 1024.0f;
        tw[k] = make_float2(cosf(ang), sinf(ang));
    }
    for (int l = t; l < 1024; l += 256) {
        int r = __brev((unsigned)l) >> 22;
        s[r] = make_float2(xr[l], 0.f);
    }
    __syncthreads();
#pragma unroll
    for (int st = 0; st < 10; st++) {
        const int half = 1 << st;
#pragma unroll
        for (int u = 0; u < 2; u++) {
            int j = t + (u << 8);
            int pos = j & (half - 1);
            int base = ((j >> st) << (st + 1)) | pos;
            float2 w = tw[pos << (9 - st)];
            float2 a = s[base], b = s[base + half];
            float2 bw = make_float2(b.x * w.x - b.y * w.y, b.x * w.y + b.y * w.x);
            s[base]        = make_float2(a.x + bw.x, a.y + bw.y);
            s[base + half] = make_float2(a.x - bw.x, a.y - bw.y);
        }
        __syncthreads();
    }
    for (int j = t; j < NBAND; j += 256) {
        float2 v = s[F0 + j];
        spec[(size_t)row * 640 + j]       = v.x;
        spec[(size_t)row * 640 + 320 + j] = v.y;
    }
}

__global__ void __launch_bounds__(256) fftinv_k(
    const float* __restrict__ spec, float* __restrict__ outr)
{
    __shared__ float2 s[1024];
    __shared__ float2 tw[512];
    const int row = blockIdx.x;
    const float* sp = spec + (size_t)row * 640;
    const int t = threadIdx.x;

    for (int k = t; k < 512; k += 256) {
        float ang = 6.283185307179586f * (float)k / 1024.0f;
        tw[k] = make_float2(cosf(ang), sinf(ang));
    }
    for (int l = t; l < 1024; l += 256) {
        float2 v = make_float2(0.f, 0.f);
        if (l >= F0 && l <= 512) {
            v.x = sp[l - F0];
            v.y = sp[320 + l - F0];
        } else if (l >= 513 && l <= 1024 - F0) {
            int f = 1024 - l;
            v.x = sp[f - F0];
            v.y = -sp[320 + f - F0];
        }
        s[__brev((unsigned)l) >> 22] = v;
    }
    __syncthreads();
#pragma unroll
    for (int st = 0; st < 10; st++) {
        const int half = 1 << st;
#pragma unroll
        for (int u = 0; u < 2; u++) {
            int j = t + (u << 8);
            int pos = j & (half - 1);
            int base = ((j >> st) << (st + 1)) | pos;
            float2 w = tw[pos << (9 - st)];
            float2 a = s[base], b = s[base + half];
            float2 bw = make_float2(b.x * w.x - b.y * w.y, b.x * w.y + b.y * w.x);
            s[base]        = make_float2(a.x + bw.x, a.y + bw.y);
            s[base + half] = make_float2(a.x - bw.x, a.y - bw.y);
        }
        __syncthreads();
    }
    const float sc = 1.0f / 1024.0f;
    for (int l = t; l < 1024; l += 256)
        outr[(size_t)row * LL + l] = s[l].x * sc;
}

// ---------------- fp32 cp.async GEMM on AT operand (QKV only) --------------
template<int EPI>
__global__ void __launch_bounds__(256) gemm_t(
    const float* __restrict__ AT, const float* __restrict__ Bw,
    const float* __restrict__ bias, const float* __restrict__ res,
    float* __restrict__ C, int M, int N, int K,
    size_t sAT, size_t sC)
{
    __shared__ float As[2][16][128];
    __shared__ float Bs[2][16][132];
    const int bz = blockIdx.z;
    const float* A = AT + (size_t)bz * sAT;
    float* Cb = C + (size_t)bz * sC;
    const int bn = blockIdx.x * 128;
    const int bm = blockIdx.y * 128;
    const int tid = threadIdx.x;
    const int tr = tid >> 4, tc = tid & 15;

    const int r0 = tid >> 5;
    const int r1 = r0 + 8;
    const int c0 = (tid & 31) * 4;

    const uint32_t asb = (uint32_t)__cvta_generic_to_shared(&As[0][0][0]);
    const uint32_t bsb = (uint32_t)__cvta_generic_to_shared(&Bs[0][0][0]);
    const uint32_t aO0 = (uint32_t)(r0 * 128 + c0) * 4;
    const uint32_t aO1 = (uint32_t)(r1 * 128 + c0) * 4;
    const uint32_t bO0 = (uint32_t)(r0 * 132 + c0) * 4;
    const uint32_t bO1 = (uint32_t)(r1 * 132 + c0) * 4;

    const int T = K >> 4;

    {
        const float* ab = A + bm + c0;
        cpa16(asb + aO0, ab + (size_t)r0 * M);
        cpa16(asb + aO1, ab + (size_t)r1 * M);
        const float* bb = Bw + bn + c0;
        cpa16(bsb + bO0, bb + (size_t)r0 * N);
        cpa16(bsb + bO1, bb + (size_t)r1 * N);
        cpa_commit();
    }

    float acc[8][8];
#pragma unroll
    for (int i = 0; i < 8; i++)
#pragma unroll
        for (int j = 0; j < 8; j++) acc[i][j] = 0.f;

    for (int kt = 0; kt < T; kt++) {
        if (kt + 1 < T) {
            int st = (kt + 1) & 1;
            int k1 = (kt + 1) << 4;
            const float* ab = A + (size_t)k1 * M + bm + c0;
            cpa16(asb + st * 8192 + aO0, ab + (size_t)r0 * M);
            cpa16(asb + st * 8192 + aO1, ab + (size_t)r1 * M);
            const float* bb = Bw + (size_t)k1 * N + bn + c0;
            cpa16(bsb + st * 8448 + bO0, bb + (size_t)r0 * N);
            cpa16(bsb + st * 8448 + bO1, bb + (size_t)r1 * N);
            cpa_commit();
            cpa_wait<1>();
        } else {
            cpa_wait<0>();
        }
        __syncthreads();

        const int st = kt & 1;
#pragma unroll
        for (int kk = 0; kk < 16; kk++) {
            float a[8], b[8];
            *(float4*)(a)     = *(float4*)&As[st][kk][tr * 8];
            *(float4*)(a + 4) = *(float4*)&As[st][kk][tr * 8 + 4];
            *(float4*)(b)     = *(float4*)&Bs[st][kk][tc * 8];
            *(float4*)(b + 4) = *(float4*)&Bs[st][kk][tc * 8 + 4];
#pragma unroll
            for (int i = 0; i < 8; i++)
#pragma unroll
                for (int j = 0; j < 8; j++) acc[i][j] = fmaf(a[i], b[j], acc[i][j]);
        }
        __syncthreads();
    }

#pragma unroll
    for (int i = 0; i < 8; i++) {
        int row = bm + tr * 8 + i;
#pragma unroll
        for (int jj = 0; jj < 2; jj++) {
            int col = bn + tc * 8 + jj * 4;
            float o[4];
#pragma unroll
            for (int q = 0; q < 4; q++) o[q] = acc[i][jj * 4 + q];
            if (EPI >= 1) {
                float4 bbv = *(const float4*)&bias[col];
                o[0] += bbv.x; o[1] += bbv.y; o[2] += bbv.z; o[3] += bbv.w;
            }
            float4 ov; ov.x = o[0]; ov.y = o[1]; ov.z = o[2]; ov.w = o[3];
            *(float4*)&Cb[(size_t)row * N + col] = ov;
        }
    }
}

// ---------------- tf32 tensor-core GEMM, row-major A --------------
// C[M,N] = A[M,K] @ Bw[K,N] (+epilogue). 256 thr, 8 warps.
// warp tile 32(m) x 64(n): 2 m-atoms (m16) x 8 n-atoms (n8), k8 steps.
// EPI: 2 +bias+res, 3 +bias then gelu(erf)
template<int EPI>
__global__ void __launch_bounds__(256) gemm_tc(
    const float* __restrict__ A, const float* __restrict__ Bw,
    const float* __restrict__ bias, const float* __restrict__ res,
    float* __restrict__ C, int M, int N, int K)
{
    __shared__ float As[2][128][20];   // [m][k] pad 20: (20m+k)%32 all distinct
    __shared__ float Bs[2][16][136];   // [k][n] pad 136: (8k+n)%32 all distinct
    const int bn = blockIdx.x * 128;
    const int bm = blockIdx.y * 128;
    const int tid = threadIdx.x, wid = tid >> 5, lane = tid & 31;
    const int grp = lane >> 2, tig = lane & 3;
    const int wm = (wid & 3) * 32, wn = (wid >> 2) * 64;

    const uint32_t asb = (uint32_t)__cvta_generic_to_shared(&As[0][0][0]);
    const uint32_t bsb = (uint32_t)__cvta_generic_to_shared(&Bs[0][0][0]);
    // A: 512 chunks of 16B; per thread 2
    const int ar0 = tid >> 1;                // chunk c = tid: row c>>2? use c = tid*2+u style
    (void)ar0;
    const int T = K >> 4;

    // chunk mapping: c in [0,512): row = c>>2, kq = (c&3)*4
    auto loadA = [&](int st, int k0) {
#pragma unroll
        for (int u = 0; u < 2; u++) {
            int c = tid + u * 256;
            int row = c >> 2, kq = (c & 3) * 4;
            cpa16(asb + (uint32_t)(st * 128 * 20 + row * 20 + kq) * 4,
                  &A[(size_t)(bm + row) * K + k0 + kq]);
        }
    };
    auto loadB = [&](int st, int k0) {
#pragma unroll
        for (int u = 0; u < 2; u++) {
            int c = tid + u * 256;
            int r = c >> 5, col = (c & 31) * 4;
            cpa16(bsb + (uint32_t)(st * 16 * 136 + r * 136 + col) * 4,
                  &Bw[(size_t)(k0 + r) * N + bn + col]);
        }
    };

    loadA(0, 0); loadB(0, 0); cpa_commit();

    float d[2][8][4];
#pragma unroll
    for (int am = 0; am < 2; am++)
#pragma unroll
        for (int an = 0; an < 8; an++)
#pragma unroll
            for (int q = 0; q < 4; q++) d[am][an][q] = 0.f;

    for (int kt = 0; kt < T; kt++) {
        if (kt + 1 < T) {
            loadA((kt + 1) & 1, (kt + 1) << 4);
            loadB((kt + 1) & 1, (kt + 1) << 4);
            cpa_commit();
            cpa_wait<1>();
        } else {
            cpa_wait<0>();
        }
        __syncthreads();
        const int st = kt & 1;
#pragma unroll
        for (int k8 = 0; k8 < 16; k8 += 8) {
            uint32_t a[2][4];
#pragma unroll
            for (int am = 0; am < 2; am++) {
                int mr = wm + am * 16;
                a[am][0] = f2tf(As[st][mr + grp][k8 + tig]);
                a[am][1] = f2tf(As[st][mr + grp + 8][k8 + tig]);
                a[am][2] = f2tf(As[st][mr + grp][k8 + tig + 4]);
                a[am][3] = f2tf(As[st][mr + grp + 8][k8 + tig + 4]);
            }
#pragma unroll
            for (int an = 0; an < 8; an++) {
                uint32_t b[2];
                b[0] = f2tf(Bs[st][k8 + tig][wn + an * 8 + grp]);
                b[1] = f2tf(Bs[st][k8 + tig + 4][wn + an * 8 + grp]);
                mma_tf32(d[0][an], a[0], b);
                mma_tf32(d[1][an], a[1], b);
            }
        }
        __syncthreads();
    }

    // epilogue: c0,c1 at (row, col..col+1), c2,c3 at (row+8, col..col+1)
#pragma unroll
    for (int am = 0; am < 2; am++) {
        int row0 = bm + wm + am * 16 + grp;
#pragma unroll
        for (int an = 0; an < 8; an++) {
            int col = bn + wn + an * 8 + 2 * tig;
            float o0 = d[am][an][0], o1 = d[am][an][1];
            float o2 = d[am][an][2], o3 = d[am][an][3];
            float2 bv = *(const float2*)&bias[col];
            o0 += bv.x; o1 += bv.y; o2 += bv.x; o3 += bv.y;
            if (EPI == 2) {
                float2 r0v = *(const float2*)&res[(size_t)row0 * N + col];
                float2 r1v = *(const float2*)&res[(size_t)(row0 + 8) * N + col];
                o0 += r0v.x; o1 += r0v.y; o2 += r1v.x; o3 += r1v.y;
            }
            if (EPI == 3) {
                o0 = o0 * 0.5f * (1.0f + erff(o0 * 0.70710678118654752f));
                o1 = o1 * 0.5f * (1.0f + erff(o1 * 0.70710678118654752f));
                o2 = o2 * 0.5f * (1.0f + erff(o2 * 0.70710678118654752f));
                o3 = o3 * 0.5f * (1.0f + erff(o3 * 0.70710678118654752f));
            }
            float2 w0; w0.x = o0; w0.y = o1;
            float2 w1; w1.x = o2; w1.y = o3;
            *(float2*)&C[(size_t)row0 * N + col] = w0;
            *(float2*)&C[(size_t)(row0 + 8) * N + col] = w1;
        }
    }
}

// ---------------- generic batched transpose: in[R][Cc] -> out[Cc][R] --------
__global__ void tr_k(const float* __restrict__ in, float* __restrict__ out,
                     int R, int Cc, size_t sIn, size_t sOut)
{
    __shared__ float tile[32][33];
    int b = blockIdx.z;
    const float* I = in + (size_t)b * sIn;
    float* O = out + (size_t)b * sOut;
    int c0 = blockIdx.x * 32, r0 = blockIdx.y * 32;
    int x = threadIdx.x, y = threadIdx.y;
#pragma unroll
    for (int i = 0; i < 32; i += 8)
        tile[y + i][x] = I[(size_t)(r0 + y + i) * Cc + c0 + x];
    __syncthreads();
#pragma unroll
    for (int i = 0; i < 32; i += 8)
        O[(size_t)(c0 + y + i) * R + r0 + x] = tile[x][y + i];
}

// ---------------- per-batch spectrum sum S[b,f] = sum_rows Q conj(K) --------
__global__ void corr_spec_k(const float* __restrict__ Qs, const float* __restrict__ Ks,
                            float* __restrict__ S)
{
    int j = blockIdx.x;
    int b = blockIdx.y;
    int t = threadIdx.x;
    size_t row = (size_t)(b * 256 + t) * 640;
    float qr = Qs[row + j], qi = Qs[row + 320 + j];
    float kr = Ks[row + j], ki = Ks[row + 320 + j];
    float re = qr * kr + qi * ki;
    float im = qi * kr - qr * ki;
    __shared__ float sr[256], si[256];
    sr[t] = re; si[t] = im; __syncthreads();
    for (int s = 128; s > 0; s >>= 1) {
        if (t < s) { sr[t] += sr[t + s]; si[t] += si[t + s]; }
        __syncthreads();
    }
    if (t == 0) { S[(size_t)b * 640 + j] = sr[0]; S[(size_t)b * 640 + 320 + j] = si[0]; }
}

// ---------------- mean_value[b,t] = (1/256) irfft(S*mask)[t] ----------------
__global__ void meanv_k(const float* __restrict__ S, float* __restrict__ mv)
{
    int b = blockIdx.x, t = threadIdx.x;
    __shared__ float sre[NBAND], sim[NBAND], tbl[1024];
    for (int j = t; j < NBAND; j += 256) {
        sre[j] = S[(size_t)b * 640 + j];
        sim[j] = S[(size_t)b * 640 + 320 + j];
    }
    for (int m = t; m < 1024; m += 256)
        tbl[m] = cosf(6.283185307179586f * (float)m / 1024.0f);
    __syncthreads();
    for (int tt = t; tt < 1024; tt += 256) {
        float acc = sre[NBAND - 1] * ((tt & 1) ? -1.f : 1.f);
        for (int j = 0; j < NBAND - 1; j++) {
            int f = F0 + j;
            int m = (f * tt) & 1023;
            float c = tbl[m];
            float s = tbl[(m + 768) & 1023];
            acc += 2.f * (sre[j] * c - sim[j] * s);
        }
        mv[(size_t)b * 1024 + tt] = acc * (1.0f / (256.0f * 1024.0f));
    }
}

// ---------------- top-k over batch-mean ----------------
__global__ void topk_k(const float* __restrict__ mv, int* __restrict__ idxout)
{
    int t = threadIdx.x;
    __shared__ float vals[1024];
    __shared__ float rv[1024];
    __shared__ int   ri[1024];
    float g = 0.f;
    for (int b = 0; b < BB; b++) g += mv[(size_t)b * 1024 + t];
    vals[t] = g;
    __syncthreads();
    for (int k = 0; k < TOPK; k++) {
        rv[t] = vals[t]; ri[t] = t; __syncthreads();
        for (int s = 512; s > 0; s >>= 1) {
            if (t < s) {
                if (rv[t + s] > rv[t] || (rv[t + s] == rv[t] && ri[t + s] < ri[t])) {
                    rv[t] = rv[t + s]; ri[t] = ri[t + s];
                }
            }
            __syncthreads();
        }
        if (t == 0) { idxout[k] = ri[0]; vals[ri[0]] = -3.4e38f; }
        __syncthreads();
    }
}

// ---------------- per-batch softmax weights ----------------
__global__ void weights_k(const float* __restrict__ mv, const int* __restrict__ idx,
                          float* __restrict__ w)
{
    int b = blockIdx.x, t = threadIdx.x;
    __shared__ float sv[64];
    float v = (t < TOPK) ? mv[(size_t)b * 1024 + idx[t]] : -3.4e38f;
    sv[t] = v; __syncthreads();
    float mx = -3.4e38f;
    for (int i = 0; i < TOPK; i++) mx = fmaxf(mx, sv[i]);
    __syncthreads();
    float e = (t < TOPK) ? expf(v - mx) : 0.f;
    sv[t] = e; __syncthreads();
    float sm = 0.f;
    for (int i = 0; i < TOPK; i++) sm += sv[i];
    if (t < TOPK) w[(size_t)b * 64 + t] = e / sm;
}

// ---------------- flash attention with tf32 tensor cores ----------------
// qs/ks/vs in (B,D,L). out in (B,L,D). K = raw Kt (band filter C is a
// symmetric projection). 128 threads = 4 warps; each warp owns 16 l-rows
// (1 m-atom) x 64 s-cols (8 n-atoms) per iteration.
__global__ void __launch_bounds__(128) flash_tc(
    const float* __restrict__ qs, const float* __restrict__ ks,
    const float* __restrict__ vs, float* __restrict__ out)
{
    extern __shared__ float sm[];
    float* Qs = sm;                     // [e][l] stride 72 ((8k+m)%32 distinct)
    float* Ks = Qs + 64 * 72;           // [e][s] stride 72
    float* Vs = Ks + 64 * 72;           // [s][e] stride 72
    float* Ps = Vs + 64 * 72;           // [l][s] stride 68 ((4m+k)%32 distinct)
    const int bh = blockIdx.y, b = bh >> 2, h = bh & 3;
    const int l0 = blockIdx.x * 64;
    const float* Q  = qs + ((size_t)b * DD + h * EE) * LL;
    const float* Kp = ks + ((size_t)b * DD + h * EE) * LL;
    const float* V  = vs + ((size_t)b * DD + h * EE) * LL;
    const int tid = threadIdx.x, wid = tid >> 5, lane = tid & 31;
    const int grp = lane >> 2, tig = lane & 3;
    const int lw = wid * 16;

    // load Q tile once: Qs[e][l_local]
    {
        int e = tid >> 1;
        int cb = (tid & 1) * 32;
#pragma unroll
        for (int w = 0; w < 8; w++) {
            int col = cb + w * 4;
            *(float4*)&Qs[e * 72 + col] = *(const float4*)&Q[(size_t)e * LL + l0 + col];
        }
    }

    float m0 = -1e30f, m1 = -1e30f, li0 = 0.f, li1 = 0.f;
    float o[8][4];
#pragma unroll
    for (int en = 0; en < 8; en++)
#pragma unroll
        for (int q = 0; q < 4; q++) o[en][q] = 0.f;

    for (int s0 = 0; s0 < LL; s0 += 64) {
        __syncthreads();
        {
            int e = tid >> 1;
            int cb = (tid & 1) * 32;
#pragma unroll
            for (int w = 0; w < 8; w++) {
                int col = cb + w * 4;
                *(float4*)&Ks[e * 72 + col] = *(const float4*)&Kp[(size_t)e * LL + s0 + col];
                float4 vv = *(const float4*)&V[(size_t)e * LL + s0 + col];
                Vs[(col + 0) * 72 + e] = vv.x;
                Vs[(col + 1) * 72 + e] = vv.y;
                Vs[(col + 2) * 72 + e] = vv.z;
                Vs[(col + 3) * 72 + e] = vv.w;
            }
        }
        __syncthreads();

        // S = Q^T K  (A[m=l][k=e] gathered from Qs[e][l])
        float sa[8][4];
#pragma unroll
        for (int an = 0; an < 8; an++)
#pragma unroll
            for (int q = 0; q < 4; q++) sa[an][q] = 0.f;
#pragma unroll
        for (int k8 = 0; k8 < 64; k8 += 8) {
            uint32_t a[4];
            a[0] = f2tf(Qs[(k8 + tig) * 72 + lw + grp]);
            a[1] = f2tf(Qs[(k8 + tig) * 72 + lw + grp + 8]);
            a[2] = f2tf(Qs[(k8 + tig + 4) * 72 + lw + grp]);
            a[3] = f2tf(Qs[(k8 + tig + 4) * 72 + lw + grp + 8]);
#pragma unroll
            for (int an = 0; an < 8; an++) {
                uint32_t bb[2];
                bb[0] = f2tf(Ks[(k8 + tig) * 72 + an * 8 + grp]);
                bb[1] = f2tf(Ks[(k8 + tig + 4) * 72 + an * 8 + grp]);
                mma_tf32(sa[an], a, bb);
            }
        }

        // online softmax: rows r0 = lw+grp, r1 = r0+8; quad (xor 1,2) = full row
        float mx0 = -1e30f, mx1 = -1e30f;
#pragma unroll
        for (int an = 0; an < 8; an++) {
#pragma unroll
            for (int q = 0; q < 4; q++) sa[an][q] *= 0.125f;
            mx0 = fmaxf(mx0, fmaxf(sa[an][0], sa[an][1]));
            mx1 = fmaxf(mx1, fmaxf(sa[an][2], sa[an][3]));
        }
        mx0 = fmaxf(mx0, __shfl_xor_sync(0xffffffffu, mx0, 1));
        mx0 = fmaxf(mx0, __shfl_xor_sync(0xffffffffu, mx0, 2));
        mx1 = fmaxf(mx1, __shfl_xor_sync(0xffffffffu, mx1, 1));
        mx1 = fmaxf(mx1, __shfl_xor_sync(0xffffffffu, mx1, 2));
        float mn0 = fmaxf(m0, mx0), mn1 = fmaxf(m1, mx1);
        float al0 = fexp(m0 - mn0), al1 = fexp(m1 - mn1);
        m0 = mn0; m1 = mn1;
        float ps0 = 0.f, ps1 = 0.f;
#pragma unroll
        for (int an = 0; an < 8; an++) {
            float p0 = fexp(sa[an][0] - mn0);
            float p1 = fexp(sa[an][1] - mn0);
            float p2 = fexp(sa[an][2] - mn1);
            float p3 = fexp(sa[an][3] - mn1);
            ps0 += p0 + p1; ps1 += p2 + p3;
            float2 w0; w0.x = p0; w0.y = p1;
            float2 w1; w1.x = p2; w1.y = p3;
            *(float2*)&Ps[(lw + grp) * 68 + an * 8 + 2 * tig] = w0;
            *(float2*)&Ps[(lw + grp + 8) * 68 + an * 8 + 2 * tig] = w1;
        }
        ps0 += __shfl_xor_sync(0xffffffffu, ps0, 1);
        ps0 += __shfl_xor_sync(0xffffffffu, ps0, 2);
        ps1 += __shfl_xor_sync(0xffffffffu, ps1, 1);
        ps1 += __shfl_xor_sync(0xffffffffu, ps1, 2);
        li0 = li0 * al0 + ps0;
        li1 = li1 * al1 + ps1;
#pragma unroll
        for (int en = 0; en < 8; en++) {
            o[en][0] *= al0; o[en][1] *= al0;
            o[en][2] *= al1; o[en][3] *= al1;
        }
        __syncwarp();

        // O += P V  (A[m=l][k=s] from Ps[l][s]; B[k=s][n=e] from Vs[s][e])
#pragma unroll
        for (int s8 = 0; s8 < 64; s8 += 8) {
            uint32_t a[4];
            a[0] = f2tf(Ps[(lw + grp) * 68 + s8 + tig]);
            a[1] = f2tf(Ps[(lw + grp + 8) * 68 + s8 + tig]);
            a[2] = f2tf(Ps[(lw + grp) * 68 + s8 + tig + 4]);
            a[3] = f2tf(Ps[(lw + grp + 8) * 68 + s8 + tig + 4]);
#pragma unroll
            for (int en = 0; en < 8; en++) {
                uint32_t bb[2];
                bb[0] = f2tf(Vs[(s8 + tig) * 72 + en * 8 + grp]);
                bb[1] = f2tf(Vs[(s8 + tig + 4) * 72 + en * 8 + grp]);
                mma_tf32(o[en], a, bb);
            }
        }
    }

    // epilogue
    float inv0 = 1.0f / li0, inv1 = 1.0f / li1;
#pragma unroll
    for (int en = 0; en < 8; en++) {
        int col = h * EE + en * 8 + 2 * tig;
        float2 w0; w0.x = o[en][0] * inv0; w0.y = o[en][1] * inv0;
        float2 w1; w1.x = o[en][2] * inv1; w1.y = o[en][3] * inv1;
        *(float2*)&out[((size_t)b * LL + l0 + lw + grp) * DD + col] = w0;
        *(float2*)&out[((size_t)b * LL + l0 + lw + grp + 8) * DD + col] = w1;
    }
}

// ---------------- time delay aggregation (B,D,L) ----------------
__global__ void timeagg_k(const float* __restrict__ Vt, const float* __restrict__ w,
                          const int* __restrict__ idx, float* __restrict__ agg)
{
    int bd = blockIdx.x;
    int b = bd >> 8;
    __shared__ float row[1024];
    __shared__ float ws[TOPK];
    __shared__ int   is[TOPK];
    int t = threadIdx.x;
    for (int l = t; l < 1024; l += 256) row[l] = Vt[(size_t)bd * 1024 + l];
    if (t < TOPK) { ws[t] = w[(size_t)b * 64 + t]; is[t] = idx[t]; }
    __syncthreads();
    for (int l = t; l < 1024; l += 256) {
        float a = 0.f;
#pragma unroll
        for (int k = 0; k < TOPK; k++) a = fmaf(ws[k], row[(l + is[k]) & 1023], a);
        agg[(size_t)bd * 1024 + l] = a;
    }
}

// ---------------- context = 0.9*agg^T + 0.1*ctx_sp ----------------
__global__ void mix_k(const float* __restrict__ agg, const float* __restrict__ csp,
                      float* __restrict__ ctx)
{
    __shared__ float tile[32][33];
    int b = blockIdx.z;
    int l0 = blockIdx.x * 32, d0 = blockIdx.y * 32;
    int x = threadIdx.x, y = threadIdx.y;
#pragma unroll
    for (int i = 0; i < 32; i += 8)
        tile[y + i][x] = agg[((size_t)b * DD + d0 + y + i) * LL + l0 + x];
    __syncthreads();
#pragma unroll
    for (int i = 0; i < 32; i += 8) {
        size_t o = ((size_t)b * LL + l0 + y + i) * DD + d0 + x;
        ctx[o] = 0.9f * tile[x][y + i] + 0.1f * csp[o];
    }
}

// ---------------- LayerNorm over D=256 ----------------
__global__ void ln_k(const float* __restrict__ in, const float* __restrict__ g,
                     const float* __restrict__ b, float* __restrict__ out)
{
    size_t row = blockIdx.x;
    int t = threadIdx.x;
    float v = in[row * DD + t];
    __shared__ float red[256];
    red[t] = v; __syncthreads();
    for (int s = 128; s > 0; s >>= 1) { if (t < s) red[t] += red[t + s]; __syncthreads(); }
    float m = red[0] * (1.0f / 256.0f);
    __syncthreads();
    float d = v - m;
    red[t] = d * d; __syncthreads();
    for (int s = 128; s > 0; s >>= 1) { if (t < s) red[t] += red[t + s]; __syncthreads(); }
    float var = red[0] * (1.0f / 256.0f);
    out[row * DD + t] = d * rsqrtf(var + 1e-8f) * g[t] + b[t];
}

// ---------------- launch ----------------
extern "C" void kernel_launch(void* const* d_in, const int* in_sizes, int n_in,
                              void* d_out, int out_size)
{
    const float* x   = (const float*)d_in[0];
    const float* Wq  = (const float*)d_in[1];
    const float* bq  = (const float*)d_in[2];
    const float* Wk  = (const float*)d_in[3];
    const float* bk  = (const float*)d_in[4];
    const float* Wv  = (const float*)d_in[5];
    const float* bv  = (const float*)d_in[6];
    const float* Wd  = (const float*)d_in[7];
    const float* bd  = (const float*)d_in[8];
    const float* ln1g = (const float*)d_in[9];
    const float* ln1b = (const float*)d_in[10];
    const float* W1  = (const float*)d_in[11];
    const float* b1  = (const float*)d_in[12];
    const float* W2  = (const float*)d_in[13];
    const float* b2  = (const float*)d_in[14];
    const float* ln2g = (const float*)d_in[15];
    const float* ln2b = (const float*)d_in[16];
    float* out = (float*)d_out;

    float* scr = nullptr;
    int* idxp = nullptr;
    cudaGetSymbolAddress((void**)&scr, g_scr);
    cudaGetSymbolAddress((void**)&idxp, g_idx);

    float* bQ   = scr + O_Q;   float* bK  = scr + O_K;   float* bV  = scr + O_V;
    float* Kt   = scr + O_KT;  float* Vt  = scr + O_VT;  float* trb = scr + O_TR;
    float* spQ  = scr + O_SPQ; float* spK = scr + O_SPK; float* spV = scr + O_SPV;
    float* qsb  = scr + O_QS;  float* vsb = scr + O_VS;
    float* csp  = scr + O_CSP; float* agg = scr + O_AGG; float* ctx = scr + O_CTX;
    float* t1   = scr + O_T1;  float* hb  = scr + O_H;
    float* g1b  = scr + O_G1;  float* fb  = scr + O_F;
    float* Sb   = scr + O_S;   float* mv  = scr + O_MV;  float* wts = scr + O_W;

    const int flash_smem = (3 * 64 * 72 + 64 * 68) * sizeof(float);   // 72704 B
    cudaFuncSetAttribute(flash_tc, cudaFuncAttributeMaxDynamicSharedMemorySize, flash_smem);

    const dim3 tb(32, 8);

    // 1. xT, then QKV projections (fp32 — keep corr/topk path exact)
    tr_k<<<dim3(8, 1024, 1), tb>>>(x, trb, BB * LL, DD, 0, 0);
    gemm_t<1><<<dim3(2, 256, 1), 256>>>(trb, Wq, bq, nullptr, bQ, BB * LL, DD, DD, 0, 0);
    gemm_t<1><<<dim3(2, 256, 1), 256>>>(trb, Wk, bk, nullptr, bK, BB * LL, DD, DD, 0, 0);
    gemm_t<1><<<dim3(2, 256, 1), 256>>>(trb, Wv, bv, nullptr, bV, BB * LL, DD, DD, 0, 0);

    // 2. transposes to (B,D,L): Kt/Vt persist; Qt reuses trb
    tr_k<<<dim3(8, 32, BB), tb>>>(bK, Kt, LL, DD, LL * DD, LL * DD);
    tr_k<<<dim3(8, 32, BB), tb>>>(bV, Vt, LL, DD, LL * DD, LL * DD);
    tr_k<<<dim3(8, 32, BB), tb>>>(bQ, trb, LL, DD, LL * DD, LL * DD);

    // 3. forward band FFT
    fftfwd_k<<<BB * DD, 256>>>(trb, spQ);
    fftfwd_k<<<BB * DD, 256>>>(Kt, spK);
    fftfwd_k<<<BB * DD, 256>>>(Vt, spV);

    // 4. corr mean path
    corr_spec_k<<<dim3(NBAND, BB), 256>>>(spQ, spK, Sb);
    meanv_k<<<BB, 256>>>(Sb, mv);
    topk_k<<<1, 1024>>>(mv, idxp);
    weights_k<<<BB, 64>>>(mv, idxp, wts);

    // 5. inverse band FFT -> qs, vs
    fftinv_k<<<BB * DD, 256>>>(spQ, qsb);
    fftinv_k<<<BB * DD, 256>>>(spV, vsb);

    // 6. spatial attention (tf32 tensor cores; K = raw Kt)
    flash_tc<<<dim3(16, BB * HH), 128, flash_smem>>>(qsb, Kt, vsb, csp);

    // 7. time aggregation + mix
    timeagg_k<<<BB * DD, 256>>>(Vt, wts, idxp, agg);
    mix_k<<<dim3(32, 8, BB), tb>>>(agg, csp, ctx);

    // 8. output projection + residual + LN1 (tf32, row-major A — no transpose)
    gemm_tc<2><<<dim3(2, 256), 256>>>(ctx, Wd, bd, x, t1, BB * LL, DD, DD);
    ln_k<<<BB * LL, 256>>>(t1, ln1g, ln1b, hb);

    // 9. FFN + LN2 (tf32, row-major A)
    gemm_tc<3><<<dim3(2, 256), 256>>>(hb, W1, b1, nullptr, g1b, BB * LL, DD, DD);
    gemm_tc<2><<<dim3(2, 256), 256>>>(g1b, W2, b2, hb, fb, BB * LL, DD, DD);
    ln_k<<<BB * LL, 256>>>(fb, ln2g, ln2b, out);
}

// round 9
// speedup vs baseline: 2.2894x; 1.1323x over previous
#include <cuda_runtime.h>
#include <math.h>
#include <stdint.h>

// ---------------- problem constants ----------------
#define BB 32
#define LL 1024
#define DD 256
#define HH 4
#define EE 64
#define NBAND 308          // f = 205..512
#define F0 205
#define TOPK 34

// ---------------- scratch layout (floats) ----------------
constexpr size_t SZ   = (size_t)BB * LL * DD;        // 8388608
constexpr size_t SPEC = (size_t)BB * DD * 640;       // 5242880 (8192 x 640)

constexpr size_t O_Q    = 0;
constexpr size_t O_K    = O_Q + SZ;
constexpr size_t O_V    = O_K + SZ;
constexpr size_t O_KT   = O_V + SZ;
constexpr size_t O_VT   = O_KT + SZ;
constexpr size_t O_TR   = O_VT + SZ;       // Qt
constexpr size_t O_SPQ  = O_TR + SZ;
constexpr size_t O_SPK  = O_SPQ + SPEC;
constexpr size_t O_SPV  = O_SPK + SPEC;
constexpr size_t O_QS   = O_SPV + SPEC;
constexpr size_t O_VS   = O_QS + SZ;
constexpr size_t O_CSP  = O_VS + SZ;       // ctx spatial (B,L,D)
constexpr size_t O_AGG  = O_CSP + SZ;      // time agg (B,D,L)
constexpr size_t O_CTX  = O_AGG + SZ;      // mixed context (B,L,D)
constexpr size_t O_T1   = O_CTX + SZ;      // also reused as corr partials scratch
constexpr size_t O_H    = O_T1 + SZ;
constexpr size_t O_G1   = O_H + SZ;
constexpr size_t O_F    = O_G1 + SZ;
constexpr size_t O_S    = O_F + SZ;                 // per-batch spectrum sum 32x640
constexpr size_t O_MV   = O_S + (size_t)BB * 640;   // mean_value 32x1024
constexpr size_t O_W    = O_MV + (size_t)BB * LL;   // weights 32x64
constexpr size_t TOTAL  = O_W + (size_t)BB * 64;

__device__ float g_scr[TOTAL + 1024];
__device__ int   g_idx[64];

// ---------------- cp.async helpers ----------------
__device__ __forceinline__ void cpa16(uint32_t saddr, const void* gptr) {
    asm volatile("cp.async.cg.shared.global [%0], [%1], 16;" :: "r"(saddr), "l"(gptr));
}
__device__ __forceinline__ void cpa_commit() {
    asm volatile("cp.async.commit_group;");
}
template<int N>
__device__ __forceinline__ void cpa_wait() {
    asm volatile("cp.async.wait_group %0;" :: "n"(N));
}

// ---------------- tf32 mma helpers ----------------
__device__ __forceinline__ uint32_t f2tf(float f) {
    uint32_t u;
    asm("cvt.rna.tf32.f32 %0, %1;" : "=r"(u) : "f"(f));
    return u;
}
__device__ __forceinline__ void mma_tf32(float* d, const uint32_t* a, const uint32_t* b) {
    asm volatile(
        "mma.sync.aligned.m16n8k8.row.col.f32.tf32.tf32.f32 "
        "{%0,%1,%2,%3}, {%4,%5,%6,%7}, {%8,%9}, {%0,%1,%2,%3};"
        : "+f"(d[0]), "+f"(d[1]), "+f"(d[2]), "+f"(d[3])
        : "r"(a[0]), "r"(a[1]), "r"(a[2]), "r"(a[3]), "r"(b[0]), "r"(b[1]));
}

// ---------------- fast exp on the FMA pipe (no MUFU) ----------------
__device__ __forceinline__ float fexp(float x) {
    x = fmaxf(x, -87.0f);
    float z = x * 1.4426950408889634f;
    float r = rintf(z);
    float f = z - r;
    float p = 1.5403530e-4f;
    p = fmaf(p, f, 1.3333558e-3f);
    p = fmaf(p, f, 9.6181291e-3f);
    p = fmaf(p, f, 5.5504109e-2f);
    p = fmaf(p, f, 2.4022651e-1f);
    p = fmaf(p, f, 6.9314718e-1f);
    p = fmaf(p, f, 1.0f);
    int e = (int)r;
    return __int_as_float((e + 127) << 23) * p;
}

// ---------------- 1024-pt radix-2 FFT machinery ----------------
__global__ void __launch_bounds__(256) fftfwd_k(
    const float* __restrict__ in, float* __restrict__ spec)
{
    __shared__ float2 s[1024];
    __shared__ float2 tw[512];
    const int row = blockIdx.x;
    const float* xr = in + (size_t)row * LL;
    const int t = threadIdx.x;

    for (int k = t; k < 512; k += 256) {
        float ang = -6.283185307179586f * (float)k / 1024.0f;
        tw[k] = make_float2(cosf(ang), sinf(ang));
    }
    for (int l = t; l < 1024; l += 256) {
        int r = __brev((unsigned)l) >> 22;
        s[r] = make_float2(xr[l], 0.f);
    }
    __syncthreads();
#pragma unroll
    for (int st = 0; st < 10; st++) {
        const int half = 1 << st;
#pragma unroll
        for (int u = 0; u < 2; u++) {
            int j = t + (u << 8);
            int pos = j & (half - 1);
            int base = ((j >> st) << (st + 1)) | pos;
            float2 w = tw[pos << (9 - st)];
            float2 a = s[base], b = s[base + half];
            float2 bw = make_float2(b.x * w.x - b.y * w.y, b.x * w.y + b.y * w.x);
            s[base]        = make_float2(a.x + bw.x, a.y + bw.y);
            s[base + half] = make_float2(a.x - bw.x, a.y - bw.y);
        }
        __syncthreads();
    }
    for (int j = t; j < NBAND; j += 256) {
        float2 v = s[F0 + j];
        spec[(size_t)row * 640 + j]       = v.x;
        spec[(size_t)row * 640 + 320 + j] = v.y;
    }
}

__global__ void __launch_bounds__(256) fftinv_k(
    const float* __restrict__ spec, float* __restrict__ outr)
{
    __shared__ float2 s[1024];
    __shared__ float2 tw[512];
    const int row = blockIdx.x;
    const float* sp = spec + (size_t)row * 640;
    const int t = threadIdx.x;

    for (int k = t; k < 512; k += 256) {
        float ang = 6.283185307179586f * (float)k / 1024.0f;
        tw[k] = make_float2(cosf(ang), sinf(ang));
    }
    for (int l = t; l < 1024; l += 256) {
        float2 v = make_float2(0.f, 0.f);
        if (l >= F0 && l <= 512) {
            v.x = sp[l - F0];
            v.y = sp[320 + l - F0];
        } else if (l >= 513 && l <= 1024 - F0) {
            int f = 1024 - l;
            v.x = sp[f - F0];
            v.y = -sp[320 + f - F0];
        }
        s[__brev((unsigned)l) >> 22] = v;
    }
    __syncthreads();
#pragma unroll
    for (int st = 0; st < 10; st++) {
        const int half = 1 << st;
#pragma unroll
        for (int u = 0; u < 2; u++) {
            int j = t + (u << 8);
            int pos = j & (half - 1);
            int base = ((j >> st) << (st + 1)) | pos;
            float2 w = tw[pos << (9 - st)];
            float2 a = s[base], b = s[base + half];
            float2 bw = make_float2(b.x * w.x - b.y * w.y, b.x * w.y + b.y * w.x);
            s[base]        = make_float2(a.x + bw.x, a.y + bw.y);
            s[base + half] = make_float2(a.x - bw.x, a.y - bw.y);
        }
        __syncthreads();
    }
    const float sc = 1.0f / 1024.0f;
    for (int l = t; l < 1024; l += 256)
        outr[(size_t)row * LL + l] = s[l].x * sc;
}

// ---------------- tf32 tensor-core GEMM, row-major A --------------
// C[M,N] = A[M,K] @ Bw[K,N] (+epilogue). 256 thr, 8 warps.
// EPI: 1 +bias, 2 +bias+res, 3 +bias then gelu(erf)
template<int EPI>
__global__ void __launch_bounds__(256) gemm_tc(
    const float* __restrict__ A, const float* __restrict__ Bw,
    const float* __restrict__ bias, const float* __restrict__ res,
    float* __restrict__ C, int M, int N, int K)
{
    __shared__ float As[2][128][20];   // [m][k] pad 20
    __shared__ float Bs[2][16][136];   // [k][n] pad 136
    const int bn = blockIdx.x * 128;
    const int bm = blockIdx.y * 128;
    const int tid = threadIdx.x, wid = tid >> 5, lane = tid & 31;
    const int grp = lane >> 2, tig = lane & 3;
    const int wm = (wid & 3) * 32, wn = (wid >> 2) * 64;

    const uint32_t asb = (uint32_t)__cvta_generic_to_shared(&As[0][0][0]);
    const uint32_t bsb = (uint32_t)__cvta_generic_to_shared(&Bs[0][0][0]);
    const int T = K >> 4;

    auto loadA = [&](int st, int k0) {
#pragma unroll
        for (int u = 0; u < 2; u++) {
            int c = tid + u * 256;
            int row = c >> 2, kq = (c & 3) * 4;
            cpa16(asb + (uint32_t)(st * 128 * 20 + row * 20 + kq) * 4,
                  &A[(size_t)(bm + row) * K + k0 + kq]);
        }
    };
    auto loadB = [&](int st, int k0) {
#pragma unroll
        for (int u = 0; u < 2; u++) {
            int c = tid + u * 256;
            int r = c >> 5, col = (c & 31) * 4;
            cpa16(bsb + (uint32_t)(st * 16 * 136 + r * 136 + col) * 4,
                  &Bw[(size_t)(k0 + r) * N + bn + col]);
        }
    };

    loadA(0, 0); loadB(0, 0); cpa_commit();

    float d[2][8][4];
#pragma unroll
    for (int am = 0; am < 2; am++)
#pragma unroll
        for (int an = 0; an < 8; an++)
#pragma unroll
            for (int q = 0; q < 4; q++) d[am][an][q] = 0.f;

    for (int kt = 0; kt < T; kt++) {
        if (kt + 1 < T) {
            loadA((kt + 1) & 1, (kt + 1) << 4);
            loadB((kt + 1) & 1, (kt + 1) << 4);
            cpa_commit();
            cpa_wait<1>();
        } else {
            cpa_wait<0>();
        }
        __syncthreads();
        const int st = kt & 1;
#pragma unroll
        for (int k8 = 0; k8 < 16; k8 += 8) {
            uint32_t a[2][4];
#pragma unroll
            for (int am = 0; am < 2; am++) {
                int mr = wm + am * 16;
                a[am][0] = f2tf(As[st][mr + grp][k8 + tig]);
                a[am][1] = f2tf(As[st][mr + grp + 8][k8 + tig]);
                a[am][2] = f2tf(As[st][mr + grp][k8 + tig + 4]);
                a[am][3] = f2tf(As[st][mr + grp + 8][k8 + tig + 4]);
            }
#pragma unroll
            for (int an = 0; an < 8; an++) {
                uint32_t b[2];
                b[0] = f2tf(Bs[st][k8 + tig][wn + an * 8 + grp]);
                b[1] = f2tf(Bs[st][k8 + tig + 4][wn + an * 8 + grp]);
                mma_tf32(d[0][an], a[0], b);
                mma_tf32(d[1][an], a[1], b);
            }
        }
        __syncthreads();
    }

#pragma unroll
    for (int am = 0; am < 2; am++) {
        int row0 = bm + wm + am * 16 + grp;
#pragma unroll
        for (int an = 0; an < 8; an++) {
            int col = bn + wn + an * 8 + 2 * tig;
            float o0 = d[am][an][0], o1 = d[am][an][1];
            float o2 = d[am][an][2], o3 = d[am][an][3];
            float2 bv = *(const float2*)&bias[col];
            o0 += bv.x; o1 += bv.y; o2 += bv.x; o3 += bv.y;
            if (EPI == 2) {
                float2 r0v = *(const float2*)&res[(size_t)row0 * N + col];
                float2 r1v = *(const float2*)&res[(size_t)(row0 + 8) * N + col];
                o0 += r0v.x; o1 += r0v.y; o2 += r1v.x; o3 += r1v.y;
            }
            if (EPI == 3) {
                o0 = o0 * 0.5f * (1.0f + erff(o0 * 0.70710678118654752f));
                o1 = o1 * 0.5f * (1.0f + erff(o1 * 0.70710678118654752f));
                o2 = o2 * 0.5f * (1.0f + erff(o2 * 0.70710678118654752f));
                o3 = o3 * 0.5f * (1.0f + erff(o3 * 0.70710678118654752f));
            }
            float2 w0; w0.x = o0; w0.y = o1;
            float2 w1; w1.x = o2; w1.y = o3;
            *(float2*)&C[(size_t)row0 * N + col] = w0;
            *(float2*)&C[(size_t)(row0 + 8) * N + col] = w1;
        }
    }
}

// ---------------- generic batched transpose: in[R][Cc] -> out[Cc][R] --------
__global__ void tr_k(const float* __restrict__ in, float* __restrict__ out,
                     int R, int Cc, size_t sIn, size_t sOut)
{
    __shared__ float tile[32][33];
    int b = blockIdx.z;
    const float* I = in + (size_t)b * sIn;
    float* O = out + (size_t)b * sOut;
    int c0 = blockIdx.x * 32, r0 = blockIdx.y * 32;
    int x = threadIdx.x, y = threadIdx.y;
#pragma unroll
    for (int i = 0; i < 32; i += 8)
        tile[y + i][x] = I[(size_t)(r0 + y + i) * Cc + c0 + x];
    __syncthreads();
#pragma unroll
    for (int i = 0; i < 32; i += 8)
        O[(size_t)(c0 + y + i) * R + r0 + x] = tile[x][y + i];
}

// ---------------- corr spectrum sum, pass 1 (coalesced partials) ----------
// grid (8, BB): block (g,b) accumulates rows [g*32, g*32+32) of batch b.
// Spart[(b*8+g)*640 + j] (re), + 320 + j (im).
__global__ void __launch_bounds__(256) corr_part_k(
    const float* __restrict__ Qs, const float* __restrict__ Ks,
    float* __restrict__ Spart)
{
    const int g = blockIdx.x, b = blockIdx.y;
    const int t = threadIdx.x;
    const int j0 = t, j1 = t + 256;
    float re0 = 0.f, im0 = 0.f, re1 = 0.f, im1 = 0.f;
    size_t base = ((size_t)(b * 256 + g * 32)) * 640;
    for (int r = 0; r < 32; r++) {
        size_t row = base + (size_t)r * 640;
        float qr = Qs[row + j0], qi = Qs[row + 320 + j0];
        float kr = Ks[row + j0], ki = Ks[row + 320 + j0];
        re0 += qr * kr + qi * ki;
        im0 += qi * kr - qr * ki;
        if (j1 < NBAND) {
            qr = Qs[row + j1]; qi = Qs[row + 320 + j1];
            kr = Ks[row + j1]; ki = Ks[row + 320 + j1];
            re1 += qr * kr + qi * ki;
            im1 += qi * kr - qr * ki;
        }
    }
    size_t o = (size_t)(b * 8 + g) * 640;
    Spart[o + j0] = re0;
    Spart[o + 320 + j0] = im0;
    if (j1 < NBAND) {
        Spart[o + j1] = re1;
        Spart[o + 320 + j1] = im1;
    } else if (j1 < 320) {
        Spart[o + j1] = 0.f;
        Spart[o + 320 + j1] = 0.f;
    }
}

// pass 2: deterministic reduction of 8 partials per batch
__global__ void corr_red_k(const float* __restrict__ Spart, float* __restrict__ S)
{
    int b = blockIdx.x, t = threadIdx.x;   // 256
    for (int e = t; e < 640; e += 256) {
        float a = 0.f;
#pragma unroll
        for (int g = 0; g < 8; g++)
            a += Spart[(size_t)(b * 8 + g) * 640 + e];
        S[(size_t)b * 640 + e] = a;
    }
}

// ---------------- mean_value[b,t] = (1/256) irfft(S*mask)[t] ----------------
// grid (BB, 4): each block computes 256 of the 1024 t-values.
__global__ void __launch_bounds__(256) meanv_k(
    const float* __restrict__ S, float* __restrict__ mv)
{
    int b = blockIdx.x, t = threadIdx.x;
    __shared__ float sre[NBAND], sim[NBAND], tbl[1024];
    for (int j = t; j < NBAND; j += 256) {
        sre[j] = S[(size_t)b * 640 + j];
        sim[j] = S[(size_t)b * 640 + 320 + j];
    }
    for (int m = t; m < 1024; m += 256)
        tbl[m] = cosf(6.283185307179586f * (float)m / 1024.0f);
    __syncthreads();
    int tt = blockIdx.y * 256 + t;
    float acc = sre[NBAND - 1] * ((tt & 1) ? -1.f : 1.f);   // f=512 Nyquist
    for (int j = 0; j < NBAND - 1; j++) {
        int f = F0 + j;
        int m = (f * tt) & 1023;
        float c = tbl[m];
        float s = tbl[(m + 768) & 1023];
        acc += 2.f * (sre[j] * c - sim[j] * s);
    }
    mv[(size_t)b * 1024 + tt] = acc * (1.0f / (256.0f * 1024.0f));
}

// ---------------- top-k over batch-mean ----------------
__global__ void topk_k(const float* __restrict__ mv, int* __restrict__ idxout)
{
    int t = threadIdx.x;
    __shared__ float vals[1024];
    __shared__ float rv[1024];
    __shared__ int   ri[1024];
    float g = 0.f;
    for (int b = 0; b < BB; b++) g += mv[(size_t)b * 1024 + t];
    vals[t] = g;
    __syncthreads();
    for (int k = 0; k < TOPK; k++) {
        rv[t] = vals[t]; ri[t] = t; __syncthreads();
        for (int s = 512; s > 0; s >>= 1) {
            if (t < s) {
                if (rv[t + s] > rv[t] || (rv[t + s] == rv[t] && ri[t + s] < ri[t])) {
                    rv[t] = rv[t + s]; ri[t] = ri[t + s];
                }
            }
            __syncthreads();
        }
        if (t == 0) { idxout[k] = ri[0]; vals[ri[0]] = -3.4e38f; }
        __syncthreads();
    }
}

// ---------------- per-batch softmax weights ----------------
__global__ void weights_k(const float* __restrict__ mv, const int* __restrict__ idx,
                          float* __restrict__ w)
{
    int b = blockIdx.x, t = threadIdx.x;
    __shared__ float sv[64];
    float v = (t < TOPK) ? mv[(size_t)b * 1024 + idx[t]] : -3.4e38f;
    sv[t] = v; __syncthreads();
    float mx = -3.4e38f;
    for (int i = 0; i < TOPK; i++) mx = fmaxf(mx, sv[i]);
    __syncthreads();
    float e = (t < TOPK) ? expf(v - mx) : 0.f;
    sv[t] = e; __syncthreads();
    float sm = 0.f;
    for (int i = 0; i < TOPK; i++) sm += sv[i];
    if (t < TOPK) w[(size_t)b * 64 + t] = e / sm;
}

// ---------------- flash attention with tf32 tensor cores ----------------
__global__ void __launch_bounds__(128) flash_tc(
    const float* __restrict__ qs, const float* __restrict__ ks,
    const float* __restrict__ vs, float* __restrict__ out)
{
    extern __shared__ float sm[];
    float* Qs = sm;                     // [e][l] stride 72
    float* Ks = Qs + 64 * 72;           // [e][s] stride 72
    float* Vs = Ks + 64 * 72;           // [s][e] stride 72
    float* Ps = Vs + 64 * 72;           // [l][s] stride 68
    const int bh = blockIdx.y, b = bh >> 2, h = bh & 3;
    const int l0 = blockIdx.x * 64;
    const float* Q  = qs + ((size_t)b * DD + h * EE) * LL;
    const float* Kp = ks + ((size_t)b * DD + h * EE) * LL;
    const float* V  = vs + ((size_t)b * DD + h * EE) * LL;
    const int tid = threadIdx.x, wid = tid >> 5, lane = tid & 31;
    const int grp = lane >> 2, tig = lane & 3;
    const int lw = wid * 16;

    {
        int e = tid >> 1;
        int cb = (tid & 1) * 32;
#pragma unroll
        for (int w = 0; w < 8; w++) {
            int col = cb + w * 4;
            *(float4*)&Qs[e * 72 + col] = *(const float4*)&Q[(size_t)e * LL + l0 + col];
        }
    }

    float m0 = -1e30f, m1 = -1e30f, li0 = 0.f, li1 = 0.f;
    float o[8][4];
#pragma unroll
    for (int en = 0; en < 8; en++)
#pragma unroll
        for (int q = 0; q < 4; q++) o[en][q] = 0.f;

    for (int s0 = 0; s0 < LL; s0 += 64) {
        __syncthreads();
        {
            int e = tid >> 1;
            int cb = (tid & 1) * 32;
#pragma unroll
            for (int w = 0; w < 8; w++) {
                int col = cb + w * 4;
                *(float4*)&Ks[e * 72 + col] = *(const float4*)&Kp[(size_t)e * LL + s0 + col];
                float4 vv = *(const float4*)&V[(size_t)e * LL + s0 + col];
                Vs[(col + 0) * 72 + e] = vv.x;
                Vs[(col + 1) * 72 + e] = vv.y;
                Vs[(col + 2) * 72 + e] = vv.z;
                Vs[(col + 3) * 72 + e] = vv.w;
            }
        }
        __syncthreads();

        float sa[8][4];
#pragma unroll
        for (int an = 0; an < 8; an++)
#pragma unroll
            for (int q = 0; q < 4; q++) sa[an][q] = 0.f;
#pragma unroll
        for (int k8 = 0; k8 < 64; k8 += 8) {
            uint32_t a[4];
            a[0] = f2tf(Qs[(k8 + tig) * 72 + lw + grp]);
            a[1] = f2tf(Qs[(k8 + tig) * 72 + lw + grp + 8]);
            a[2] = f2tf(Qs[(k8 + tig + 4) * 72 + lw + grp]);
            a[3] = f2tf(Qs[(k8 + tig + 4) * 72 + lw + grp + 8]);
#pragma unroll
            for (int an = 0; an < 8; an++) {
                uint32_t bb[2];
                bb[0] = f2tf(Ks[(k8 + tig) * 72 + an * 8 + grp]);
                bb[1] = f2tf(Ks[(k8 + tig + 4) * 72 + an * 8 + grp]);
                mma_tf32(sa[an], a, bb);
            }
        }

        float mx0 = -1e30f, mx1 = -1e30f;
#pragma unroll
        for (int an = 0; an < 8; an++) {
#pragma unroll
            for (int q = 0; q < 4; q++) sa[an][q] *= 0.125f;
            mx0 = fmaxf(mx0, fmaxf(sa[an][0], sa[an][1]));
            mx1 = fmaxf(mx1, fmaxf(sa[an][2], sa[an][3]));
        }
        mx0 = fmaxf(mx0, __shfl_xor_sync(0xffffffffu, mx0, 1));
        mx0 = fmaxf(mx0, __shfl_xor_sync(0xffffffffu, mx0, 2));
        mx1 = fmaxf(mx1, __shfl_xor_sync(0xffffffffu, mx1, 1));
        mx1 = fmaxf(mx1, __shfl_xor_sync(0xffffffffu, mx1, 2));
        float mn0 = fmaxf(m0, mx0), mn1 = fmaxf(m1, mx1);
        float al0 = fexp(m0 - mn0), al1 = fexp(m1 - mn1);
        m0 = mn0; m1 = mn1;
        float ps0 = 0.f, ps1 = 0.f;
#pragma unroll
        for (int an = 0; an < 8; an++) {
            float p0 = fexp(sa[an][0] - mn0);
            float p1 = fexp(sa[an][1] - mn0);
            float p2 = fexp(sa[an][2] - mn1);
            float p3 = fexp(sa[an][3] - mn1);
            ps0 += p0 + p1; ps1 += p2 + p3;
            float2 w0; w0.x = p0; w0.y = p1;
            float2 w1; w1.x = p2; w1.y = p3;
            *(float2*)&Ps[(lw + grp) * 68 + an * 8 + 2 * tig] = w0;
            *(float2*)&Ps[(lw + grp + 8) * 68 + an * 8 + 2 * tig] = w1;
        }
        ps0 += __shfl_xor_sync(0xffffffffu, ps0, 1);
        ps0 += __shfl_xor_sync(0xffffffffu, ps0, 2);
        ps1 += __shfl_xor_sync(0xffffffffu, ps1, 1);
        ps1 += __shfl_xor_sync(0xffffffffu, ps1, 2);
        li0 = li0 * al0 + ps0;
        li1 = li1 * al1 + ps1;
#pragma unroll
        for (int en = 0; en < 8; en++) {
            o[en][0] *= al0; o[en][1] *= al0;
            o[en][2] *= al1; o[en][3] *= al1;
        }
        __syncwarp();

#pragma unroll
        for (int s8 = 0; s8 < 64; s8 += 8) {
            uint32_t a[4];
            a[0] = f2tf(Ps[(lw + grp) * 68 + s8 + tig]);
            a[1] = f2tf(Ps[(lw + grp + 8) * 68 + s8 + tig]);
            a[2] = f2tf(Ps[(lw + grp) * 68 + s8 + tig + 4]);
            a[3] = f2tf(Ps[(lw + grp + 8) * 68 + s8 + tig + 4]);
#pragma unroll
            for (int en = 0; en < 8; en++) {
                uint32_t bb[2];
                bb[0] = f2tf(Vs[(s8 + tig) * 72 + en * 8 + grp]);
                bb[1] = f2tf(Vs[(s8 + tig + 4) * 72 + en * 8 + grp]);
                mma_tf32(o[en], a, bb);
            }
        }
    }

    float inv0 = 1.0f / li0, inv1 = 1.0f / li1;
#pragma unroll
    for (int en = 0; en < 8; en++) {
        int col = h * EE + en * 8 + 2 * tig;
        float2 w0; w0.x = o[en][0] * inv0; w0.y = o[en][1] * inv0;
        float2 w1; w1.x = o[en][2] * inv1; w1.y = o[en][3] * inv1;
        *(float2*)&out[((size_t)b * LL + l0 + lw + grp) * DD + col] = w0;
        *(float2*)&out[((size_t)b * LL + l0 + lw + grp + 8) * DD + col] = w1;
    }
}

// ---------------- time delay aggregation (B,D,L) ----------------
__global__ void timeagg_k(const float* __restrict__ Vt, const float* __restrict__ w,
                          const int* __restrict__ idx, float* __restrict__ agg)
{
    int bd = blockIdx.x;
    int b = bd >> 8;
    __shared__ float row[1024];
    __shared__ float ws[TOPK];
    __shared__ int   is[TOPK];
    int t = threadIdx.x;
    for (int l = t; l < 1024; l += 256) row[l] = Vt[(size_t)bd * 1024 + l];
    if (t < TOPK) { ws[t] = w[(size_t)b * 64 + t]; is[t] = idx[t]; }
    __syncthreads();
    for (int l = t; l < 1024; l += 256) {
        float a = 0.f;
#pragma unroll
        for (int k = 0; k < TOPK; k++) a = fmaf(ws[k], row[(l + is[k]) & 1023], a);
        agg[(size_t)bd * 1024 + l] = a;
    }
}

// ---------------- context = 0.9*agg^T + 0.1*ctx_sp ----------------
__global__ void mix_k(const float* __restrict__ agg, const float* __restrict__ csp,
                      float* __restrict__ ctx)
{
    __shared__ float tile[32][33];
    int b = blockIdx.z;
    int l0 = blockIdx.x * 32, d0 = blockIdx.y * 32;
    int x = threadIdx.x, y = threadIdx.y;
#pragma unroll
    for (int i = 0; i < 32; i += 8)
        tile[y + i][x] = agg[((size_t)b * DD + d0 + y + i) * LL + l0 + x];
    __syncthreads();
#pragma unroll
    for (int i = 0; i < 32; i += 8) {
        size_t o = ((size_t)b * LL + l0 + y + i) * DD + d0 + x;
        ctx[o] = 0.9f * tile[x][y + i] + 0.1f * csp[o];
    }
}

// ---------------- LayerNorm over D=256 ----------------
__global__ void ln_k(const float* __restrict__ in, const float* __restrict__ g,
                     const float* __restrict__ b, float* __restrict__ out)
{
    size_t row = blockIdx.x;
    int t = threadIdx.x;
    float v = in[row * DD + t];
    __shared__ float red[256];
    red[t] = v; __syncthreads();
    for (int s = 128; s > 0; s >>= 1) { if (t < s) red[t] += red[t + s]; __syncthreads(); }
    float m = red[0] * (1.0f / 256.0f);
    __syncthreads();
    float d = v - m;
    red[t] = d * d; __syncthreads();
    for (int s = 128; s > 0; s >>= 1) { if (t < s) red[t] += red[t + s]; __syncthreads(); }
    float var = red[0] * (1.0f / 256.0f);
    out[row * DD + t] = d * rsqrtf(var + 1e-8f) * g[t] + b[t];
}

// ---------------- launch ----------------
extern "C" void kernel_launch(void* const* d_in, const int* in_sizes, int n_in,
                              void* d_out, int out_size)
{
    const float* x   = (const float*)d_in[0];
    const float* Wq  = (const float*)d_in[1];
    const float* bq  = (const float*)d_in[2];
    const float* Wk  = (const float*)d_in[3];
    const float* bk  = (const float*)d_in[4];
    const float* Wv  = (const float*)d_in[5];
    const float* bv  = (const float*)d_in[6];
    const float* Wd  = (const float*)d_in[7];
    const float* bd  = (const float*)d_in[8];
    const float* ln1g = (const float*)d_in[9];
    const float* ln1b = (const float*)d_in[10];
    const float* W1  = (const float*)d_in[11];
    const float* b1  = (const float*)d_in[12];
    const float* W2  = (const float*)d_in[13];
    const float* b2  = (const float*)d_in[14];
    const float* ln2g = (const float*)d_in[15];
    const float* ln2b = (const float*)d_in[16];
    float* out = (float*)d_out;

    float* scr = nullptr;
    int* idxp = nullptr;
    cudaGetSymbolAddress((void**)&scr, g_scr);
    cudaGetSymbolAddress((void**)&idxp, g_idx);

    float* bQ   = scr + O_Q;   float* bK  = scr + O_K;   float* bV  = scr + O_V;
    float* Kt   = scr + O_KT;  float* Vt  = scr + O_VT;  float* trb = scr + O_TR;
    float* spQ  = scr + O_SPQ; float* spK = scr + O_SPK; float* spV = scr + O_SPV;
    float* qsb  = scr + O_QS;  float* vsb = scr + O_VS;
    float* csp  = scr + O_CSP; float* agg = scr + O_AGG; float* ctx = scr + O_CTX;
    float* t1   = scr + O_T1;  float* hb  = scr + O_H;
    float* g1b  = scr + O_G1;  float* fb  = scr + O_F;
    float* Sb   = scr + O_S;   float* mv  = scr + O_MV;  float* wts = scr + O_W;

    const int flash_smem = (3 * 64 * 72 + 64 * 68) * sizeof(float);   // 72704 B
    cudaFuncSetAttribute(flash_tc, cudaFuncAttributeMaxDynamicSharedMemorySize, flash_smem);

    const dim3 tb(32, 8);

    // 1. QKV projections (tf32 tensor cores, row-major x directly)
    gemm_tc<1><<<dim3(2, 256), 256>>>(x, Wq, bq, nullptr, bQ, BB * LL, DD, DD);
    gemm_tc<1><<<dim3(2, 256), 256>>>(x, Wk, bk, nullptr, bK, BB * LL, DD, DD);
    gemm_tc<1><<<dim3(2, 256), 256>>>(x, Wv, bv, nullptr, bV, BB * LL, DD, DD);

    // 2. transposes to (B,D,L): Kt/Vt persist; Qt in trb
    tr_k<<<dim3(8, 32, BB), tb>>>(bK, Kt, LL, DD, LL * DD, LL * DD);
    tr_k<<<dim3(8, 32, BB), tb>>>(bV, Vt, LL, DD, LL * DD, LL * DD);
    tr_k<<<dim3(8, 32, BB), tb>>>(bQ, trb, LL, DD, LL * DD, LL * DD);

    // 3. forward band FFT
    fftfwd_k<<<BB * DD, 256>>>(trb, spQ);
    fftfwd_k<<<BB * DD, 256>>>(Kt, spK);
    fftfwd_k<<<BB * DD, 256>>>(Vt, spV);

    // 4. corr mean path (coalesced two-pass reduction; t1 as partials scratch)
    corr_part_k<<<dim3(8, BB), 256>>>(spQ, spK, t1);
    corr_red_k<<<BB, 256>>>(t1, Sb);
    meanv_k<<<dim3(BB, 4), 256>>>(Sb, mv);
    topk_k<<<1, 1024>>>(mv, idxp);
    weights_k<<<BB, 64>>>(mv, idxp, wts);

    // 5. inverse band FFT -> qs, vs (ks not needed: C is a symmetric projection)
    fftinv_k<<<BB * DD, 256>>>(spQ, qsb);
    fftinv_k<<<BB * DD, 256>>>(spV, vsb);

    // 6. spatial attention (tf32 tensor cores; K = raw Kt)
    flash_tc<<<dim3(16, BB * HH), 128, flash_smem>>>(qsb, Kt, vsb, csp);

    // 7. time aggregation + mix
    timeagg_k<<<BB * DD, 256>>>(Vt, wts, idxp, agg);
    mix_k<<<dim3(32, 8, BB), tb>>>(agg, csp, ctx);

    // 8. output projection + residual + LN1 (tf32)
    gemm_tc<2><<<dim3(2, 256), 256>>>(ctx, Wd, bd, x, t1, BB * LL, DD, DD);
    ln_k<<<BB * LL, 256>>>(t1, ln1g, ln1b, hb);

    // 9. FFN + LN2 (tf32)
    gemm_tc<3><<<dim3(2, 256), 256>>>(hb, W1, b1, nullptr, g1b, BB * LL, DD, DD);
    gemm_tc<2><<<dim3(2, 256), 256>>>(g1b, W2, b2, hb, fb, BB * LL, DD, DD);
    ln_k<<<BB * LL, 256>>>(fb, ln2g, ln2b, out);
}

// round 10
// speedup vs baseline: 2.4831x; 1.0846x over previous
#include <cuda_runtime.h>
#include <math.h>
#include <stdint.h>

// ---------------- problem constants ----------------
#define BB 32
#define LL 1024
#define DD 256
#define HH 4
#define EE 64
#define NBAND 308          // f = 205..512
#define F0 205
#define TOPK 34

// ---------------- scratch layout (floats) ----------------
constexpr size_t SZ   = (size_t)BB * LL * DD;        // 8388608
constexpr size_t SPEC = (size_t)BB * DD * 640;       // 5242880 (8192 x 640)

constexpr size_t O_Q    = 0;
constexpr size_t O_K    = O_Q + SZ;
constexpr size_t O_V    = O_K + SZ;
constexpr size_t O_KT   = O_V + SZ;
constexpr size_t O_VT   = O_KT + SZ;
constexpr size_t O_TR   = O_VT + SZ;       // Qt
constexpr size_t O_SPQ  = O_TR + SZ;
constexpr size_t O_SPK  = O_SPQ + SPEC;
constexpr size_t O_SPV  = O_SPK + SPEC;
constexpr size_t O_QS   = O_SPV + SPEC;
constexpr size_t O_VS   = O_QS + SZ;
constexpr size_t O_CSP  = O_VS + SZ;       // ctx spatial (B,L,D)
constexpr size_t O_AGG  = O_CSP + SZ;      // time agg (B,D,L)
constexpr size_t O_CTX  = O_AGG + SZ;      // mixed context (B,L,D)
constexpr size_t O_T1   = O_CTX + SZ;      // also reused as corr partials scratch
constexpr size_t O_H    = O_T1 + SZ;
constexpr size_t O_G1   = O_H + SZ;
constexpr size_t O_F    = O_G1 + SZ;
constexpr size_t O_S    = O_F + SZ;                 // per-batch spectrum sum 32x640
constexpr size_t O_MV   = O_S + (size_t)BB * 640;   // mean_value 32x1024
constexpr size_t O_W    = O_MV + (size_t)BB * LL;   // weights 32x64
constexpr size_t TOTAL  = O_W + (size_t)BB * 64;

__device__ float g_scr[TOTAL + 1024];
__device__ int   g_idx[64];

// ---------------- cp.async helpers ----------------
__device__ __forceinline__ void cpa16(uint32_t saddr, const void* gptr) {
    asm volatile("cp.async.cg.shared.global [%0], [%1], 16;" :: "r"(saddr), "l"(gptr));
}
__device__ __forceinline__ void cpa_commit() {
    asm volatile("cp.async.commit_group;");
}
template<int N>
__device__ __forceinline__ void cpa_wait() {
    asm volatile("cp.async.wait_group %0;" :: "n"(N));
}

// ---------------- tf32 mma helpers ----------------
// Raw fp32 bits: hardware tf32 mma reads the top 19 bits (truncation vs
// cvt.rna — error <= 2x rounding, saves the cvt issue slots entirely).
__device__ __forceinline__ uint32_t f2tf(float f) {
    return __float_as_uint(f);
}
__device__ __forceinline__ void mma_tf32(float* d, const uint32_t* a, const uint32_t* b) {
    asm volatile(
        "mma.sync.aligned.m16n8k8.row.col.f32.tf32.tf32.f32 "
        "{%0,%1,%2,%3}, {%4,%5,%6,%7}, {%8,%9}, {%0,%1,%2,%3};"
        : "+f"(d[0]), "+f"(d[1]), "+f"(d[2]), "+f"(d[3])
        : "r"(a[0]), "r"(a[1]), "r"(a[2]), "r"(a[3]), "r"(b[0]), "r"(b[1]));
}

// ---------------- fast exp on the FMA pipe (no MUFU) ----------------
__device__ __forceinline__ float fexp(float x) {
    x = fmaxf(x, -87.0f);
    float z = x * 1.4426950408889634f;
    float r = rintf(z);
    float f = z - r;
    float p = 1.5403530e-4f;
    p = fmaf(p, f, 1.3333558e-3f);
    p = fmaf(p, f, 9.6181291e-3f);
    p = fmaf(p, f, 5.5504109e-2f);
    p = fmaf(p, f, 2.4022651e-1f);
    p = fmaf(p, f, 6.9314718e-1f);
    p = fmaf(p, f, 1.0f);
    int e = (int)r;
    return __int_as_float((e + 127) << 23) * p;
}

// ---------------- 1024-pt radix-4 FFT machinery ----------------
__device__ __forceinline__ int rev4_10(int l) {
    int b = __brev((unsigned)l) >> 22;               // 10-bit bit reversal
    return ((b & 0x155) << 1) | ((b & 0x2AA) >> 1);  // base-4 digit reversal
}
__device__ __forceinline__ float2 cmul(float2 a, float2 b) {
    return make_float2(a.x * b.x - a.y * b.y, a.x * b.y + a.y * b.x);
}

// 5 radix-4 stages over s[1024]; tw holds 768 direction-signed twiddles.
template<bool INV>
__device__ __forceinline__ void fft4_core(float2* s, const float2* tw, int t) {
#pragma unroll
    for (int m = 0; m < 5; m++) {
        const int L = 1 << (2 * m);
        int pos = t & (L - 1);
        int base = ((t >> (2 * m)) << (2 * m + 2)) | pos;
        int e1 = pos << (2 * (4 - m));
        float2 w1 = tw[e1], w2 = tw[2 * e1], w3 = tw[3 * e1];
        float2 a = s[base];
        float2 b = cmul(s[base + L], w1);
        float2 c = cmul(s[base + 2 * L], w2);
        float2 d = cmul(s[base + 3 * L], w3);
        float2 t0 = make_float2(a.x + c.x, a.y + c.y);
        float2 t1 = make_float2(a.x - c.x, a.y - c.y);
        float2 t2 = make_float2(b.x + d.x, b.y + d.y);
        float2 t3 = make_float2(b.x - d.x, b.y - d.y);
        s[base]         = make_float2(t0.x + t2.x, t0.y + t2.y);
        s[base + 2 * L] = make_float2(t0.x - t2.x, t0.y - t2.y);
        if (!INV) {   // X1 = t1 - i t3, X3 = t1 + i t3
            s[base + L]     = make_float2(t1.x + t3.y, t1.y - t3.x);
            s[base + 3 * L] = make_float2(t1.x - t3.y, t1.y + t3.x);
        } else {      // X1 = t1 + i t3, X3 = t1 - i t3
            s[base + L]     = make_float2(t1.x - t3.y, t1.y + t3.x);
            s[base + 3 * L] = make_float2(t1.x + t3.y, t1.y - t3.x);
        }
        __syncthreads();
    }
}

// Forward: rows of `in` (contiguous 1024 real) -> band bins packed
// spec[row*640 + j] = Re, spec[row*640 + 320 + j] = Im (j = f - 205).
__global__ void __launch_bounds__(256) fftfwd_k(
    const float* __restrict__ in, float* __restrict__ spec)
{
    __shared__ float2 s[1024];
    __shared__ float2 tw[768];
    const int row = blockIdx.x;
    const float* xr = in + (size_t)row * LL;
    const int t = threadIdx.x;

    for (int k = t; k < 768; k += 256) {
        float ang = -6.283185307179586f * (float)k / 1024.0f;
        tw[k] = make_float2(cosf(ang), sinf(ang));
    }
    for (int l = t; l < 1024; l += 256)
        s[rev4_10(l)] = make_float2(xr[l], 0.f);
    __syncthreads();
    fft4_core<false>(s, tw, t);
    for (int j = t; j < NBAND; j += 256) {
        float2 v = s[F0 + j];
        spec[(size_t)row * 640 + j]       = v.x;
        spec[(size_t)row * 640 + 320 + j] = v.y;
    }
}

// Inverse: packed band spectrum -> real signal (length 1024).
__global__ void __launch_bounds__(256) fftinv_k(
    const float* __restrict__ spec, float* __restrict__ outr)
{
    __shared__ float2 s[1024];
    __shared__ float2 tw[768];
    const int row = blockIdx.x;
    const float* sp = spec + (size_t)row * 640;
    const int t = threadIdx.x;

    for (int k = t; k < 768; k += 256) {
        float ang = 6.283185307179586f * (float)k / 1024.0f;
        tw[k] = make_float2(cosf(ang), sinf(ang));
    }
    for (int l = t; l < 1024; l += 256) {
        float2 v = make_float2(0.f, 0.f);
        if (l >= F0 && l <= 512) {
            v.x = sp[l - F0];
            v.y = sp[320 + l - F0];
        } else if (l >= 513 && l <= 1024 - F0) {
            int f = 1024 - l;
            v.x = sp[f - F0];
            v.y = -sp[320 + f - F0];
        }
        s[rev4_10(l)] = v;
    }
    __syncthreads();
    fft4_core<true>(s, tw, t);
    const float sc = 1.0f / 1024.0f;
    for (int l = t; l < 1024; l += 256)
        outr[(size_t)row * LL + l] = s[l].x * sc;
}

// ---------------- tf32 tensor-core GEMM, row-major A --------------
// C[M,N] = A[M,K] @ Bw[K,N] (+epilogue). 256 thr, 8 warps.
// EPI: 1 +bias, 2 +bias+res, 3 +bias then gelu(erf)
template<int EPI>
__global__ void __launch_bounds__(256) gemm_tc(
    const float* __restrict__ A, const float* __restrict__ Bw,
    const float* __restrict__ bias, const float* __restrict__ res,
    float* __restrict__ C, int M, int N, int K)
{
    __shared__ float As[2][128][20];   // [m][k] pad 20
    __shared__ float Bs[2][16][136];   // [k][n] pad 136
    const int bn = blockIdx.x * 128;
    const int bm = blockIdx.y * 128;
    const int tid = threadIdx.x, wid = tid >> 5, lane = tid & 31;
    const int grp = lane >> 2, tig = lane & 3;
    const int wm = (wid & 3) * 32, wn = (wid >> 2) * 64;

    const uint32_t asb = (uint32_t)__cvta_generic_to_shared(&As[0][0][0]);
    const uint32_t bsb = (uint32_t)__cvta_generic_to_shared(&Bs[0][0][0]);
    const int T = K >> 4;

    auto loadA = [&](int st, int k0) {
#pragma unroll
        for (int u = 0; u < 2; u++) {
            int c = tid + u * 256;
            int row = c >> 2, kq = (c & 3) * 4;
            cpa16(asb + (uint32_t)(st * 128 * 20 + row * 20 + kq) * 4,
                  &A[(size_t)(bm + row) * K + k0 + kq]);
        }
    };
    auto loadB = [&](int st, int k0) {
#pragma unroll
        for (int u = 0; u < 2; u++) {
            int c = tid + u * 256;
            int r = c >> 5, col = (c & 31) * 4;
            cpa16(bsb + (uint32_t)(st * 16 * 136 + r * 136 + col) * 4,
                  &Bw[(size_t)(k0 + r) * N + bn + col]);
        }
    };

    loadA(0, 0); loadB(0, 0); cpa_commit();

    float d[2][8][4];
#pragma unroll
    for (int am = 0; am < 2; am++)
#pragma unroll
        for (int an = 0; an < 8; an++)
#pragma unroll
            for (int q = 0; q < 4; q++) d[am][an][q] = 0.f;

    for (int kt = 0; kt < T; kt++) {
        if (kt + 1 < T) {
            loadA((kt + 1) & 1, (kt + 1) << 4);
            loadB((kt + 1) & 1, (kt + 1) << 4);
            cpa_commit();
            cpa_wait<1>();
        } else {
            cpa_wait<0>();
        }
        __syncthreads();
        const int st = kt & 1;
#pragma unroll
        for (int k8 = 0; k8 < 16; k8 += 8) {
            uint32_t a[2][4];
#pragma unroll
            for (int am = 0; am < 2; am++) {
                int mr = wm + am * 16;
                a[am][0] = f2tf(As[st][mr + grp][k8 + tig]);
                a[am][1] = f2tf(As[st][mr + grp + 8][k8 + tig]);
                a[am][2] = f2tf(As[st][mr + grp][k8 + tig + 4]);
                a[am][3] = f2tf(As[st][mr + grp + 8][k8 + tig + 4]);
            }
#pragma unroll
            for (int an = 0; an < 8; an++) {
                uint32_t b[2];
                b[0] = f2tf(Bs[st][k8 + tig][wn + an * 8 + grp]);
                b[1] = f2tf(Bs[st][k8 + tig + 4][wn + an * 8 + grp]);
                mma_tf32(d[0][an], a[0], b);
                mma_tf32(d[1][an], a[1], b);
            }
        }
        __syncthreads();
    }

#pragma unroll
    for (int am = 0; am < 2; am++) {
        int row0 = bm + wm + am * 16 + grp;
#pragma unroll
        for (int an = 0; an < 8; an++) {
            int col = bn + wn + an * 8 + 2 * tig;
            float o0 = d[am][an][0], o1 = d[am][an][1];
            float o2 = d[am][an][2], o3 = d[am][an][3];
            float2 bv = *(const float2*)&bias[col];
            o0 += bv.x; o1 += bv.y; o2 += bv.x; o3 += bv.y;
            if (EPI == 2) {
                float2 r0v = *(const float2*)&res[(size_t)row0 * N + col];
                float2 r1v = *(const float2*)&res[(size_t)(row0 + 8) * N + col];
                o0 += r0v.x; o1 += r0v.y; o2 += r1v.x; o3 += r1v.y;
            }
            if (EPI == 3) {
                o0 = o0 * 0.5f * (1.0f + erff(o0 * 0.70710678118654752f));
                o1 = o1 * 0.5f * (1.0f + erff(o1 * 0.70710678118654752f));
                o2 = o2 * 0.5f * (1.0f + erff(o2 * 0.70710678118654752f));
                o3 = o3 * 0.5f * (1.0f + erff(o3 * 0.70710678118654752f));
            }
            float2 w0; w0.x = o0; w0.y = o1;
            float2 w1; w1.x = o2; w1.y = o3;
            *(float2*)&C[(size_t)row0 * N + col] = w0;
            *(float2*)&C[(size_t)(row0 + 8) * N + col] = w1;
        }
    }
}

// ---------------- generic batched transpose: in[R][Cc] -> out[Cc][R] --------
__global__ void tr_k(const float* __restrict__ in, float* __restrict__ out,
                     int R, int Cc, size_t sIn, size_t sOut)
{
    __shared__ float tile[32][33];
    int b = blockIdx.z;
    const float* I = in + (size_t)b * sIn;
    float* O = out + (size_t)b * sOut;
    int c0 = blockIdx.x * 32, r0 = blockIdx.y * 32;
    int x = threadIdx.x, y = threadIdx.y;
#pragma unroll
    for (int i = 0; i < 32; i += 8)
        tile[y + i][x] = I[(size_t)(r0 + y + i) * Cc + c0 + x];
    __syncthreads();
#pragma unroll
    for (int i = 0; i < 32; i += 8)
        O[(size_t)(c0 + y + i) * R + r0 + x] = tile[x][y + i];
}

// ---------------- corr spectrum sum, pass 1 (coalesced partials) ----------
__global__ void __launch_bounds__(256) corr_part_k(
    const float* __restrict__ Qs, const float* __restrict__ Ks,
    float* __restrict__ Spart)
{
    const int g = blockIdx.x, b = blockIdx.y;
    const int t = threadIdx.x;
    const int j0 = t, j1 = t + 256;
    float re0 = 0.f, im0 = 0.f, re1 = 0.f, im1 = 0.f;
    size_t base = ((size_t)(b * 256 + g * 32)) * 640;
    for (int r = 0; r < 32; r++) {
        size_t row = base + (size_t)r * 640;
        float qr = Qs[row + j0], qi = Qs[row + 320 + j0];
        float kr = Ks[row + j0], ki = Ks[row + 320 + j0];
        re0 += qr * kr + qi * ki;
        im0 += qi * kr - qr * ki;
        if (j1 < NBAND) {
            qr = Qs[row + j1]; qi = Qs[row + 320 + j1];
            kr = Ks[row + j1]; ki = Ks[row + 320 + j1];
            re1 += qr * kr + qi * ki;
            im1 += qi * kr - qr * ki;
        }
    }
    size_t o = (size_t)(b * 8 + g) * 640;
    Spart[o + j0] = re0;
    Spart[o + 320 + j0] = im0;
    if (j1 < NBAND) {
        Spart[o + j1] = re1;
        Spart[o + 320 + j1] = im1;
    } else if (j1 < 320) {
        Spart[o + j1] = 0.f;
        Spart[o + 320 + j1] = 0.f;
    }
}

__global__ void corr_red_k(const float* __restrict__ Spart, float* __restrict__ S)
{
    int b = blockIdx.x, t = threadIdx.x;
    for (int e = t; e < 640; e += 256) {
        float a = 0.f;
#pragma unroll
        for (int g = 0; g < 8; g++)
            a += Spart[(size_t)(b * 8 + g) * 640 + e];
        S[(size_t)b * 640 + e] = a;
    }
}

// ---------------- mean_value[b,t] = (1/256) irfft(S*mask)[t] ----------------
__global__ void __launch_bounds__(256) meanv_k(
    const float* __restrict__ S, float* __restrict__ mv)
{
    int b = blockIdx.x, t = threadIdx.x;
    __shared__ float sre[NBAND], sim[NBAND], tbl[1024];
    for (int j = t; j < NBAND; j += 256) {
        sre[j] = S[(size_t)b * 640 + j];
        sim[j] = S[(size_t)b * 640 + 320 + j];
    }
    for (int m = t; m < 1024; m += 256)
        tbl[m] = cosf(6.283185307179586f * (float)m / 1024.0f);
    __syncthreads();
    int tt = blockIdx.y * 256 + t;
    float acc = sre[NBAND - 1] * ((tt & 1) ? -1.f : 1.f);
    for (int j = 0; j < NBAND - 1; j++) {
        int f = F0 + j;
        int m = (f * tt) & 1023;
        float c = tbl[m];
        float s = tbl[(m + 768) & 1023];
        acc += 2.f * (sre[j] * c - sim[j] * s);
    }
    mv[(size_t)b * 1024 + tt] = acc * (1.0f / (256.0f * 1024.0f));
}

// ---------------- top-k over batch-mean ----------------
__global__ void topk_k(const float* __restrict__ mv, int* __restrict__ idxout)
{
    int t = threadIdx.x;
    __shared__ float vals[1024];
    __shared__ float rv[1024];
    __shared__ int   ri[1024];
    float g = 0.f;
    for (int b = 0; b < BB; b++) g += mv[(size_t)b * 1024 + t];
    vals[t] = g;
    __syncthreads();
    for (int k = 0; k < TOPK; k++) {
        rv[t] = vals[t]; ri[t] = t; __syncthreads();
        for (int s = 512; s > 0; s >>= 1) {
            if (t < s) {
                if (rv[t + s] > rv[t] || (rv[t + s] == rv[t] && ri[t + s] < ri[t])) {
                    rv[t] = rv[t + s]; ri[t] = ri[t + s];
                }
            }
            __syncthreads();
        }
        if (t == 0) { idxout[k] = ri[0]; vals[ri[0]] = -3.4e38f; }
        __syncthreads();
    }
}

// ---------------- per-batch softmax weights ----------------
__global__ void weights_k(const float* __restrict__ mv, const int* __restrict__ idx,
                          float* __restrict__ w)
{
    int b = blockIdx.x, t = threadIdx.x;
    __shared__ float sv[64];
    float v = (t < TOPK) ? mv[(size_t)b * 1024 + idx[t]] : -3.4e38f;
    sv[t] = v; __syncthreads();
    float mx = -3.4e38f;
    for (int i = 0; i < TOPK; i++) mx = fmaxf(mx, sv[i]);
    __syncthreads();
    float e = (t < TOPK) ? expf(v - mx) : 0.f;
    sv[t] = e; __syncthreads();
    float sm = 0.f;
    for (int i = 0; i < TOPK; i++) sm += sv[i];
    if (t < TOPK) w[(size_t)b * 64 + t] = e / sm;
}

// ---------------- flash attention with tf32 tensor cores ----------------
__global__ void __launch_bounds__(128) flash_tc(
    const float* __restrict__ qs, const float* __restrict__ ks,
    const float* __restrict__ vs, float* __restrict__ out)
{
    extern __shared__ float sm[];
    float* Qs = sm;                     // [e][l] stride 72
    float* Ks = Qs + 64 * 72;           // [e][s] stride 72
    float* Vs = Ks + 64 * 72;           // [s][e] stride 72
    float* Ps = Vs + 64 * 72;           // [l][s] stride 68
    const int bh = blockIdx.y, b = bh >> 2, h = bh & 3;
    const int l0 = blockIdx.x * 64;
    const float* Q  = qs + ((size_t)b * DD + h * EE) * LL;
    const float* Kp = ks + ((size_t)b * DD + h * EE) * LL;
    const float* V  = vs + ((size_t)b * DD + h * EE) * LL;
    const int tid = threadIdx.x, wid = tid >> 5, lane = tid & 31;
    const int grp = lane >> 2, tig = lane & 3;
    const int lw = wid * 16;

    {
        int e = tid >> 1;
        int cb = (tid & 1) * 32;
#pragma unroll
        for (int w = 0; w < 8; w++) {
            int col = cb + w * 4;
            *(float4*)&Qs[e * 72 + col] = *(const float4*)&Q[(size_t)e * LL + l0 + col];
        }
    }

    float m0 = -1e30f, m1 = -1e30f, li0 = 0.f, li1 = 0.f;
    float o[8][4];
#pragma unroll
    for (int en = 0; en < 8; en++)
#pragma unroll
        for (int q = 0; q < 4; q++) o[en][q] = 0.f;

    for (int s0 = 0; s0 < LL; s0 += 64) {
        __syncthreads();
        {
            int e = tid >> 1;
            int cb = (tid & 1) * 32;
#pragma unroll
            for (int w = 0; w < 8; w++) {
                int col = cb + w * 4;
                *(float4*)&Ks[e * 72 + col] = *(const float4*)&Kp[(size_t)e * LL + s0 + col];
                float4 vv = *(const float4*)&V[(size_t)e * LL + s0 + col];
                Vs[(col + 0) * 72 + e] = vv.x;
                Vs[(col + 1) * 72 + e] = vv.y;
                Vs[(col + 2) * 72 + e] = vv.z;
                Vs[(col + 3) * 72 + e] = vv.w;
            }
        }
        __syncthreads();

        float sa[8][4];
#pragma unroll
        for (int an = 0; an < 8; an++)
#pragma unroll
            for (int q = 0; q < 4; q++) sa[an][q] = 0.f;
#pragma unroll
        for (int k8 = 0; k8 < 64; k8 += 8) {
            uint32_t a[4];
            a[0] = f2tf(Qs[(k8 + tig) * 72 + lw + grp]);
            a[1] = f2tf(Qs[(k8 + tig) * 72 + lw + grp + 8]);
            a[2] = f2tf(Qs[(k8 + tig + 4) * 72 + lw + grp]);
            a[3] = f2tf(Qs[(k8 + tig + 4) * 72 + lw + grp + 8]);
#pragma unroll
            for (int an = 0; an < 8; an++) {
                uint32_t bb[2];
                bb[0] = f2tf(Ks[(k8 + tig) * 72 + an * 8 + grp]);
                bb[1] = f2tf(Ks[(k8 + tig + 4) * 72 + an * 8 + grp]);
                mma_tf32(sa[an], a, bb);
            }
        }

        float mx0 = -1e30f, mx1 = -1e30f;
#pragma unroll
        for (int an = 0; an < 8; an++) {
#pragma unroll
            for (int q = 0; q < 4; q++) sa[an][q] *= 0.125f;
            mx0 = fmaxf(mx0, fmaxf(sa[an][0], sa[an][1]));
            mx1 = fmaxf(mx1, fmaxf(sa[an][2], sa[an][3]));
        }
        mx0 = fmaxf(mx0, __shfl_xor_sync(0xffffffffu, mx0, 1));
        mx0 = fmaxf(mx0, __shfl_xor_sync(0xffffffffu, mx0, 2));
        mx1 = fmaxf(mx1, __shfl_xor_sync(0xffffffffu, mx1, 1));
        mx1 = fmaxf(mx1, __shfl_xor_sync(0xffffffffu, mx1, 2));
        float mn0 = fmaxf(m0, mx0), mn1 = fmaxf(m1, mx1);
        float al0 = fexp(m0 - mn0), al1 = fexp(m1 - mn1);
        m0 = mn0; m1 = mn1;
        float ps0 = 0.f, ps1 = 0.f;
#pragma unroll
        for (int an = 0; an < 8; an++) {
            float p0 = fexp(sa[an][0] - mn0);
            float p1 = fexp(sa[an][1] - mn0);
            float p2 = fexp(sa[an][2] - mn1);
            float p3 = fexp(sa[an][3] - mn1);
            ps0 += p0 + p1; ps1 += p2 + p3;
            float2 w0; w0.x = p0; w0.y = p1;
            float2 w1; w1.x = p2; w1.y = p3;
            *(float2*)&Ps[(lw + grp) * 68 + an * 8 + 2 * tig] = w0;
            *(float2*)&Ps[(lw + grp + 8) * 68 + an * 8 + 2 * tig] = w1;
        }
        ps0 += __shfl_xor_sync(0xffffffffu, ps0, 1);
        ps0 += __shfl_xor_sync(0xffffffffu, ps0, 2);
        ps1 += __shfl_xor_sync(0xffffffffu, ps1, 1);
        ps1 += __shfl_xor_sync(0xffffffffu, ps1, 2);
        li0 = li0 * al0 + ps0;
        li1 = li1 * al1 + ps1;
#pragma unroll
        for (int en = 0; en < 8; en++) {
            o[en][0] *= al0; o[en][1] *= al0;
            o[en][2] *= al1; o[en][3] *= al1;
        }
        __syncwarp();

#pragma unroll
        for (int s8 = 0; s8 < 64; s8 += 8) {
            uint32_t a[4];
            a[0] = f2tf(Ps[(lw + grp) * 68 + s8 + tig]);
            a[1] = f2tf(Ps[(lw + grp + 8) * 68 + s8 + tig]);
            a[2] = f2tf(Ps[(lw + grp) * 68 + s8 + tig + 4]);
            a[3] = f2tf(Ps[(lw + grp + 8) * 68 + s8 + tig + 4]);
#pragma unroll
            for (int en = 0; en < 8; en++) {
                uint32_t bb[2];
                bb[0] = f2tf(Vs[(s8 + tig) * 72 + en * 8 + grp]);
                bb[1] = f2tf(Vs[(s8 + tig + 4) * 72 + en * 8 + grp]);
                mma_tf32(o[en], a, bb);
            }
        }
    }

    float inv0 = 1.0f / li0, inv1 = 1.0f / li1;
#pragma unroll
    for (int en = 0; en < 8; en++) {
        int col = h * EE + en * 8 + 2 * tig;
        float2 w0; w0.x = o[en][0] * inv0; w0.y = o[en][1] * inv0;
        float2 w1; w1.x = o[en][2] * inv1; w1.y = o[en][3] * inv1;
        *(float2*)&out[((size_t)b * LL + l0 + lw + grp) * DD + col] = w0;
        *(float2*)&out[((size_t)b * LL + l0 + lw + grp + 8) * DD + col] = w1;
    }
}

// ---------------- time delay aggregation (B,D,L) ----------------
__global__ void timeagg_k(const float* __restrict__ Vt, const float* __restrict__ w,
                          const int* __restrict__ idx, float* __restrict__ agg)
{
    int bd = blockIdx.x;
    int b = bd >> 8;
    __shared__ float row[1024];
    __shared__ float ws[TOPK];
    __shared__ int   is[TOPK];
    int t = threadIdx.x;
    for (int l = t; l < 1024; l += 256) row[l] = Vt[(size_t)bd * 1024 + l];
    if (t < TOPK) { ws[t] = w[(size_t)b * 64 + t]; is[t] = idx[t]; }
    __syncthreads();
    for (int l = t; l < 1024; l += 256) {
        float a = 0.f;
#pragma unroll
        for (int k = 0; k < TOPK; k++) a = fmaf(ws[k], row[(l + is[k]) & 1023], a);
        agg[(size_t)bd * 1024 + l] = a;
    }
}

// ---------------- context = 0.9*agg^T + 0.1*ctx_sp ----------------
__global__ void mix_k(const float* __restrict__ agg, const float* __restrict__ csp,
                      float* __restrict__ ctx)
{
    __shared__ float tile[32][33];
    int b = blockIdx.z;
    int l0 = blockIdx.x * 32, d0 = blockIdx.y * 32;
    int x = threadIdx.x, y = threadIdx.y;
#pragma unroll
    for (int i = 0; i < 32; i += 8)
        tile[y + i][x] = agg[((size_t)b * DD + d0 + y + i) * LL + l0 + x];
    __syncthreads();
#pragma unroll
    for (int i = 0; i < 32; i += 8) {
        size_t o = ((size_t)b * LL + l0 + y + i) * DD + d0 + x;
        ctx[o] = 0.9f * tile[x][y + i] + 0.1f * csp[o];
    }
}

// ---------------- LayerNorm over D=256 ----------------
__global__ void ln_k(const float* __restrict__ in, const float* __restrict__ g,
                     const float* __restrict__ b, float* __restrict__ out)
{
    size_t row = blockIdx.x;
    int t = threadIdx.x;
    float v = in[row * DD + t];
    __shared__ float red[256];
    red[t] = v; __syncthreads();
    for (int s = 128; s > 0; s >>= 1) { if (t < s) red[t] += red[t + s]; __syncthreads(); }
    float m = red[0] * (1.0f / 256.0f);
    __syncthreads();
    float d = v - m;
    red[t] = d * d; __syncthreads();
    for (int s = 128; s > 0; s >>= 1) { if (t < s) red[t] += red[t + s]; __syncthreads(); }
    float var = red[0] * (1.0f / 256.0f);
    out[row * DD + t] = d * rsqrtf(var + 1e-8f) * g[t] + b[t];
}

// ---------------- launch ----------------
extern "C" void kernel_launch(void* const* d_in, const int* in_sizes, int n_in,
                              void* d_out, int out_size)
{
    const float* x   = (const float*)d_in[0];
    const float* Wq  = (const float*)d_in[1];
    const float* bq  = (const float*)d_in[2];
    const float* Wk  = (const float*)d_in[3];
    const float* bk  = (const float*)d_in[4];
    const float* Wv  = (const float*)d_in[5];
    const float* bv  = (const float*)d_in[6];
    const float* Wd  = (const float*)d_in[7];
    const float* bd  = (const float*)d_in[8];
    const float* ln1g = (const float*)d_in[9];
    const float* ln1b = (const float*)d_in[10];
    const float* W1  = (const float*)d_in[11];
    const float* b1  = (const float*)d_in[12];
    const float* W2  = (const float*)d_in[13];
    const float* b2  = (const float*)d_in[14];
    const float* ln2g = (const float*)d_in[15];
    const float* ln2b = (const float*)d_in[16];
    float* out = (float*)d_out;

    float* scr = nullptr;
    int* idxp = nullptr;
    cudaGetSymbolAddress((void**)&scr, g_scr);
    cudaGetSymbolAddress((void**)&idxp, g_idx);

    float* bQ   = scr + O_Q;   float* bK  = scr + O_K;   float* bV  = scr + O_V;
    float* Kt   = scr + O_KT;  float* Vt  = scr + O_VT;  float* trb = scr + O_TR;
    float* spQ  = scr + O_SPQ; float* spK = scr + O_SPK; float* spV = scr + O_SPV;
    float* qsb  = scr + O_QS;  float* vsb = scr + O_VS;
    float* csp  = scr + O_CSP; float* agg = scr + O_AGG; float* ctx = scr + O_CTX;
    float* t1   = scr + O_T1;  float* hb  = scr + O_H;
    float* g1b  = scr + O_G1;  float* fb  = scr + O_F;
    float* Sb   = scr + O_S;   float* mv  = scr + O_MV;  float* wts = scr + O_W;

    const int flash_smem = (3 * 64 * 72 + 64 * 68) * sizeof(float);   // 72704 B
    cudaFuncSetAttribute(flash_tc, cudaFuncAttributeMaxDynamicSharedMemorySize, flash_smem);

    const dim3 tb(32, 8);

    // 1. QKV projections (tf32 tensor cores, row-major x directly)
    gemm_tc<1><<<dim3(2, 256), 256>>>(x, Wq, bq, nullptr, bQ, BB * LL, DD, DD);
    gemm_tc<1><<<dim3(2, 256), 256>>>(x, Wk, bk, nullptr, bK, BB * LL, DD, DD);
    gemm_tc<1><<<dim3(2, 256), 256>>>(x, Wv, bv, nullptr, bV, BB * LL, DD, DD);

    // 2. transposes to (B,D,L): Kt/Vt persist; Qt in trb
    tr_k<<<dim3(8, 32, BB), tb>>>(bK, Kt, LL, DD, LL * DD, LL * DD);
    tr_k<<<dim3(8, 32, BB), tb>>>(bV, Vt, LL, DD, LL * DD, LL * DD);
    tr_k<<<dim3(8, 32, BB), tb>>>(bQ, trb, LL, DD, LL * DD, LL * DD);

    // 3. forward band FFT (radix-4)
    fftfwd_k<<<BB * DD, 256>>>(trb, spQ);
    fftfwd_k<<<BB * DD, 256>>>(Kt, spK);
    fftfwd_k<<<BB * DD, 256>>>(Vt, spV);

    // 4. corr mean path
    corr_part_k<<<dim3(8, BB), 256>>>(spQ, spK, t1);
    corr_red_k<<<BB, 256>>>(t1, Sb);
    meanv_k<<<dim3(BB, 4), 256>>>(Sb, mv);
    topk_k<<<1, 1024>>>(mv, idxp);
    weights_k<<<BB, 64>>>(mv, idxp, wts);

    // 5. inverse band FFT -> qs, vs (ks not needed: C is a symmetric projection)
    fftinv_k<<<BB * DD, 256>>>(spQ, qsb);
    fftinv_k<<<BB * DD, 256>>>(spV, vsb);

    // 6. spatial attention (tf32 tensor cores; K = raw Kt)
    flash_tc<<<dim3(16, BB * HH), 128, flash_smem>>>(qsb, Kt, vsb, csp);

    // 7. time aggregation + mix
    timeagg_k<<<BB * DD, 256>>>(Vt, wts, idxp, agg);
    mix_k<<<dim3(32, 8, BB), tb>>>(agg, csp, ctx);

    // 8. output projection + residual + LN1 (tf32)
    gemm_tc<2><<<dim3(2, 256), 256>>>(ctx, Wd, bd, x, t1, BB * LL, DD, DD);
    ln_k<<<BB * LL, 256>>>(t1, ln1g, ln1b, hb);

    // 9. FFN + LN2 (tf32)
    gemm_tc<3><<<dim3(2, 256), 256>>>(hb, W1, b1, nullptr, g1b, BB * LL, DD, DD);
    gemm_tc<2><<<dim3(2, 256), 256>>>(g1b, W2, b2, hb, fb, BB * LL, DD, DD);
    ln_k<<<BB * LL, 256>>>(fb, ln2g, ln2b, out);
}

// round 11
// speedup vs baseline: 2.9102x; 1.1720x over previous
#include <cuda_runtime.h>
#include <math.h>
#include <stdint.h>

// ---------------- problem constants ----------------
#define BB 32
#define LL 1024
#define DD 256
#define HH 4
#define EE 64
#define NBAND 308          // f = 205..512
#define F0 205
#define TOPK 34

// ---------------- scratch layout (floats) ----------------
constexpr size_t SZ   = (size_t)BB * LL * DD;        // 8388608
constexpr size_t SPEC = (size_t)BB * DD * 640;       // 5242880 (8192 x 640)

constexpr size_t O_Q    = 0;
constexpr size_t O_K    = O_Q + SZ;
constexpr size_t O_V    = O_K + SZ;
constexpr size_t O_KT   = O_V + SZ;
constexpr size_t O_VT   = O_KT + SZ;
constexpr size_t O_TR   = O_VT + SZ;       // Qt
constexpr size_t O_SPQ  = O_TR + SZ;
constexpr size_t O_SPK  = O_SPQ + SPEC;
constexpr size_t O_SPV  = O_SPK + SPEC;
constexpr size_t O_QS   = O_SPV + SPEC;
constexpr size_t O_VS   = O_QS + SZ;
constexpr size_t O_CSP  = O_VS + SZ;       // ctx spatial (B,L,D)
constexpr size_t O_AGG  = O_CSP + SZ;      // time agg (B,D,L)
constexpr size_t O_CTX  = O_AGG + SZ;      // mixed context (B,L,D)
constexpr size_t O_T1   = O_CTX + SZ;      // also reused as corr partials scratch
constexpr size_t O_H    = O_T1 + SZ;
constexpr size_t O_G1   = O_H + SZ;
constexpr size_t O_F    = O_G1 + SZ;
constexpr size_t O_S    = O_F + SZ;                 // per-batch spectrum sum 32x640
constexpr size_t O_MV   = O_S + (size_t)BB * 640;   // mean_value 32x1024
constexpr size_t O_W    = O_MV + (size_t)BB * LL;   // weights 32x64
constexpr size_t TOTAL  = O_W + (size_t)BB * 64;

__device__ float g_scr[TOTAL + 1024];
__device__ int   g_idx[64];

// ---------------- cp.async helpers ----------------
__device__ __forceinline__ void cpa16(uint32_t saddr, const void* gptr) {
    asm volatile("cp.async.cg.shared.global [%0], [%1], 16;" :: "r"(saddr), "l"(gptr));
}
__device__ __forceinline__ void cpa_commit() {
    asm volatile("cp.async.commit_group;");
}
template<int N>
__device__ __forceinline__ void cpa_wait() {
    asm volatile("cp.async.wait_group %0;" :: "n"(N));
}

// ---------------- tf32 mma helpers ----------------
__device__ __forceinline__ uint32_t f2tf(float f) {
    return __float_as_uint(f);   // hardware tf32 mma truncates to top 19 bits
}
__device__ __forceinline__ void mma_tf32(float* d, const uint32_t* a, const uint32_t* b) {
    asm volatile(
        "mma.sync.aligned.m16n8k8.row.col.f32.tf32.tf32.f32 "
        "{%0,%1,%2,%3}, {%4,%5,%6,%7}, {%8,%9}, {%0,%1,%2,%3};"
        : "+f"(d[0]), "+f"(d[1]), "+f"(d[2]), "+f"(d[3])
        : "r"(a[0]), "r"(a[1]), "r"(a[2]), "r"(a[3]), "r"(b[0]), "r"(b[1]));
}

// ---------------- fast exp on the FMA pipe (no MUFU) ----------------
__device__ __forceinline__ float fexp(float x) {
    x = fmaxf(x, -87.0f);
    float z = x * 1.4426950408889634f;
    float r = rintf(z);
    float f = z - r;
    float p = 1.5403530e-4f;
    p = fmaf(p, f, 1.3333558e-3f);
    p = fmaf(p, f, 9.6181291e-3f);
    p = fmaf(p, f, 5.5504109e-2f);
    p = fmaf(p, f, 2.4022651e-1f);
    p = fmaf(p, f, 6.9314718e-1f);
    p = fmaf(p, f, 1.0f);
    int e = (int)r;
    return __int_as_float((e + 127) << 23) * p;
}

// ---------------- 1024-pt radix-4 FFT machinery ----------------
__device__ __forceinline__ int rev4_10(int l) {
    int b = __brev((unsigned)l) >> 22;
    return ((b & 0x155) << 1) | ((b & 0x2AA) >> 1);
}
__device__ __forceinline__ float2 cmul(float2 a, float2 b) {
    return make_float2(a.x * b.x - a.y * b.y, a.x * b.y + a.y * b.x);
}

template<bool INV>
__device__ __forceinline__ void fft4_core(float2* s, const float2* tw, int t) {
#pragma unroll
    for (int m = 0; m < 5; m++) {
        const int L = 1 << (2 * m);
        int pos = t & (L - 1);
        int base = ((t >> (2 * m)) << (2 * m + 2)) | pos;
        int e1 = pos << (2 * (4 - m));
        float2 w1 = tw[e1], w2 = tw[2 * e1], w3 = tw[3 * e1];
        float2 a = s[base];
        float2 b = cmul(s[base + L], w1);
        float2 c = cmul(s[base + 2 * L], w2);
        float2 d = cmul(s[base + 3 * L], w3);
        float2 t0 = make_float2(a.x + c.x, a.y + c.y);
        float2 t1 = make_float2(a.x - c.x, a.y - c.y);
        float2 t2 = make_float2(b.x + d.x, b.y + d.y);
        float2 t3 = make_float2(b.x - d.x, b.y - d.y);
        s[base]         = make_float2(t0.x + t2.x, t0.y + t2.y);
        s[base + 2 * L] = make_float2(t0.x - t2.x, t0.y - t2.y);
        if (!INV) {
            s[base + L]     = make_float2(t1.x + t3.y, t1.y - t3.x);
            s[base + 3 * L] = make_float2(t1.x - t3.y, t1.y + t3.x);
        } else {
            s[base + L]     = make_float2(t1.x - t3.y, t1.y + t3.x);
            s[base + 3 * L] = make_float2(t1.x + t3.y, t1.y - t3.x);
        }
        __syncthreads();
    }
}

__global__ void __launch_bounds__(256) fftfwd_k(
    const float* __restrict__ in, float* __restrict__ spec)
{
    __shared__ float2 s[1024];
    __shared__ float2 tw[768];
    const int row = blockIdx.x;
    const float* xr = in + (size_t)row * LL;
    const int t = threadIdx.x;

    for (int k = t; k < 768; k += 256) {
        float ang = -6.283185307179586f * (float)k / 1024.0f;
        tw[k] = make_float2(cosf(ang), sinf(ang));
    }
    for (int l = t; l < 1024; l += 256)
        s[rev4_10(l)] = make_float2(xr[l], 0.f);
    __syncthreads();
    fft4_core<false>(s, tw, t);
    for (int j = t; j < NBAND; j += 256) {
        float2 v = s[F0 + j];
        spec[(size_t)row * 640 + j]       = v.x;
        spec[(size_t)row * 640 + 320 + j] = v.y;
    }
}

__global__ void __launch_bounds__(256) fftinv_k(
    const float* __restrict__ spec, float* __restrict__ outr)
{
    __shared__ float2 s[1024];
    __shared__ float2 tw[768];
    const int row = blockIdx.x;
    const float* sp = spec + (size_t)row * 640;
    const int t = threadIdx.x;

    for (int k = t; k < 768; k += 256) {
        float ang = 6.283185307179586f * (float)k / 1024.0f;
        tw[k] = make_float2(cosf(ang), sinf(ang));
    }
    for (int l = t; l < 1024; l += 256) {
        float2 v = make_float2(0.f, 0.f);
        if (l >= F0 && l <= 512) {
            v.x = sp[l - F0];
            v.y = sp[320 + l - F0];
        } else if (l >= 513 && l <= 1024 - F0) {
            int f = 1024 - l;
            v.x = sp[f - F0];
            v.y = -sp[320 + f - F0];
        }
        s[rev4_10(l)] = v;
    }
    __syncthreads();
    fft4_core<true>(s, tw, t);
    const float sc = 1.0f / 1024.0f;
    for (int l = t; l < 1024; l += 256)
        outr[(size_t)row * LL + l] = s[l].x * sc;
}

// ---------------- tf32 tensor-core GEMM, row-major A --------------
template<int EPI>
__global__ void __launch_bounds__(256) gemm_tc(
    const float* __restrict__ A, const float* __restrict__ Bw,
    const float* __restrict__ bias, const float* __restrict__ res,
    float* __restrict__ C, int M, int N, int K)
{
    __shared__ float As[2][128][20];
    __shared__ float Bs[2][16][136];
    const int bn = blockIdx.x * 128;
    const int bm = blockIdx.y * 128;
    const int tid = threadIdx.x, wid = tid >> 5, lane = tid & 31;
    const int grp = lane >> 2, tig = lane & 3;
    const int wm = (wid & 3) * 32, wn = (wid >> 2) * 64;

    const uint32_t asb = (uint32_t)__cvta_generic_to_shared(&As[0][0][0]);
    const uint32_t bsb = (uint32_t)__cvta_generic_to_shared(&Bs[0][0][0]);
    const int T = K >> 4;

    auto loadA = [&](int st, int k0) {
#pragma unroll
        for (int u = 0; u < 2; u++) {
            int c = tid + u * 256;
            int row = c >> 2, kq = (c & 3) * 4;
            cpa16(asb + (uint32_t)(st * 128 * 20 + row * 20 + kq) * 4,
                  &A[(size_t)(bm + row) * K + k0 + kq]);
        }
    };
    auto loadB = [&](int st, int k0) {
#pragma unroll
        for (int u = 0; u < 2; u++) {
            int c = tid + u * 256;
            int r = c >> 5, col = (c & 31) * 4;
            cpa16(bsb + (uint32_t)(st * 16 * 136 + r * 136 + col) * 4,
                  &Bw[(size_t)(k0 + r) * N + bn + col]);
        }
    };

    loadA(0, 0); loadB(0, 0); cpa_commit();

    float d[2][8][4];
#pragma unroll
    for (int am = 0; am < 2; am++)
#pragma unroll
        for (int an = 0; an < 8; an++)
#pragma unroll
            for (int q = 0; q < 4; q++) d[am][an][q] = 0.f;

    for (int kt = 0; kt < T; kt++) {
        if (kt + 1 < T) {
            loadA((kt + 1) & 1, (kt + 1) << 4);
            loadB((kt + 1) & 1, (kt + 1) << 4);
            cpa_commit();
            cpa_wait<1>();
        } else {
            cpa_wait<0>();
        }
        __syncthreads();
        const int st = kt & 1;
#pragma unroll
        for (int k8 = 0; k8 < 16; k8 += 8) {
            uint32_t a[2][4];
#pragma unroll
            for (int am = 0; am < 2; am++) {
                int mr = wm + am * 16;
                a[am][0] = f2tf(As[st][mr + grp][k8 + tig]);
                a[am][1] = f2tf(As[st][mr + grp + 8][k8 + tig]);
                a[am][2] = f2tf(As[st][mr + grp][k8 + tig + 4]);
                a[am][3] = f2tf(As[st][mr + grp + 8][k8 + tig + 4]);
            }
#pragma unroll
            for (int an = 0; an < 8; an++) {
                uint32_t b[2];
                b[0] = f2tf(Bs[st][k8 + tig][wn + an * 8 + grp]);
                b[1] = f2tf(Bs[st][k8 + tig + 4][wn + an * 8 + grp]);
                mma_tf32(d[0][an], a[0], b);
                mma_tf32(d[1][an], a[1], b);
            }
        }
        __syncthreads();
    }

#pragma unroll
    for (int am = 0; am < 2; am++) {
        int row0 = bm + wm + am * 16 + grp;
#pragma unroll
        for (int an = 0; an < 8; an++) {
            int col = bn + wn + an * 8 + 2 * tig;
            float o0 = d[am][an][0], o1 = d[am][an][1];
            float o2 = d[am][an][2], o3 = d[am][an][3];
            float2 bv = *(const float2*)&bias[col];
            o0 += bv.x; o1 += bv.y; o2 += bv.x; o3 += bv.y;
            if (EPI == 2) {
                float2 r0v = *(const float2*)&res[(size_t)row0 * N + col];
                float2 r1v = *(const float2*)&res[(size_t)(row0 + 8) * N + col];
                o0 += r0v.x; o1 += r0v.y; o2 += r1v.x; o3 += r1v.y;
            }
            if (EPI == 3) {
                o0 = o0 * 0.5f * (1.0f + erff(o0 * 0.70710678118654752f));
                o1 = o1 * 0.5f * (1.0f + erff(o1 * 0.70710678118654752f));
                o2 = o2 * 0.5f * (1.0f + erff(o2 * 0.70710678118654752f));
                o3 = o3 * 0.5f * (1.0f + erff(o3 * 0.70710678118654752f));
            }
            float2 w0; w0.x = o0; w0.y = o1;
            float2 w1; w1.x = o2; w1.y = o3;
            *(float2*)&C[(size_t)row0 * N + col] = w0;
            *(float2*)&C[(size_t)(row0 + 8) * N + col] = w1;
        }
    }
}

// ---------------- generic batched transpose ----------------
__global__ void tr_k(const float* __restrict__ in, float* __restrict__ out,
                     int R, int Cc, size_t sIn, size_t sOut)
{
    __shared__ float tile[32][33];
    int b = blockIdx.z;
    const float* I = in + (size_t)b * sIn;
    float* O = out + (size_t)b * sOut;
    int c0 = blockIdx.x * 32, r0 = blockIdx.y * 32;
    int x = threadIdx.x, y = threadIdx.y;
#pragma unroll
    for (int i = 0; i < 32; i += 8)
        tile[y + i][x] = I[(size_t)(r0 + y + i) * Cc + c0 + x];
    __syncthreads();
#pragma unroll
    for (int i = 0; i < 32; i += 8)
        O[(size_t)(c0 + y + i) * R + r0 + x] = tile[x][y + i];
}

// ---------------- corr spectrum sum, pass 1 ----------
__global__ void __launch_bounds__(256) corr_part_k(
    const float* __restrict__ Qs, const float* __restrict__ Ks,
    float* __restrict__ Spart)
{
    const int g = blockIdx.x, b = blockIdx.y;
    const int t = threadIdx.x;
    const int j0 = t, j1 = t + 256;
    float re0 = 0.f, im0 = 0.f, re1 = 0.f, im1 = 0.f;
    size_t base = ((size_t)(b * 256 + g * 32)) * 640;
    for (int r = 0; r < 32; r++) {
        size_t row = base + (size_t)r * 640;
        float qr = Qs[row + j0], qi = Qs[row + 320 + j0];
        float kr = Ks[row + j0], ki = Ks[row + 320 + j0];
        re0 += qr * kr + qi * ki;
        im0 += qi * kr - qr * ki;
        if (j1 < NBAND) {
            qr = Qs[row + j1]; qi = Qs[row + 320 + j1];
            kr = Ks[row + j1]; ki = Ks[row + 320 + j1];
            re1 += qr * kr + qi * ki;
            im1 += qi * kr - qr * ki;
        }
    }
    size_t o = (size_t)(b * 8 + g) * 640;
    Spart[o + j0] = re0;
    Spart[o + 320 + j0] = im0;
    if (j1 < NBAND) {
        Spart[o + j1] = re1;
        Spart[o + 320 + j1] = im1;
    } else if (j1 < 320) {
        Spart[o + j1] = 0.f;
        Spart[o + 320 + j1] = 0.f;
    }
}

__global__ void corr_red_k(const float* __restrict__ Spart, float* __restrict__ S)
{
    int b = blockIdx.x, t = threadIdx.x;
    for (int e = t; e < 640; e += 256) {
        float a = 0.f;
#pragma unroll
        for (int g = 0; g < 8; g++)
            a += Spart[(size_t)(b * 8 + g) * 640 + e];
        S[(size_t)b * 640 + e] = a;
    }
}

// ---------------- mean_value ----------------
__global__ void __launch_bounds__(256) meanv_k(
    const float* __restrict__ S, float* __restrict__ mv)
{
    int b = blockIdx.x, t = threadIdx.x;
    __shared__ float sre[NBAND], sim[NBAND], tbl[1024];
    for (int j = t; j < NBAND; j += 256) {
        sre[j] = S[(size_t)b * 640 + j];
        sim[j] = S[(size_t)b * 640 + 320 + j];
    }
    for (int m = t; m < 1024; m += 256)
        tbl[m] = cosf(6.283185307179586f * (float)m / 1024.0f);
    __syncthreads();
    int tt = blockIdx.y * 256 + t;
    float acc = sre[NBAND - 1] * ((tt & 1) ? -1.f : 1.f);
    for (int j = 0; j < NBAND - 1; j++) {
        int f = F0 + j;
        int m = (f * tt) & 1023;
        float c = tbl[m];
        float s = tbl[(m + 768) & 1023];
        acc += 2.f * (sre[j] * c - sim[j] * s);
    }
    mv[(size_t)b * 1024 + tt] = acc * (1.0f / (256.0f * 1024.0f));
}

// ---------------- top-k over batch-mean ----------------
__global__ void topk_k(const float* __restrict__ mv, int* __restrict__ idxout)
{
    int t = threadIdx.x;
    __shared__ float vals[1024];
    __shared__ float rv[1024];
    __shared__ int   ri[1024];
    float g = 0.f;
    for (int b = 0; b < BB; b++) g += mv[(size_t)b * 1024 + t];
    vals[t] = g;
    __syncthreads();
    for (int k = 0; k < TOPK; k++) {
        rv[t] = vals[t]; ri[t] = t; __syncthreads();
        for (int s = 512; s > 0; s >>= 1) {
            if (t < s) {
                if (rv[t + s] > rv[t] || (rv[t + s] == rv[t] && ri[t + s] < ri[t])) {
                    rv[t] = rv[t + s]; ri[t] = ri[t + s];
                }
            }
            __syncthreads();
        }
        if (t == 0) { idxout[k] = ri[0]; vals[ri[0]] = -3.4e38f; }
        __syncthreads();
    }
}

// ---------------- per-batch softmax weights ----------------
__global__ void weights_k(const float* __restrict__ mv, const int* __restrict__ idx,
                          float* __restrict__ w)
{
    int b = blockIdx.x, t = threadIdx.x;
    __shared__ float sv[64];
    float v = (t < TOPK) ? mv[(size_t)b * 1024 + idx[t]] : -3.4e38f;
    sv[t] = v; __syncthreads();
    float mx = -3.4e38f;
    for (int i = 0; i < TOPK; i++) mx = fmaxf(mx, sv[i]);
    __syncthreads();
    float e = (t < TOPK) ? expf(v - mx) : 0.f;
    sv[t] = e; __syncthreads();
    float sm = 0.f;
    for (int i = 0; i < TOPK; i++) sm += sv[i];
    if (t < TOPK) w[(size_t)b * 64 + t] = e / sm;
}

// ---------------- flash attention, tf32 tensor cores, 2 m-atoms/warp -------
// 128 threads = 4 warps; warp owns 32 l-rows (2 m16 atoms) x 64 s-cols.
// Block l-tile = 128 rows; grid = (LL/128, B*H).
__global__ void __launch_bounds__(128) flash_tc(
    const float* __restrict__ qs, const float* __restrict__ ks,
    const float* __restrict__ vs, float* __restrict__ out)
{
    extern __shared__ float sm[];
    float* Qs = sm;                     // [e][l] stride 136 (l = 0..127)
    float* Ks = Qs + 64 * 136;          // [e][s] stride 72
    float* Vs = Ks + 64 * 72;           // [s][e] stride 72
    float* Ps = Vs + 64 * 72;           // [l][s] stride 68 (l = 0..127)
    const int bh = blockIdx.y, b = bh >> 2, h = bh & 3;
    const int l0 = blockIdx.x * 128;
    const float* Q  = qs + ((size_t)b * DD + h * EE) * LL;
    const float* Kp = ks + ((size_t)b * DD + h * EE) * LL;
    const float* V  = vs + ((size_t)b * DD + h * EE) * LL;
    const int tid = threadIdx.x, wid = tid >> 5, lane = tid & 31;
    const int grp = lane >> 2, tig = lane & 3;
    const int lw = wid * 32;

    // load Q tile once: 64 e-rows x 128 l-cols
    {
        int e = tid >> 1;
        int cb = (tid & 1) * 64;
#pragma unroll
        for (int w = 0; w < 16; w++) {
            int col = cb + w * 4;
            *(float4*)&Qs[e * 136 + col] = *(const float4*)&Q[(size_t)e * LL + l0 + col];
        }
    }

    float mI[2][2], li[2][2];
#pragma unroll
    for (int am = 0; am < 2; am++) {
        mI[am][0] = -1e30f; mI[am][1] = -1e30f;
        li[am][0] = 0.f; li[am][1] = 0.f;
    }
    float o[2][8][4];
#pragma unroll
    for (int am = 0; am < 2; am++)
#pragma unroll
        for (int en = 0; en < 8; en++)
#pragma unroll
            for (int q = 0; q < 4; q++) o[am][en][q] = 0.f;

    for (int s0 = 0; s0 < LL; s0 += 64) {
        __syncthreads();
        {
            int e = tid >> 1;
            int cb = (tid & 1) * 32;
#pragma unroll
            for (int w = 0; w < 8; w++) {
                int col = cb + w * 4;
                *(float4*)&Ks[e * 72 + col] = *(const float4*)&Kp[(size_t)e * LL + s0 + col];
                float4 vv = *(const float4*)&V[(size_t)e * LL + s0 + col];
                Vs[(col + 0) * 72 + e] = vv.x;
                Vs[(col + 1) * 72 + e] = vv.y;
                Vs[(col + 2) * 72 + e] = vv.z;
                Vs[(col + 3) * 72 + e] = vv.w;
            }
        }
        __syncthreads();

        // S = Q^T K for 32 rows (2 m-atoms), 64 cols
        float sa[2][8][4];
#pragma unroll
        for (int am = 0; am < 2; am++)
#pragma unroll
            for (int an = 0; an < 8; an++)
#pragma unroll
                for (int q = 0; q < 4; q++) sa[am][an][q] = 0.f;
#pragma unroll
        for (int k8 = 0; k8 < 64; k8 += 8) {
            uint32_t a[2][4];
#pragma unroll
            for (int am = 0; am < 2; am++) {
                int c = lw + am * 16 + grp;
                a[am][0] = f2tf(Qs[(k8 + tig) * 136 + c]);
                a[am][1] = f2tf(Qs[(k8 + tig) * 136 + c + 8]);
                a[am][2] = f2tf(Qs[(k8 + tig + 4) * 136 + c]);
                a[am][3] = f2tf(Qs[(k8 + tig + 4) * 136 + c + 8]);
            }
#pragma unroll
            for (int an = 0; an < 8; an++) {
                uint32_t bb[2];
                bb[0] = f2tf(Ks[(k8 + tig) * 72 + an * 8 + grp]);
                bb[1] = f2tf(Ks[(k8 + tig + 4) * 72 + an * 8 + grp]);
                mma_tf32(sa[0][an], a[0], bb);
                mma_tf32(sa[1][an], a[1], bb);
            }
        }

        // online softmax per m-atom; quad (xor 1,2) = full 64-col row
#pragma unroll
        for (int am = 0; am < 2; am++) {
            float mx0 = -1e30f, mx1 = -1e30f;
#pragma unroll
            for (int an = 0; an < 8; an++) {
#pragma unroll
                for (int q = 0; q < 4; q++) sa[am][an][q] *= 0.125f;
                mx0 = fmaxf(mx0, fmaxf(sa[am][an][0], sa[am][an][1]));
                mx1 = fmaxf(mx1, fmaxf(sa[am][an][2], sa[am][an][3]));
            }
            mx0 = fmaxf(mx0, __shfl_xor_sync(0xffffffffu, mx0, 1));
            mx0 = fmaxf(mx0, __shfl_xor_sync(0xffffffffu, mx0, 2));
            mx1 = fmaxf(mx1, __shfl_xor_sync(0xffffffffu, mx1, 1));
            mx1 = fmaxf(mx1, __shfl_xor_sync(0xffffffffu, mx1, 2));
            float mn0 = fmaxf(mI[am][0], mx0), mn1 = fmaxf(mI[am][1], mx1);
            float al0 = fexp(mI[am][0] - mn0), al1 = fexp(mI[am][1] - mn1);
            mI[am][0] = mn0; mI[am][1] = mn1;
            float ps0 = 0.f, ps1 = 0.f;
            int r = lw + am * 16 + grp;
#pragma unroll
            for (int an = 0; an < 8; an++) {
                float p0 = fexp(sa[am][an][0] - mn0);
                float p1 = fexp(sa[am][an][1] - mn0);
                float p2 = fexp(sa[am][an][2] - mn1);
                float p3 = fexp(sa[am][an][3] - mn1);
                ps0 += p0 + p1; ps1 += p2 + p3;
                float2 w0; w0.x = p0; w0.y = p1;
                float2 w1; w1.x = p2; w1.y = p3;
                *(float2*)&Ps[r * 68 + an * 8 + 2 * tig] = w0;
                *(float2*)&Ps[(r + 8) * 68 + an * 8 + 2 * tig] = w1;
            }
            ps0 += __shfl_xor_sync(0xffffffffu, ps0, 1);
            ps0 += __shfl_xor_sync(0xffffffffu, ps0, 2);
            ps1 += __shfl_xor_sync(0xffffffffu, ps1, 1);
            ps1 += __shfl_xor_sync(0xffffffffu, ps1, 2);
            li[am][0] = li[am][0] * al0 + ps0;
            li[am][1] = li[am][1] * al1 + ps1;
#pragma unroll
            for (int en = 0; en < 8; en++) {
                o[am][en][0] *= al0; o[am][en][1] *= al0;
                o[am][en][2] *= al1; o[am][en][3] *= al1;
            }
        }
        __syncwarp();

        // O += P V
#pragma unroll
        for (int s8 = 0; s8 < 64; s8 += 8) {
            uint32_t a[2][4];
#pragma unroll
            for (int am = 0; am < 2; am++) {
                int r = lw + am * 16 + grp;
                a[am][0] = f2tf(Ps[r * 68 + s8 + tig]);
                a[am][1] = f2tf(Ps[(r + 8) * 68 + s8 + tig]);
                a[am][2] = f2tf(Ps[r * 68 + s8 + tig + 4]);
                a[am][3] = f2tf(Ps[(r + 8) * 68 + s8 + tig + 4]);
            }
#pragma unroll
            for (int en = 0; en < 8; en++) {
                uint32_t bb[2];
                bb[0] = f2tf(Vs[(s8 + tig) * 72 + en * 8 + grp]);
                bb[1] = f2tf(Vs[(s8 + tig + 4) * 72 + en * 8 + grp]);
                mma_tf32(o[0][en], a[0], bb);
                mma_tf32(o[1][en], a[1], bb);
            }
        }
    }

    // epilogue
#pragma unroll
    for (int am = 0; am < 2; am++) {
        float inv0 = 1.0f / li[am][0], inv1 = 1.0f / li[am][1];
        int r = lw + am * 16 + grp;
#pragma unroll
        for (int en = 0; en < 8; en++) {
            int col = h * EE + en * 8 + 2 * tig;
            float2 w0; w0.x = o[am][en][0] * inv0; w0.y = o[am][en][1] * inv0;
            float2 w1; w1.x = o[am][en][2] * inv1; w1.y = o[am][en][3] * inv1;
            *(float2*)&out[((size_t)b * LL + l0 + r) * DD + col] = w0;
            *(float2*)&out[((size_t)b * LL + l0 + r + 8) * DD + col] = w1;
        }
    }
}

// ---------------- time delay aggregation (B,D,L) ----------------
__global__ void timeagg_k(const float* __restrict__ Vt, const float* __restrict__ w,
                          const int* __restrict__ idx, float* __restrict__ agg)
{
    int bd = blockIdx.x;
    int b = bd >> 8;
    __shared__ float row[1024];
    __shared__ float ws[TOPK];
    __shared__ int   is[TOPK];
    int t = threadIdx.x;
    for (int l = t; l < 1024; l += 256) row[l] = Vt[(size_t)bd * 1024 + l];
    if (t < TOPK) { ws[t] = w[(size_t)b * 64 + t]; is[t] = idx[t]; }
    __syncthreads();
    for (int l = t; l < 1024; l += 256) {
        float a = 0.f;
#pragma unroll
        for (int k = 0; k < TOPK; k++) a = fmaf(ws[k], row[(l + is[k]) & 1023], a);
        agg[(size_t)bd * 1024 + l] = a;
    }
}

// ---------------- context = 0.9*agg^T + 0.1*ctx_sp ----------------
__global__ void mix_k(const float* __restrict__ agg, const float* __restrict__ csp,
                      float* __restrict__ ctx)
{
    __shared__ float tile[32][33];
    int b = blockIdx.z;
    int l0 = blockIdx.x * 32, d0 = blockIdx.y * 32;
    int x = threadIdx.x, y = threadIdx.y;
#pragma unroll
    for (int i = 0; i < 32; i += 8)
        tile[y + i][x] = agg[((size_t)b * DD + d0 + y + i) * LL + l0 + x];
    __syncthreads();
#pragma unroll
    for (int i = 0; i < 32; i += 8) {
        size_t o = ((size_t)b * LL + l0 + y + i) * DD + d0 + x;
        ctx[o] = 0.9f * tile[x][y + i] + 0.1f * csp[o];
    }
}

// ---------------- LayerNorm over D=256, warp per row ----------------
// 256 threads = 8 warps = 8 rows/block; grid = B*L/8.
__global__ void __launch_bounds__(256) ln_k(
    const float* __restrict__ in, const float* __restrict__ g,
    const float* __restrict__ b, float* __restrict__ out)
{
    const int lane = threadIdx.x & 31;
    const size_t row = (size_t)blockIdx.x * 8 + (threadIdx.x >> 5);
    const float* p = in + row * DD;
    float4 v0 = *(const float4*)&p[lane * 8];
    float4 v1 = *(const float4*)&p[lane * 8 + 4];
    float s = v0.x + v0.y + v0.z + v0.w + v1.x + v1.y + v1.z + v1.w;
#pragma unroll
    for (int off = 16; off > 0; off >>= 1)
        s += __shfl_xor_sync(0xffffffffu, s, off);
    float m = s * (1.0f / 256.0f);
    float d0x = v0.x - m, d0y = v0.y - m, d0z = v0.z - m, d0w = v0.w - m;
    float d1x = v1.x - m, d1y = v1.y - m, d1z = v1.z - m, d1w = v1.w - m;
    float vv = d0x * d0x + d0y * d0y + d0z * d0z + d0w * d0w
             + d1x * d1x + d1y * d1y + d1z * d1z + d1w * d1w;
#pragma unroll
    for (int off = 16; off > 0; off >>= 1)
        vv += __shfl_xor_sync(0xffffffffu, vv, off);
    float inv = rsqrtf(vv * (1.0f / 256.0f) + 1e-8f);
    float4 g0 = *(const float4*)&g[lane * 8];
    float4 g1 = *(const float4*)&g[lane * 8 + 4];
    float4 b0 = *(const float4*)&b[lane * 8];
    float4 b1 = *(const float4*)&b[lane * 8 + 4];
    float4 o0, o1;
    o0.x = d0x * inv * g0.x + b0.x; o0.y = d0y * inv * g0.y + b0.y;
    o0.z = d0z * inv * g0.z + b0.z; o0.w = d0w * inv * g0.w + b0.w;
    o1.x = d1x * inv * g1.x + b1.x; o1.y = d1y * inv * g1.y + b1.y;
    o1.z = d1z * inv * g1.z + b1.z; o1.w = d1w * inv * g1.w + b1.w;
    *(float4*)&out[row * DD + lane * 8] = o0;
    *(float4*)&out[row * DD + lane * 8 + 4] = o1;
}

// ---------------- launch ----------------
extern "C" void kernel_launch(void* const* d_in, const int* in_sizes, int n_in,
                              void* d_out, int out_size)
{
    const float* x   = (const float*)d_in[0];
    const float* Wq  = (const float*)d_in[1];
    const float* bq  = (const float*)d_in[2];
    const float* Wk  = (const float*)d_in[3];
    const float* bk  = (const float*)d_in[4];
    const float* Wv  = (const float*)d_in[5];
    const float* bv  = (const float*)d_in[6];
    const float* Wd  = (const float*)d_in[7];
    const float* bd  = (const float*)d_in[8];
    const float* ln1g = (const float*)d_in[9];
    const float* ln1b = (const float*)d_in[10];
    const float* W1  = (const float*)d_in[11];
    const float* b1  = (const float*)d_in[12];
    const float* W2  = (const float*)d_in[13];
    const float* b2  = (const float*)d_in[14];
    const float* ln2g = (const float*)d_in[15];
    const float* ln2b = (const float*)d_in[16];
    float* out = (float*)d_out;

    float* scr = nullptr;
    int* idxp = nullptr;
    cudaGetSymbolAddress((void**)&scr, g_scr);
    cudaGetSymbolAddress((void**)&idxp, g_idx);

    float* bQ   = scr + O_Q;   float* bK  = scr + O_K;   float* bV  = scr + O_V;
    float* Kt   = scr + O_KT;  float* Vt  = scr + O_VT;  float* trb = scr + O_TR;
    float* spQ  = scr + O_SPQ; float* spK = scr + O_SPK; float* spV = scr + O_SPV;
    float* qsb  = scr + O_QS;  float* vsb = scr + O_VS;
    float* csp  = scr + O_CSP; float* agg = scr + O_AGG; float* ctx = scr + O_CTX;
    float* t1   = scr + O_T1;  float* hb  = scr + O_H;
    float* g1b  = scr + O_G1;  float* fb  = scr + O_F;
    float* Sb   = scr + O_S;   float* mv  = scr + O_MV;  float* wts = scr + O_W;

    const int flash_smem = (64 * 136 + 2 * 64 * 72 + 128 * 68) * sizeof(float); // 106496 B
    cudaFuncSetAttribute(flash_tc, cudaFuncAttributeMaxDynamicSharedMemorySize, flash_smem);

    const dim3 tb(32, 8);

    // 1. QKV projections (tf32 tensor cores)
    gemm_tc<1><<<dim3(2, 256), 256>>>(x, Wq, bq, nullptr, bQ, BB * LL, DD, DD);
    gemm_tc<1><<<dim3(2, 256), 256>>>(x, Wk, bk, nullptr, bK, BB * LL, DD, DD);
    gemm_tc<1><<<dim3(2, 256), 256>>>(x, Wv, bv, nullptr, bV, BB * LL, DD, DD);

    // 2. transposes to (B,D,L)
    tr_k<<<dim3(8, 32, BB), tb>>>(bK, Kt, LL, DD, LL * DD, LL * DD);
    tr_k<<<dim3(8, 32, BB), tb>>>(bV, Vt, LL, DD, LL * DD, LL * DD);
    tr_k<<<dim3(8, 32, BB), tb>>>(bQ, trb, LL, DD, LL * DD, LL * DD);

    // 3. forward band FFT (radix-4)
    fftfwd_k<<<BB * DD, 256>>>(trb, spQ);
    fftfwd_k<<<BB * DD, 256>>>(Kt, spK);
    fftfwd_k<<<BB * DD, 256>>>(Vt, spV);

    // 4. corr mean path
    corr_part_k<<<dim3(8, BB), 256>>>(spQ, spK, t1);
    corr_red_k<<<BB, 256>>>(t1, Sb);
    meanv_k<<<dim3(BB, 4), 256>>>(Sb, mv);
    topk_k<<<1, 1024>>>(mv, idxp);
    weights_k<<<BB, 64>>>(mv, idxp, wts);

    // 5. inverse band FFT -> qs, vs
    fftinv_k<<<BB * DD, 256>>>(spQ, qsb);
    fftinv_k<<<BB * DD, 256>>>(spV, vsb);

    // 6. spatial attention (tf32; 2 m-atoms/warp; K = raw Kt)
    flash_tc<<<dim3(8, BB * HH), 128, flash_smem>>>(qsb, Kt, vsb, csp);

    // 7. time aggregation + mix
    timeagg_k<<<BB * DD, 256>>>(Vt, wts, idxp, agg);
    mix_k<<<dim3(32, 8, BB), tb>>>(agg, csp, ctx);

    // 8. output projection + residual + LN1
    gemm_tc<2><<<dim3(2, 256), 256>>>(ctx, Wd, bd, x, t1, BB * LL, DD, DD);
    ln_k<<<BB * LL / 8, 256>>>(t1, ln1g, ln1b, hb);

    // 9. FFN + LN2
    gemm_tc<3><<<dim3(2, 256), 256>>>(hb, W1, b1, nullptr, g1b, BB * LL, DD, DD);
    gemm_tc<2><<<dim3(2, 256), 256>>>(g1b, W2, b2, hb, fb, BB * LL, DD, DD);
    ln_k<<<BB * LL / 8, 256>>>(fb, ln2g, ln2b, out);
}